// round 9
// baseline (speedup 1.0000x reference)
#include <cuda_runtime.h>
#include <math.h>
#include <cstdint>

#define NTOT 16384
#define AS_F 4608          // 128*36 floats (A plane)
#define BS_F 2304          // 64*36 floats (B plane)
#define PL_F (AS_F + BS_F) // 6912 floats per 32-k plane
#define STAGE_F (2 * PL_F) // 64-k stage = two planes
#define ROW36 (32 * 36)

// ---------------- scratch (device globals; no allocation allowed) ----------
__device__ __align__(16) float g_x[131072 * 64];    // encoder out (tf32-rounded)
__device__ __align__(16) float g_stf[NTOT * 512];   // tf32-rounded states
__device__ __align__(16) float g_wtf[503808];       // tf32-rounded weights pool
__device__ __align__(16) float g_aq[NTOT * 8];
__device__ __align__(16) float g_h1[NTOT * 256];    // tf32-rounded
__device__ __align__(16) float g_hf[NTOT * 256];    // tf32-rounded
__device__ __align__(16) float g_w1[NTOT * 512];
__device__ __align__(16) float g_wf[NTOT * 64];
__device__ __align__(16) float g_b1[NTOT * 64];
__device__ __align__(16) float g_v1[NTOT * 64];

// offsets (floats) in g_wtf
#define OFF_WOBS 0
#define OFF_WQKV 16384
#define OFF_WH1A 28672
#define OFF_WHFA 159744
#define OFF_WH1B 290816
#define OFF_WHFB 421888
#define OFF_WB1  438272
#define OFF_WV1  471040
#define WTF_TOTAL 503808

// ---------------- helpers ---------------------------------------------------
__device__ __forceinline__ uint32_t f2tf(float x) {   // RNA round to tf32
    uint32_t r;
    asm("cvt.rna.tf32.f32 %0, %1;" : "=r"(r) : "f"(x));
    return r;
}
__device__ __forceinline__ uint32_t smem_u32(const void* p) {
    uint32_t a;
    asm("{ .reg .u64 t; cvta.to.shared.u64 t, %1; cvt.u32.u64 %0, t; }" : "=r"(a) : "l"(p));
    return a;
}
__device__ __forceinline__ void cp16(uint32_t s, const void* g) {
    asm volatile("cp.async.cg.shared.global [%0], [%1], 16;" :: "r"(s), "l"(g));
}
#define CP_COMMIT asm volatile("cp.async.commit_group;" ::: "memory")
#define CP_WAIT(N) asm volatile("cp.async.wait_group %0;" :: "n"(N) : "memory")

__device__ __forceinline__ void mma_tf32(float* c, const uint32_t* a, const uint32_t* b) {
    asm volatile(
        "mma.sync.aligned.m16n8k8.row.col.f32.tf32.tf32.f32 "
        "{%0,%1,%2,%3}, {%4,%5,%6,%7}, {%8,%9}, {%0,%1,%2,%3};\n"
        : "+f"(c[0]), "+f"(c[1]), "+f"(c[2]), "+f"(c[3])
        : "r"(a[0]), "r"(a[1]), "r"(a[2]), "r"(a[3]), "r"(b[0]), "r"(b[1]));
}

// ---- compute one 128x64x32 plane from [r][36] tiles ------------------------
// k-slot permutation: logical k = 8t + 2*kk8 + half (applied to A & B)
template <int CVTA>
__device__ __forceinline__ void compute_chunk(
    const float* __restrict__ Ab, const float* __restrict__ Bb,
    float acc[2][4][4], int wm, int wn, int g, int t)
{
    float a8[4][8], b8[4][8];
#pragma unroll
    for (int i = 0; i < 4; i++) {
        const float* pr = Ab + (wm * 32 + i * 8 + g) * 36 + t * 8;
        *(float4*)&a8[i][0] = *(const float4*)pr;
        *(float4*)&a8[i][4] = *(const float4*)(pr + 4);
    }
#pragma unroll
    for (int i = 0; i < 4; i++) {
        const float* pr = Bb + (wn * 32 + i * 8 + g) * 36 + t * 8;
        *(float4*)&b8[i][0] = *(const float4*)pr;
        *(float4*)&b8[i][4] = *(const float4*)(pr + 4);
    }
#pragma unroll
    for (int k8 = 0; k8 < 4; k8++) {
        uint32_t af[2][4], bf[4][2];
#pragma unroll
        for (int mi = 0; mi < 2; mi++) {
            if (CVTA) {
                af[mi][0] = f2tf(a8[2 * mi][2 * k8]);
                af[mi][1] = f2tf(a8[2 * mi + 1][2 * k8]);
                af[mi][2] = f2tf(a8[2 * mi][2 * k8 + 1]);
                af[mi][3] = f2tf(a8[2 * mi + 1][2 * k8 + 1]);
            } else {
                af[mi][0] = __float_as_uint(a8[2 * mi][2 * k8]);
                af[mi][1] = __float_as_uint(a8[2 * mi + 1][2 * k8]);
                af[mi][2] = __float_as_uint(a8[2 * mi][2 * k8 + 1]);
                af[mi][3] = __float_as_uint(a8[2 * mi + 1][2 * k8 + 1]);
            }
        }
#pragma unroll
        for (int ni = 0; ni < 4; ni++) {
            bf[ni][0] = __float_as_uint(b8[ni][2 * k8]);
            bf[ni][1] = __float_as_uint(b8[ni][2 * k8 + 1]);
        }
#pragma unroll
        for (int mi = 0; mi < 2; mi++)
#pragma unroll
            for (int ni = 0; ni < 4; ni++)
                mma_tf32(acc[mi][ni], af[mi], bf[ni]);
    }
}

// ---- stage one 64-k chunk (two 32-k planes) via cp.async -------------------
__device__ __forceinline__ void issue_stage64(
    const float* __restrict__ Ab, const float* __restrict__ Bb, int K,
    uint32_t sa, uint32_t sb)
{
#pragma unroll
    for (int p = 0; p < 2; p++) {
#pragma unroll
        for (int i = 0; i < 4; i++)
            cp16(sa + (uint32_t)(p * PL_F + i * ROW36) * 4, Ab + p * 32 + (size_t)i * 32 * K);
#pragma unroll
        for (int i = 0; i < 2; i++)
            cp16(sb + (uint32_t)(p * PL_F + i * ROW36) * 4, Bb + p * 32 + (size_t)i * 32 * K);
    }
}

// 2-stage, BK=64, ONE wait + ONE barrier per 64-k.
// Safety: the in-loop issue targets buf (c+1)&1, last read at compute(c-1);
// the barrier (after the wait, before the issue) orders all warps past
// compute(c-1). cvta is CTA-uniform -> coherent branch per chunk.
__device__ __forceinline__ void gemm_main64(
    const float* __restrict__ A, const float* __restrict__ B, int K,
    int row0, int col0, float* Sm, float acc[2][4][4],
    int tid, int wm, int wn, int g, int t, int cvta)
{
    const uint32_t su = smem_u32(Sm);
    const int ra = tid >> 3, q4 = (tid & 7) * 4;
    const float* Abase = A + (size_t)(row0 + ra) * K + q4;
    const float* Bbase = B + (size_t)(col0 + ra) * K + q4;
    const uint32_t sa = su + (uint32_t)(ra * 36 + q4) * 4;
    const uint32_t sb = sa + (uint32_t)AS_F * 4;
    const int nk = K >> 6;

    issue_stage64(Abase, Bbase, K, sa, sb); CP_COMMIT;
    for (int c = 0; c < nk; c++) {
        CP_WAIT(0);
        __syncthreads();
        if (c + 1 < nk) {
            const uint32_t so = (uint32_t)(((c + 1) & 1) * STAGE_F) * 4;
            issue_stage64(Abase + (c + 1) * 64, Bbase + (c + 1) * 64, K, sa + so, sb + so);
            CP_COMMIT;
        }
        const float* st = Sm + (c & 1) * STAGE_F;
        if (cvta) {
            compute_chunk<1>(st,        st + AS_F,        acc, wm, wn, g, t);
            compute_chunk<1>(st + PL_F, st + PL_F + AS_F, acc, wm, wn, g, t);
        } else {
            compute_chunk<0>(st,        st + AS_F,        acc, wm, wn, g, t);
            compute_chunk<0>(st + PL_F, st + PL_F + AS_F, acc, wm, wn, g, t);
        }
    }
}

// ---------------- merged pre-conversion kernel (states + weights) -----------
struct WSeg { const float* src; int off; int cnt; };
struct WSegs { WSeg v[8]; };
#define CVT_STATE_BLOCKS 8192
#define CVT_W_BLOCKS 492            // WTF_TOTAL / 1024

__global__ void __launch_bounds__(256) cvt_all_kernel(
    const float* __restrict__ s, float* __restrict__ d,
    WSegs segs, float* __restrict__ wdst)
{
    int b = blockIdx.x;
    if (b < CVT_STATE_BLOCKS) {
        size_t i = (size_t)(b * 256 + threadIdx.x) * 4;
        float4 v = *(const float4*)(s + i);
        uint4 u = { f2tf(v.x), f2tf(v.y), f2tf(v.z), f2tf(v.w) };
        *(uint4*)(d + i) = u;
    } else {
        int i4 = ((b - CVT_STATE_BLOCKS) * 256 + threadIdx.x) * 4;
#pragma unroll
        for (int k = 0; k < 8; k++) {
            int off = segs.v[k].off, cnt = segs.v[k].cnt;
            if (i4 >= off && i4 < off + cnt) {
                float4 v = *(const float4*)(segs.v[k].src + (i4 - off));
                uint4 u = { f2tf(v.x), f2tf(v.y), f2tf(v.z), f2tf(v.w) };
                *(uint4*)(wdst + i4) = u;
            }
        }
    }
}

// ---------------- packed GEMM: op table, 1D grid of 128-row tiles -----------
// epi: 0=id, 1=relu, 2=abs, 4=encoder. rnd: store f2tf-rounded. cvta: cvt A.
struct GOp {
    const float* A; const float* B; const float* bias; float* C;
    int K; int Nout; int col0; int epi; int tileBase; int flags; // bit0=rnd, bit1=cvta
};
struct GOps { GOp v[11]; };
#define G_SMEM_BYTES ((2 * STAGE_F + 192) * 4)

__global__ void __launch_bounds__(256, 2) packed_gemm(
    GOps ops,
    const int* __restrict__ actions, const float* __restrict__ qvals,
    const float* __restrict__ W_act, const float* __restrict__ W_q,
    const float* __restrict__ b_act, const float* __restrict__ b_q)
{
    extern __shared__ float dsm[];
    float* bias_sh = dsm + 2 * STAGE_F;
    float* cvec_sh = bias_sh + 64;
    float* wq_sh   = cvec_sh + 64;

    const int bid = blockIdx.x;
    int j = 0;
#pragma unroll
    for (int k = 1; k < 11; k++) if (bid >= ops.v[k].tileBase) j = k;
    const GOp op = ops.v[j];

    const int tid = threadIdx.x;
    const int wid = tid >> 5, lane = tid & 31;
    const int wm = wid >> 1, wn = wid & 1;
    const int g = lane >> 2, t = lane & 3;
    const int row0 = (bid - op.tileBase) * 128;
    const int col0 = op.col0;
    const int epi = op.epi;
    const int rnd = op.flags & 1, cvta = (op.flags >> 1) & 1;

    if (tid < 64) {
        bias_sh[tid] = op.bias[col0 + tid];
        if (epi == 4) {
            cvec_sh[tid] = b_act[tid] + b_q[tid];
            wq_sh[tid] = W_q[tid];
        }
    }

    float acc[2][4][4];
#pragma unroll
    for (int mi = 0; mi < 2; mi++)
#pragma unroll
        for (int ni = 0; ni < 4; ni++)
#pragma unroll
            for (int jj = 0; jj < 4; jj++) acc[mi][ni][jj] = 0.f;

    gemm_main64(op.A, op.B, op.K, row0, col0, dsm, acc, tid, wm, wn, g, t, cvta);

    const int Nout = op.Nout;
#pragma unroll
    for (int mi = 0; mi < 2; mi++)
#pragma unroll
        for (int half = 0; half < 2; half++) {
            const int row = row0 + wm * 32 + mi * 16 + half * 8 + g;
            int act = 0; float qv = 0.f;
            if (epi == 4) { act = actions[row]; qv = qvals[row]; }
            float* dst = op.C + (size_t)row * Nout + col0;
#pragma unroll
            for (int ni = 0; ni < 4; ni++) {
                const int lc = wn * 32 + ni * 8 + t * 2;
                float v0 = acc[mi][ni][half * 2 + 0] + bias_sh[lc];
                float v1 = acc[mi][ni][half * 2 + 1] + bias_sh[lc + 1];
                if (epi == 4) {
                    v0 += cvec_sh[lc] + __ldg(&W_act[lc * 32 + act]) + qv * wq_sh[lc];
                    v1 += cvec_sh[lc + 1] + __ldg(&W_act[(lc + 1) * 32 + act]) + qv * wq_sh[lc + 1];
                } else if (epi == 1) {
                    v0 = fmaxf(v0, 0.f); v1 = fmaxf(v1, 0.f);
                } else if (epi == 2) {
                    v0 = fabsf(v0); v1 = fabsf(v1);
                }
                if (rnd) { v0 = __uint_as_float(f2tf(v0)); v1 = __uint_as_float(f2tf(v1)); }
                float2 o = { v0, v1 };
                *(float2*)(dst + lc) = o;
            }
        }
}

// ---------------- fused qkv GEMM + attention (+ inline wcomb) ---------------
#define QA_XS_F (2 * 128 * 36)
#define QA_WS_F (2 * 192 * 36)
#define QA_QS_F (128 * 196)
#define QA_SMEM_BYTES ((QA_XS_F + QA_WS_F + QA_QS_F + 192 + 65) * 4)

__global__ void __launch_bounds__(256) qkv_attn_kernel(
    const float* __restrict__ Wqkv_tf, const float* __restrict__ bqkv,
    const float* __restrict__ Wa2q, const float* __restrict__ ba2q,
    const float* __restrict__ Wo, const float* __restrict__ bo)
{
    extern __shared__ float sm[];
    float* xs = sm;                        // [2][128][36]
    float* ws = xs + QA_XS_F;              // [2][192][36]
    float* qs = ws + QA_WS_F;              // [128][196]
    float* bq = qs + QA_QS_F;              // 192
    float* wc = bq + 192;                  // 65

    const int tid = threadIdx.x;
    const int wid = tid >> 5, lane = tid & 31;
    const int wm = wid >> 1, wn = wid & 1;
    const int g = lane >> 2, t = lane & 3;
    const int row0 = blockIdx.x * 128;

    const uint32_t xs_u = smem_u32(xs);
    const uint32_t ws_u = smem_u32(ws);
#pragma unroll
    for (int i = 0; i < 8; i++) {          // x tile: 2048 float4
        int e = tid + i * 256;
        int r = e >> 4, q = e & 15;
        cp16(xs_u + (uint32_t)((q >> 3) * (128 * 36) + r * 36 + (q & 7) * 4) * 4,
             g_x + (size_t)(row0 + r) * 64 + q * 4);
    }
#pragma unroll
    for (int i = 0; i < 12; i++) {         // Wqkv: 3072 float4
        int e = tid + i * 256;
        int n = e >> 4, q = e & 15;
        cp16(ws_u + (uint32_t)((q >> 3) * (192 * 36) + n * 36 + (q & 7) * 4) * 4,
             Wqkv_tf + (size_t)n * 64 + q * 4);
    }
    if (tid < 192) bq[tid] = bqkv[tid];
    // inline wcomb = Wa2q @ Wo (hidden under cp.async wait)
    if (tid < 64) {
        float s = 0.f;
#pragma unroll 8
        for (int c = 0; c < 64; c++) s += Wa2q[c] * Wo[c * 64 + tid];
        wc[tid] = s;
    }
    if (wid == 6) {                        // bcomb = Wa2q.bo + ba2q
        float v = Wa2q[lane] * bo[lane] + Wa2q[lane + 32] * bo[lane + 32];
#pragma unroll
        for (int off = 16; off > 0; off >>= 1) v += __shfl_xor_sync(0xffffffffu, v, off);
        if (lane == 0) wc[64] = v + ba2q[0];
    }
    CP_COMMIT; CP_WAIT(0);
    __syncthreads();

    // ---- phase B: qkv = x @ Wqkv^T (3 col blocks of 64); x pre-rounded ----
#pragma unroll 1
    for (int cb = 0; cb < 3; cb++) {
        float acc[2][4][4];
#pragma unroll
        for (int mi = 0; mi < 2; mi++)
#pragma unroll
            for (int ni = 0; ni < 4; ni++)
#pragma unroll
                for (int jj = 0; jj < 4; jj++) acc[mi][ni][jj] = 0.f;

#pragma unroll
        for (int c = 0; c < 2; c++)
            compute_chunk<0>(xs + c * (128 * 36),
                             ws + c * (192 * 36) + (cb * 64) * 36,
                             acc, wm, wn, g, t);

#pragma unroll
        for (int mi = 0; mi < 2; mi++)
#pragma unroll
            for (int half = 0; half < 2; half++) {
                const int row = wm * 32 + mi * 16 + half * 8 + g;
#pragma unroll
                for (int ni = 0; ni < 4; ni++) {
                    const int lc = wn * 32 + ni * 8 + t * 2;
                    qs[row * 196 + cb * 64 + lc]     = acc[mi][ni][half * 2 + 0] + bq[cb * 64 + lc];
                    qs[row * 196 + cb * 64 + lc + 1] = acc[mi][ni][half * 2 + 1] + bq[cb * 64 + lc + 1];
                }
            }
    }
    __syncthreads();

    // ---- phase C: attention per sample (2 samples per warp) ----
    const int h = lane >> 3, a = lane & 7;
#pragma unroll
    for (int s2 = 0; s2 < 2; s2++) {
        const int s = wid * 2 + s2;
        const float* base = qs + s * 8 * 196;

        float q[16];
#pragma unroll
        for (int d = 0; d < 16; d++) q[d] = base[a * 196 + h * 16 + d];
        float sc[8], m = -1e30f;
#pragma unroll
        for (int b = 0; b < 8; b++) {
            float acc = 0.f;
#pragma unroll
            for (int d = 0; d < 16; d++) acc += q[d] * base[b * 196 + 64 + h * 16 + d];
            sc[b] = acc * 0.25f;          // 1/sqrt(16)
            m = fmaxf(m, sc[b]);
        }
        float sum = 0.f;
#pragma unroll
        for (int b = 0; b < 8; b++) { sc[b] = __expf(sc[b] - m); sum += sc[b]; }
        float inv = 1.f / sum;
        float o[16];
#pragma unroll
        for (int d = 0; d < 16; d++) o[d] = 0.f;
#pragma unroll
        for (int b = 0; b < 8; b++) {
            float p = sc[b] * inv;
#pragma unroll
            for (int d = 0; d < 16; d++) o[d] += p * base[b * 196 + 128 + h * 16 + d];
        }
        float part = 0.f;
#pragma unroll
        for (int d = 0; d < 16; d++) part += o[d] * wc[h * 16 + d];
        part += __shfl_xor_sync(0xffffffffu, part, 8);
        part += __shfl_xor_sync(0xffffffffu, part, 16);
        if (h == 0) {
            const int n = blockIdx.x * 16 + s;
            g_aq[n * 8 + a] = part + wc[64];
        }
    }
}

// ---------------- final mixing: elu(aq @ w1 + b1) . w_f + v ----------------
__global__ void __launch_bounds__(256) final_kernel(
    const float* __restrict__ Wv2, const float* __restrict__ bv2,
    float* __restrict__ out)
{
    const int warp = threadIdx.x >> 5, lane = threadIdx.x & 31;
    const int n = blockIdx.x * 8 + warp;
    if (n >= NTOT) return;

    float aqv[8];
#pragma unroll
    for (int a = 0; a < 8; a++) aqv[a] = g_aq[n * 8 + a];

    float tot = 0.f;
#pragma unroll
    for (int jj = 0; jj < 2; jj++) {
        int e = jj * 32 + lane;
        float hsum = g_b1[n * 64 + e];
#pragma unroll
        for (int a = 0; a < 8; a++) hsum += aqv[a] * g_w1[(size_t)n * 512 + a * 64 + e];
        float hid = hsum > 0.f ? hsum : expm1f(hsum);
        tot += hid * g_wf[n * 64 + e] + g_v1[n * 64 + e] * Wv2[e];
    }
#pragma unroll
    for (int off = 16; off > 0; off >>= 1) tot += __shfl_xor_sync(0xffffffffu, tot, off);
    if (lane == 0) out[n] = tot + bv2[0];
}

// ---------------- launch ----------------------------------------------------
extern "C" void kernel_launch(void* const* d_in, const int* in_sizes, int n_in,
                              void* d_out, int out_size)
{
    const float* agent_qs = (const float*)d_in[0];
    const float* states   = (const float*)d_in[1];
    const float* obs      = (const float*)d_in[2];
    const int*   actions  = (const int*)d_in[3];
    const float* W_obs = (const float*)d_in[4];  const float* b_obs = (const float*)d_in[5];
    const float* W_act = (const float*)d_in[6];  const float* b_act = (const float*)d_in[7];
    const float* W_q   = (const float*)d_in[8];  const float* b_q   = (const float*)d_in[9];
    const float* Wqkv  = (const float*)d_in[10]; const float* bqkv  = (const float*)d_in[11];
    const float* Wo    = (const float*)d_in[12]; const float* bo    = (const float*)d_in[13];
    const float* Wa2q  = (const float*)d_in[14]; const float* ba2q  = (const float*)d_in[15];
    const float* Wh1a  = (const float*)d_in[16]; const float* bh1a  = (const float*)d_in[17];
    const float* Wh1b  = (const float*)d_in[18]; const float* bh1b  = (const float*)d_in[19];
    const float* Whfa  = (const float*)d_in[20]; const float* bhfa  = (const float*)d_in[21];
    const float* Whfb  = (const float*)d_in[22]; const float* bhfb  = (const float*)d_in[23];
    const float* Wb1   = (const float*)d_in[24]; const float* bb1   = (const float*)d_in[25];
    const float* Wv1   = (const float*)d_in[26]; const float* bv1   = (const float*)d_in[27];
    const float* Wv2   = (const float*)d_in[28]; const float* bv2   = (const float*)d_in[29];
    float* out = (float*)d_out;

    void *p_x, *p_stf, *p_wtf, *p_h1, *p_hf, *p_w1, *p_wf, *p_b1, *p_v1;
    cudaGetSymbolAddress(&p_x,   g_x);
    cudaGetSymbolAddress(&p_stf, g_stf);
    cudaGetSymbolAddress(&p_wtf, g_wtf);
    cudaGetSymbolAddress(&p_h1,  g_h1);
    cudaGetSymbolAddress(&p_hf,  g_hf);
    cudaGetSymbolAddress(&p_w1,  g_w1);
    cudaGetSymbolAddress(&p_wf,  g_wf);
    cudaGetSymbolAddress(&p_b1,  g_b1);
    cudaGetSymbolAddress(&p_v1,  g_v1);
    float* wtf = (float*)p_wtf;

    cudaFuncSetAttribute(packed_gemm,     cudaFuncAttributeMaxDynamicSharedMemorySize, G_SMEM_BYTES);
    cudaFuncSetAttribute(qkv_attn_kernel, cudaFuncAttributeMaxDynamicSharedMemorySize, QA_SMEM_BYTES);

    // 0) pre-convert states + weights (one launch)
    WSegs segs;
    segs.v[0] = { W_obs, OFF_WOBS, 16384 };
    segs.v[1] = { Wqkv,  OFF_WQKV, 12288 };
    segs.v[2] = { Wh1a,  OFF_WH1A, 131072 };
    segs.v[3] = { Whfa,  OFF_WHFA, 131072 };
    segs.v[4] = { Wh1b,  OFF_WH1B, 131072 };
    segs.v[5] = { Whfb,  OFF_WHFB, 16384 };
    segs.v[6] = { Wb1,   OFF_WB1,  32768 };
    segs.v[7] = { Wv1,   OFF_WV1,  32768 };
    cvt_all_kernel<<<CVT_STATE_BLOCKS + CVT_W_BLOCKS, 256>>>(states, (float*)p_stf, segs, wtf);

    // 1) mega launch 1: encoder (1024 tiles, cvta) + state hypernets (1280)
    // flags: bit0 = round output, bit1 = cvt A on the fly
    GOps m1 = {};
    m1.v[0] = { obs, wtf + OFF_WOBS, b_obs, (float*)p_x, 256, 64, 0, 4, 0, 3 };
    for (int i = 0; i < 4; i++)
        m1.v[1 + i] = { (float*)p_stf, wtf + OFF_WH1A, bh1a, (float*)p_h1, 512, 256, i * 64, 1, 1024 + i * 128, 1 };
    for (int i = 0; i < 4; i++)
        m1.v[5 + i] = { (float*)p_stf, wtf + OFF_WHFA, bhfa, (float*)p_hf, 512, 256, i * 64, 1, 1536 + i * 128, 1 };
    m1.v[9]  = { (float*)p_stf, wtf + OFF_WB1, bb1, (float*)p_b1, 512, 64, 0, 0, 2048, 0 };
    m1.v[10] = { (float*)p_stf, wtf + OFF_WV1, bv1, (float*)p_v1, 512, 64, 0, 1, 2176, 0 };
    packed_gemm<<<2304, 256, G_SMEM_BYTES>>>(m1, actions, agent_qs, W_act, W_q, b_act, b_q);

    // 2) fused qkv + attention (wcomb inline) -> attended_qs
    qkv_attn_kernel<<<1024, 256, QA_SMEM_BYTES>>>(wtf + OFF_WQKV, bqkv, Wa2q, ba2q, Wo, bo);

    // 3) mega launch 2: second hypernet stage (w1 x8 + wf = 1152 tiles)
    GOps m2 = {};
    for (int i = 0; i < 8; i++)
        m2.v[i] = { (float*)p_h1, wtf + OFF_WH1B, bh1b, (float*)p_w1, 256, 512, i * 64, 2, i * 128, 0 };
    m2.v[8]  = { (float*)p_hf, wtf + OFF_WHFB, bhfb, (float*)p_wf, 256, 64, 0, 2, 1024, 0 };
    m2.v[9]  = { (float*)p_hf, wtf + OFF_WHFB, bhfb, (float*)p_wf, 256, 64, 0, 2, 0x7FFFFFFF, 0 };
    m2.v[10] = { (float*)p_hf, wtf + OFF_WHFB, bhfb, (float*)p_wf, 256, 64, 0, 2, 0x7FFFFFFF, 0 };
    packed_gemm<<<1152, 256, G_SMEM_BYTES>>>(m2, actions, agent_qs, W_act, W_q, b_act, b_q);

    // 4) final mix -> y
    final_kernel<<<2048, 256>>>(Wv2, bv2, out);
}

// round 10
// speedup vs baseline: 1.0451x; 1.0451x over previous
#include <cuda_runtime.h>
#include <math.h>
#include <cstdint>

#define NTOT 16384
#define AS_F 4608          // 128*36 floats (A plane)
#define BS_F 2304          // 64*36 floats (B plane)
#define PL_F (AS_F + BS_F) // 6912 floats per 32-k plane
#define ROW36 (32 * 36)

// ---------------- scratch (device globals; no allocation allowed) ----------
__device__ __align__(16) float g_x[131072 * 64];    // encoder out (tf32-rounded)
__device__ __align__(16) float g_stf[NTOT * 512];   // tf32-rounded states
__device__ __align__(16) float g_wtf[503808];       // tf32-rounded weights pool
__device__ __align__(16) float g_aq[NTOT * 8];
__device__ __align__(16) float g_h1[NTOT * 256];    // tf32-rounded
__device__ __align__(16) float g_hf[NTOT * 256];    // tf32-rounded
__device__ __align__(16) float g_w1[NTOT * 512];
__device__ __align__(16) float g_wf[NTOT * 64];
__device__ __align__(16) float g_b1[NTOT * 64];
__device__ __align__(16) float g_v1[NTOT * 64];

// offsets (floats) in g_wtf
#define OFF_WOBS 0
#define OFF_WQKV 16384
#define OFF_WH1A 28672
#define OFF_WHFA 159744
#define OFF_WH1B 290816
#define OFF_WHFB 421888
#define OFF_WB1  438272
#define OFF_WV1  471040
#define WTF_TOTAL 503808

// ---------------- helpers ---------------------------------------------------
__device__ __forceinline__ uint32_t f2tf(float x) {   // RNA round to tf32
    uint32_t r;
    asm("cvt.rna.tf32.f32 %0, %1;" : "=r"(r) : "f"(x));
    return r;
}
__device__ __forceinline__ uint32_t smem_u32(const void* p) {
    uint32_t a;
    asm("{ .reg .u64 t; cvta.to.shared.u64 t, %1; cvt.u32.u64 %0, t; }" : "=r"(a) : "l"(p));
    return a;
}
__device__ __forceinline__ void cp16(uint32_t s, const void* g) {
    asm volatile("cp.async.cg.shared.global [%0], [%1], 16;" :: "r"(s), "l"(g));
}
#define CP_COMMIT asm volatile("cp.async.commit_group;" ::: "memory")
#define CP_WAIT(N) asm volatile("cp.async.wait_group %0;" :: "n"(N) : "memory")

__device__ __forceinline__ void mma_tf32(float* c, const uint32_t* a, const uint32_t* b) {
    asm volatile(
        "mma.sync.aligned.m16n8k8.row.col.f32.tf32.tf32.f32 "
        "{%0,%1,%2,%3}, {%4,%5,%6,%7}, {%8,%9}, {%0,%1,%2,%3};\n"
        : "+f"(c[0]), "+f"(c[1]), "+f"(c[2]), "+f"(c[3])
        : "r"(a[0]), "r"(a[1]), "r"(a[2]), "r"(a[3]), "r"(b[0]), "r"(b[1]));
}

// ---- compute one 128x64x32 plane from [r][36] tiles ------------------------
// k-slot permutation: logical k = 8t + 2*kk8 + half (applied to A & B).
// Processed as two half-planes (float4 fragments) to halve live registers;
// mma order identical to the previous float4x2 version -> identical numerics.
template <int CVTA>
__device__ __forceinline__ void compute_chunk(
    const float* __restrict__ Ab, const float* __restrict__ Bb,
    float acc[2][4][4], int wm, int wn, int g, int t)
{
#pragma unroll
    for (int h = 0; h < 2; h++) {
        float a4[4][4], b4[4][4];
#pragma unroll
        for (int i = 0; i < 4; i++)
            *(float4*)&a4[i][0] = *(const float4*)(Ab + (wm * 32 + i * 8 + g) * 36 + t * 8 + h * 4);
#pragma unroll
        for (int i = 0; i < 4; i++)
            *(float4*)&b4[i][0] = *(const float4*)(Bb + (wn * 32 + i * 8 + g) * 36 + t * 8 + h * 4);
#pragma unroll
        for (int k2 = 0; k2 < 2; k2++) {
            uint32_t af[2][4], bf[4][2];
#pragma unroll
            for (int mi = 0; mi < 2; mi++) {
                if (CVTA) {
                    af[mi][0] = f2tf(a4[2 * mi][2 * k2]);
                    af[mi][1] = f2tf(a4[2 * mi + 1][2 * k2]);
                    af[mi][2] = f2tf(a4[2 * mi][2 * k2 + 1]);
                    af[mi][3] = f2tf(a4[2 * mi + 1][2 * k2 + 1]);
                } else {
                    af[mi][0] = __float_as_uint(a4[2 * mi][2 * k2]);
                    af[mi][1] = __float_as_uint(a4[2 * mi + 1][2 * k2]);
                    af[mi][2] = __float_as_uint(a4[2 * mi][2 * k2 + 1]);
                    af[mi][3] = __float_as_uint(a4[2 * mi + 1][2 * k2 + 1]);
                }
            }
#pragma unroll
            for (int ni = 0; ni < 4; ni++) {
                bf[ni][0] = __float_as_uint(b4[ni][2 * k2]);
                bf[ni][1] = __float_as_uint(b4[ni][2 * k2 + 1]);
            }
#pragma unroll
            for (int mi = 0; mi < 2; mi++)
#pragma unroll
                for (int ni = 0; ni < 4; ni++)
                    mma_tf32(acc[mi][ni], af[mi], bf[ni]);
        }
    }
}

// ---- stage one 32-k plane via cp.async -------------------------------------
__device__ __forceinline__ void issue_stage32(
    const float* __restrict__ Ab, const float* __restrict__ Bb, int K,
    uint32_t sa, uint32_t sb)
{
#pragma unroll
    for (int i = 0; i < 4; i++)
        cp16(sa + (uint32_t)(i * ROW36) * 4, Ab + (size_t)i * 32 * K);
#pragma unroll
    for (int i = 0; i < 2; i++)
        cp16(sb + (uint32_t)(i * ROW36) * 4, Bb + (size_t)i * 32 * K);
}

// 2-stage, BK=32, one wait + one barrier per 32-k chunk.
// Safety: the in-loop issue targets buf (c+1)&1, last read at compute(c-1);
// the barrier (after the wait, before the issue) orders all warps past
// compute(c-1). cvta is CTA-uniform -> coherent branch.
__device__ __forceinline__ void gemm_main32(
    const float* __restrict__ A, const float* __restrict__ B, int K,
    int row0, int col0, float* Sm, float acc[2][4][4],
    int tid, int wm, int wn, int g, int t, int cvta)
{
    const uint32_t su = smem_u32(Sm);
    const int ra = tid >> 3, q4 = (tid & 7) * 4;
    const float* Abase = A + (size_t)(row0 + ra) * K + q4;
    const float* Bbase = B + (size_t)(col0 + ra) * K + q4;
    const uint32_t sa = su + (uint32_t)(ra * 36 + q4) * 4;
    const uint32_t sb = sa + (uint32_t)AS_F * 4;
    const int nk = K >> 5;

    issue_stage32(Abase, Bbase, K, sa, sb); CP_COMMIT;
    for (int c = 0; c < nk; c++) {
        CP_WAIT(0);
        __syncthreads();
        if (c + 1 < nk) {
            const uint32_t so = (uint32_t)(((c + 1) & 1) * PL_F) * 4;
            issue_stage32(Abase + (c + 1) * 32, Bbase + (c + 1) * 32, K, sa + so, sb + so);
            CP_COMMIT;
        }
        const float* st = Sm + (c & 1) * PL_F;
        if (cvta) compute_chunk<1>(st, st + AS_F, acc, wm, wn, g, t);
        else      compute_chunk<0>(st, st + AS_F, acc, wm, wn, g, t);
    }
}

// ---------------- merged pre-conversion kernel (states + weights) -----------
struct WSeg { const float* src; int off; int cnt; };
struct WSegs { WSeg v[8]; };
#define CVT_STATE_BLOCKS 8192
#define CVT_W_BLOCKS 492            // WTF_TOTAL / 1024

__global__ void __launch_bounds__(256) cvt_all_kernel(
    const float* __restrict__ s, float* __restrict__ d,
    WSegs segs, float* __restrict__ wdst)
{
    int b = blockIdx.x;
    if (b < CVT_STATE_BLOCKS) {
        size_t i = (size_t)(b * 256 + threadIdx.x) * 4;
        float4 v = *(const float4*)(s + i);
        uint4 u = { f2tf(v.x), f2tf(v.y), f2tf(v.z), f2tf(v.w) };
        *(uint4*)(d + i) = u;
    } else {
        int i4 = ((b - CVT_STATE_BLOCKS) * 256 + threadIdx.x) * 4;
#pragma unroll
        for (int k = 0; k < 8; k++) {
            int off = segs.v[k].off, cnt = segs.v[k].cnt;
            if (i4 >= off && i4 < off + cnt) {
                float4 v = *(const float4*)(segs.v[k].src + (i4 - off));
                uint4 u = { f2tf(v.x), f2tf(v.y), f2tf(v.z), f2tf(v.w) };
                *(uint4*)(wdst + i4) = u;
            }
        }
    }
}

// ---------------- packed GEMM: op table, 1D grid of 128-row tiles -----------
// epi: 0=id, 1=relu, 2=abs, 4=encoder. flags: bit0=round out, bit1=cvt A.
struct GOp {
    const float* A; const float* B; const float* bias; float* C;
    int K; int Nout; int col0; int epi; int tileBase; int flags;
};
struct GOps { GOp v[11]; };
#define G_SMEM_BYTES ((2 * PL_F + 192) * 4)     // ~55.9 KB -> 3 CTAs/SM

__global__ void __launch_bounds__(256, 3) packed_gemm(
    GOps ops,
    const int* __restrict__ actions, const float* __restrict__ qvals,
    const float* __restrict__ W_act, const float* __restrict__ W_q,
    const float* __restrict__ b_act, const float* __restrict__ b_q)
{
    extern __shared__ float dsm[];
    float* bias_sh = dsm + 2 * PL_F;
    float* cvec_sh = bias_sh + 64;
    float* wq_sh   = cvec_sh + 64;

    const int bid = blockIdx.x;
    int j = 0;
#pragma unroll
    for (int k = 1; k < 11; k++) if (bid >= ops.v[k].tileBase) j = k;
    const GOp op = ops.v[j];

    const int tid = threadIdx.x;
    const int wid = tid >> 5, lane = tid & 31;
    const int wm = wid >> 1, wn = wid & 1;
    const int g = lane >> 2, t = lane & 3;
    const int row0 = (bid - op.tileBase) * 128;
    const int col0 = op.col0;
    const int epi = op.epi;
    const int rnd = op.flags & 1, cvta = (op.flags >> 1) & 1;

    if (tid < 64) {
        bias_sh[tid] = op.bias[col0 + tid];
        if (epi == 4) {
            cvec_sh[tid] = b_act[tid] + b_q[tid];
            wq_sh[tid] = W_q[tid];
        }
    }

    float acc[2][4][4];
#pragma unroll
    for (int mi = 0; mi < 2; mi++)
#pragma unroll
        for (int ni = 0; ni < 4; ni++)
#pragma unroll
            for (int jj = 0; jj < 4; jj++) acc[mi][ni][jj] = 0.f;

    gemm_main32(op.A, op.B, op.K, row0, col0, dsm, acc, tid, wm, wn, g, t, cvta);

    const int Nout = op.Nout;
#pragma unroll
    for (int mi = 0; mi < 2; mi++)
#pragma unroll
        for (int half = 0; half < 2; half++) {
            const int row = row0 + wm * 32 + mi * 16 + half * 8 + g;
            int act = 0; float qv = 0.f;
            if (epi == 4) { act = actions[row]; qv = qvals[row]; }
            float* dst = op.C + (size_t)row * Nout + col0;
#pragma unroll
            for (int ni = 0; ni < 4; ni++) {
                const int lc = wn * 32 + ni * 8 + t * 2;
                float v0 = acc[mi][ni][half * 2 + 0] + bias_sh[lc];
                float v1 = acc[mi][ni][half * 2 + 1] + bias_sh[lc + 1];
                if (epi == 4) {
                    v0 += cvec_sh[lc] + __ldg(&W_act[lc * 32 + act]) + qv * wq_sh[lc];
                    v1 += cvec_sh[lc + 1] + __ldg(&W_act[(lc + 1) * 32 + act]) + qv * wq_sh[lc + 1];
                } else if (epi == 1) {
                    v0 = fmaxf(v0, 0.f); v1 = fmaxf(v1, 0.f);
                } else if (epi == 2) {
                    v0 = fabsf(v0); v1 = fabsf(v1);
                }
                if (rnd) { v0 = __uint_as_float(f2tf(v0)); v1 = __uint_as_float(f2tf(v1)); }
                float2 o = { v0, v1 };
                *(float2*)(dst + lc) = o;
            }
        }
}

// ---------------- fused qkv GEMM + attention (+ inline wcomb) ---------------
#define QA_XS_F (2 * 128 * 36)
#define QA_WS_F (2 * 192 * 36)
#define QA_QS_F (128 * 196)
#define QA_SMEM_BYTES ((QA_XS_F + QA_WS_F + QA_QS_F + 192 + 65) * 4)

__global__ void __launch_bounds__(256) qkv_attn_kernel(
    const float* __restrict__ Wqkv_tf, const float* __restrict__ bqkv,
    const float* __restrict__ Wa2q, const float* __restrict__ ba2q,
    const float* __restrict__ Wo, const float* __restrict__ bo)
{
    extern __shared__ float sm[];
    float* xs = sm;                        // [2][128][36]
    float* ws = xs + QA_XS_F;              // [2][192][36]
    float* qs = ws + QA_WS_F;              // [128][196]
    float* bq = qs + QA_QS_F;              // 192
    float* wc = bq + 192;                  // 65

    const int tid = threadIdx.x;
    const int wid = tid >> 5, lane = tid & 31;
    const int wm = wid >> 1, wn = wid & 1;
    const int g = lane >> 2, t = lane & 3;
    const int row0 = blockIdx.x * 128;

    const uint32_t xs_u = smem_u32(xs);
    const uint32_t ws_u = smem_u32(ws);
#pragma unroll
    for (int i = 0; i < 8; i++) {          // x tile: 2048 float4
        int e = tid + i * 256;
        int r = e >> 4, q = e & 15;
        cp16(xs_u + (uint32_t)((q >> 3) * (128 * 36) + r * 36 + (q & 7) * 4) * 4,
             g_x + (size_t)(row0 + r) * 64 + q * 4);
    }
#pragma unroll
    for (int i = 0; i < 12; i++) {         // Wqkv: 3072 float4
        int e = tid + i * 256;
        int n = e >> 4, q = e & 15;
        cp16(ws_u + (uint32_t)((q >> 3) * (192 * 36) + n * 36 + (q & 7) * 4) * 4,
             Wqkv_tf + (size_t)n * 64 + q * 4);
    }
    if (tid < 192) bq[tid] = bqkv[tid];
    // inline wcomb = Wa2q @ Wo (hidden under cp.async wait)
    if (tid < 64) {
        float s = 0.f;
#pragma unroll 8
        for (int c = 0; c < 64; c++) s += Wa2q[c] * Wo[c * 64 + tid];
        wc[tid] = s;
    }
    if (wid == 6) {                        // bcomb = Wa2q.bo + ba2q
        float v = Wa2q[lane] * bo[lane] + Wa2q[lane + 32] * bo[lane + 32];
#pragma unroll
        for (int off = 16; off > 0; off >>= 1) v += __shfl_xor_sync(0xffffffffu, v, off);
        if (lane == 0) wc[64] = v + ba2q[0];
    }
    CP_COMMIT; CP_WAIT(0);
    __syncthreads();

    // ---- phase B: qkv = x @ Wqkv^T (3 col blocks of 64); x pre-rounded ----
#pragma unroll 1
    for (int cb = 0; cb < 3; cb++) {
        float acc[2][4][4];
#pragma unroll
        for (int mi = 0; mi < 2; mi++)
#pragma unroll
            for (int ni = 0; ni < 4; ni++)
#pragma unroll
                for (int jj = 0; jj < 4; jj++) acc[mi][ni][jj] = 0.f;

#pragma unroll
        for (int c = 0; c < 2; c++)
            compute_chunk<0>(xs + c * (128 * 36),
                             ws + c * (192 * 36) + (cb * 64) * 36,
                             acc, wm, wn, g, t);

#pragma unroll
        for (int mi = 0; mi < 2; mi++)
#pragma unroll
            for (int half = 0; half < 2; half++) {
                const int row = wm * 32 + mi * 16 + half * 8 + g;
#pragma unroll
                for (int ni = 0; ni < 4; ni++) {
                    const int lc = wn * 32 + ni * 8 + t * 2;
                    qs[row * 196 + cb * 64 + lc]     = acc[mi][ni][half * 2 + 0] + bq[cb * 64 + lc];
                    qs[row * 196 + cb * 64 + lc + 1] = acc[mi][ni][half * 2 + 1] + bq[cb * 64 + lc + 1];
                }
            }
    }
    __syncthreads();

    // ---- phase C: attention per sample (2 samples per warp) ----
    const int h = lane >> 3, a = lane & 7;
#pragma unroll
    for (int s2 = 0; s2 < 2; s2++) {
        const int s = wid * 2 + s2;
        const float* base = qs + s * 8 * 196;

        float q[16];
#pragma unroll
        for (int d = 0; d < 16; d++) q[d] = base[a * 196 + h * 16 + d];
        float sc[8], m = -1e30f;
#pragma unroll
        for (int b = 0; b < 8; b++) {
            float acc = 0.f;
#pragma unroll
            for (int d = 0; d < 16; d++) acc += q[d] * base[b * 196 + 64 + h * 16 + d];
            sc[b] = acc * 0.25f;          // 1/sqrt(16)
            m = fmaxf(m, sc[b]);
        }
        float sum = 0.f;
#pragma unroll
        for (int b = 0; b < 8; b++) { sc[b] = __expf(sc[b] - m); sum += sc[b]; }
        float inv = 1.f / sum;
        float o[16];
#pragma unroll
        for (int d = 0; d < 16; d++) o[d] = 0.f;
#pragma unroll
        for (int b = 0; b < 8; b++) {
            float p = sc[b] * inv;
#pragma unroll
            for (int d = 0; d < 16; d++) o[d] += p * base[b * 196 + 128 + h * 16 + d];
        }
        float part = 0.f;
#pragma unroll
        for (int d = 0; d < 16; d++) part += o[d] * wc[h * 16 + d];
        part += __shfl_xor_sync(0xffffffffu, part, 8);
        part += __shfl_xor_sync(0xffffffffu, part, 16);
        if (h == 0) {
            const int n = blockIdx.x * 16 + s;
            g_aq[n * 8 + a] = part + wc[64];
        }
    }
}

// ---------------- final mixing: elu(aq @ w1 + b1) . w_f + v ----------------
__global__ void __launch_bounds__(256) final_kernel(
    const float* __restrict__ Wv2, const float* __restrict__ bv2,
    float* __restrict__ out)
{
    const int warp = threadIdx.x >> 5, lane = threadIdx.x & 31;
    const int n = blockIdx.x * 8 + warp;
    if (n >= NTOT) return;

    float aqv[8];
#pragma unroll
    for (int a = 0; a < 8; a++) aqv[a] = g_aq[n * 8 + a];

    float tot = 0.f;
#pragma unroll
    for (int jj = 0; jj < 2; jj++) {
        int e = jj * 32 + lane;
        float hsum = g_b1[n * 64 + e];
#pragma unroll
        for (int a = 0; a < 8; a++) hsum += aqv[a] * g_w1[(size_t)n * 512 + a * 64 + e];
        float hid = hsum > 0.f ? hsum : expm1f(hsum);
        tot += hid * g_wf[n * 64 + e] + g_v1[n * 64 + e] * Wv2[e];
    }
#pragma unroll
    for (int off = 16; off > 0; off >>= 1) tot += __shfl_xor_sync(0xffffffffu, tot, off);
    if (lane == 0) out[n] = tot + bv2[0];
}

// ---------------- launch ----------------------------------------------------
extern "C" void kernel_launch(void* const* d_in, const int* in_sizes, int n_in,
                              void* d_out, int out_size)
{
    const float* agent_qs = (const float*)d_in[0];
    const float* states   = (const float*)d_in[1];
    const float* obs      = (const float*)d_in[2];
    const int*   actions  = (const int*)d_in[3];
    const float* W_obs = (const float*)d_in[4];  const float* b_obs = (const float*)d_in[5];
    const float* W_act = (const float*)d_in[6];  const float* b_act = (const float*)d_in[7];
    const float* W_q   = (const float*)d_in[8];  const float* b_q   = (const float*)d_in[9];
    const float* Wqkv  = (const float*)d_in[10]; const float* bqkv  = (const float*)d_in[11];
    const float* Wo    = (const float*)d_in[12]; const float* bo    = (const float*)d_in[13];
    const float* Wa2q  = (const float*)d_in[14]; const float* ba2q  = (const float*)d_in[15];
    const float* Wh1a  = (const float*)d_in[16]; const float* bh1a  = (const float*)d_in[17];
    const float* Wh1b  = (const float*)d_in[18]; const float* bh1b  = (const float*)d_in[19];
    const float* Whfa  = (const float*)d_in[20]; const float* bhfa  = (const float*)d_in[21];
    const float* Whfb  = (const float*)d_in[22]; const float* bhfb  = (const float*)d_in[23];
    const float* Wb1   = (const float*)d_in[24]; const float* bb1   = (const float*)d_in[25];
    const float* Wv1   = (const float*)d_in[26]; const float* bv1   = (const float*)d_in[27];
    const float* Wv2   = (const float*)d_in[28]; const float* bv2   = (const float*)d_in[29];
    float* out = (float*)d_out;

    void *p_x, *p_stf, *p_wtf, *p_h1, *p_hf, *p_w1, *p_wf, *p_b1, *p_v1;
    cudaGetSymbolAddress(&p_x,   g_x);
    cudaGetSymbolAddress(&p_stf, g_stf);
    cudaGetSymbolAddress(&p_wtf, g_wtf);
    cudaGetSymbolAddress(&p_h1,  g_h1);
    cudaGetSymbolAddress(&p_hf,  g_hf);
    cudaGetSymbolAddress(&p_w1,  g_w1);
    cudaGetSymbolAddress(&p_wf,  g_wf);
    cudaGetSymbolAddress(&p_b1,  g_b1);
    cudaGetSymbolAddress(&p_v1,  g_v1);
    float* wtf = (float*)p_wtf;

    cudaFuncSetAttribute(packed_gemm,     cudaFuncAttributeMaxDynamicSharedMemorySize, G_SMEM_BYTES);
    cudaFuncSetAttribute(qkv_attn_kernel, cudaFuncAttributeMaxDynamicSharedMemorySize, QA_SMEM_BYTES);

    // 0) pre-convert states + weights (one launch)
    WSegs segs;
    segs.v[0] = { W_obs, OFF_WOBS, 16384 };
    segs.v[1] = { Wqkv,  OFF_WQKV, 12288 };
    segs.v[2] = { Wh1a,  OFF_WH1A, 131072 };
    segs.v[3] = { Whfa,  OFF_WHFA, 131072 };
    segs.v[4] = { Wh1b,  OFF_WH1B, 131072 };
    segs.v[5] = { Whfb,  OFF_WHFB, 16384 };
    segs.v[6] = { Wb1,   OFF_WB1,  32768 };
    segs.v[7] = { Wv1,   OFF_WV1,  32768 };
    cvt_all_kernel<<<CVT_STATE_BLOCKS + CVT_W_BLOCKS, 256>>>(states, (float*)p_stf, segs, wtf);

    // 1) mega launch 1: encoder (1024 tiles, cvta) + state hypernets (1280)
    GOps m1 = {};
    m1.v[0] = { obs, wtf + OFF_WOBS, b_obs, (float*)p_x, 256, 64, 0, 4, 0, 3 };
    for (int i = 0; i < 4; i++)
        m1.v[1 + i] = { (float*)p_stf, wtf + OFF_WH1A, bh1a, (float*)p_h1, 512, 256, i * 64, 1, 1024 + i * 128, 1 };
    for (int i = 0; i < 4; i++)
        m1.v[5 + i] = { (float*)p_stf, wtf + OFF_WHFA, bhfa, (float*)p_hf, 512, 256, i * 64, 1, 1536 + i * 128, 1 };
    m1.v[9]  = { (float*)p_stf, wtf + OFF_WB1, bb1, (float*)p_b1, 512, 64, 0, 0, 2048, 0 };
    m1.v[10] = { (float*)p_stf, wtf + OFF_WV1, bv1, (float*)p_v1, 512, 64, 0, 1, 2176, 0 };
    packed_gemm<<<2304, 256, G_SMEM_BYTES>>>(m1, actions, agent_qs, W_act, W_q, b_act, b_q);

    // 2) fused qkv + attention (wcomb inline) -> attended_qs
    qkv_attn_kernel<<<1024, 256, QA_SMEM_BYTES>>>(wtf + OFF_WQKV, bqkv, Wa2q, ba2q, Wo, bo);

    // 3) mega launch 2: second hypernet stage (w1 x8 + wf = 1152 tiles)
    GOps m2 = {};
    for (int i = 0; i < 8; i++)
        m2.v[i] = { (float*)p_h1, wtf + OFF_WH1B, bh1b, (float*)p_w1, 256, 512, i * 64, 2, i * 128, 0 };
    m2.v[8]  = { (float*)p_hf, wtf + OFF_WHFB, bhfb, (float*)p_wf, 256, 64, 0, 2, 1024, 0 };
    m2.v[9]  = { (float*)p_hf, wtf + OFF_WHFB, bhfb, (float*)p_wf, 256, 64, 0, 2, 0x7FFFFFFF, 0 };
    m2.v[10] = { (float*)p_hf, wtf + OFF_WHFB, bhfb, (float*)p_wf, 256, 64, 0, 2, 0x7FFFFFFF, 0 };
    packed_gemm<<<1152, 256, G_SMEM_BYTES>>>(m2, actions, agent_qs, W_act, W_q, b_act, b_q);

    // 4) final mix -> y
    final_kernel<<<2048, 256>>>(Wv2, bv2, out);
}

// round 12
// speedup vs baseline: 1.3814x; 1.3218x over previous
#include <cuda_runtime.h>
#include <cuda_fp16.h>
#include <math.h>
#include <cstdint>

#define NTOT 16384

// ---- tf32 (encoder) plane geometry ----
#define AS_F 4608          // 128*36 floats
#define BS_F 2304          // 64*36 floats
#define PL_F (AS_F + BS_F)
#define ROW36 (32 * 36)

// ---- fp16 plane geometry: 16 words (64B) per 32-half row, NO padding.
// 16B-aligned for cp.async (64B row stride) and conflict-free fragment LDS:
// quarter-warp = 2 rows x 4 threads -> words [32r,32r+32) -> banks 0-15/16-31.
#define ROWW 16
#define APLH (128 * ROWW)          // 2048 words
#define BPLH (64 * ROWW)           // 1024 words
#define PLH  (APLH + BPLH)         // 3072 words per stage

// ---------------- scratch (device globals) ----------------------------------
__device__ __align__(16) __half g_xh[131072 * 64];   // encoder out, fp16 k-perm
__device__ __align__(16) __half g_sth[NTOT * 512];   // states fp16 k-perm
__device__ __align__(16) __half g_wh[487424];        // fp16 k-perm weights pool
__device__ __align__(16) float  g_wtf[16384];        // Wobs tf32-rounded fp32
__device__ __align__(16) __half g_h1h[NTOT * 256];   // h1 fp16 k-perm
__device__ __align__(16) __half g_hfh[NTOT * 256];   // hf fp16 k-perm
__device__ __align__(16) float g_aq[NTOT * 8];
__device__ __align__(16) float g_w1[NTOT * 512];
__device__ __align__(16) float g_wf[NTOT * 64];
__device__ __align__(16) float g_b1[NTOT * 64];
__device__ __align__(16) float g_v1[NTOT * 64];

// g_wh offsets (halves)
#define HOFF_WQKV 0        // 12288
#define HOFF_WH1A 12288    // 131072
#define HOFF_WHFA 143360   // 131072
#define HOFF_WH1B 274432   // 131072
#define HOFF_WHFB 405504   // 16384
#define HOFF_WB1  421888   // 32768
#define HOFF_WV1  454656   // 32768

// ---------------- helpers ---------------------------------------------------
__device__ __forceinline__ uint32_t f2tf(float x) {
    uint32_t r;
    asm("cvt.rna.tf32.f32 %0, %1;" : "=r"(r) : "f"(x));
    return r;
}
__device__ __forceinline__ uint32_t smem_u32(const void* p) {
    uint32_t a;
    asm("{ .reg .u64 t; cvta.to.shared.u64 t, %1; cvt.u32.u64 %0, t; }" : "=r"(a) : "l"(p));
    return a;
}
__device__ __forceinline__ void cp16(uint32_t s, const void* g) {
    asm volatile("cp.async.cg.shared.global [%0], [%1], 16;" :: "r"(s), "l"(g));
}
#define CP_COMMIT asm volatile("cp.async.commit_group;" ::: "memory")
#define CP_WAIT(N) asm volatile("cp.async.wait_group %0;" :: "n"(N) : "memory")

__device__ __forceinline__ void mma_tf32(float* c, const uint32_t* a, const uint32_t* b) {
    asm volatile(
        "mma.sync.aligned.m16n8k8.row.col.f32.tf32.tf32.f32 "
        "{%0,%1,%2,%3}, {%4,%5,%6,%7}, {%8,%9}, {%0,%1,%2,%3};\n"
        : "+f"(c[0]), "+f"(c[1]), "+f"(c[2]), "+f"(c[3])
        : "r"(a[0]), "r"(a[1]), "r"(a[2]), "r"(a[3]), "r"(b[0]), "r"(b[1]));
}
__device__ __forceinline__ void mma_f16(float* c, uint32_t a0, uint32_t a1, uint32_t a2,
                                        uint32_t a3, uint32_t b0, uint32_t b1) {
    asm volatile(
        "mma.sync.aligned.m16n8k16.row.col.f32.f16.f16.f32 "
        "{%0,%1,%2,%3}, {%4,%5,%6,%7}, {%8,%9}, {%0,%1,%2,%3};\n"
        : "+f"(c[0]), "+f"(c[1]), "+f"(c[2]), "+f"(c[3])
        : "r"(a0), "r"(a1), "r"(a2), "r"(a3), "r"(b0), "r"(b1));
}

// k-perm within each 32-half group: logical half l -> word 4t+2g+h,
// where g = l>>4 (16-subgroup), h = (l&15)>=8, t = ((l&15) mod 8)>>1.
// Thread t then reads words [4t,4t+3] as one uint4 per row.
__device__ __forceinline__ int perm_half_base(int c) {   // c even; returns half idx
    int lg = c & 31;
    int gg = lg >> 4, l16 = lg & 15;
    int hi = (l16 >= 8) ? 1 : 0;
    int tt = (l16 - (hi ? 8 : 0)) >> 1;
    return (c & ~31) + (4 * tt + 2 * gg + hi) * 2;
}

// ---------------- fp16 compute: one 128x64x32 chunk -> 16 mma ---------------
__device__ __forceinline__ void compute_chunk_h(
    const uint32_t* __restrict__ Ab, const uint32_t* __restrict__ Bb,
    float acc[2][4][4], int wm, int wn, int g, int t)
{
    uint4 ar[2][2], br[4];
#pragma unroll
    for (int mi = 0; mi < 2; mi++)
#pragma unroll
        for (int rr = 0; rr < 2; rr++)
            ar[mi][rr] = *(const uint4*)(Ab + (wm * 32 + mi * 16 + rr * 8 + g) * ROWW + t * 4);
#pragma unroll
    for (int ni = 0; ni < 4; ni++)
        br[ni] = *(const uint4*)(Bb + (wn * 32 + ni * 8 + g) * ROWW + t * 4);
#pragma unroll
    for (int mi = 0; mi < 2; mi++)
#pragma unroll
        for (int ni = 0; ni < 4; ni++)
            mma_f16(acc[mi][ni], ar[mi][0].x, ar[mi][1].x, ar[mi][0].y, ar[mi][1].y,
                    br[ni].x, br[ni].y);
#pragma unroll
    for (int mi = 0; mi < 2; mi++)
#pragma unroll
        for (int ni = 0; ni < 4; ni++)
            mma_f16(acc[mi][ni], ar[mi][0].z, ar[mi][1].z, ar[mi][0].w, ar[mi][1].w,
                    br[ni].z, br[ni].w);
}

// ---------------- tf32 compute (encoder only) -------------------------------
__device__ __forceinline__ void compute_chunk_t(
    const float* __restrict__ Ab, const float* __restrict__ Bb,
    float acc[2][4][4], int wm, int wn, int g, int t)
{
#pragma unroll
    for (int h = 0; h < 2; h++) {
        float a4[4][4], b4[4][4];
#pragma unroll
        for (int i = 0; i < 4; i++)
            *(float4*)&a4[i][0] = *(const float4*)(Ab + (wm * 32 + i * 8 + g) * 36 + t * 8 + h * 4);
#pragma unroll
        for (int i = 0; i < 4; i++)
            *(float4*)&b4[i][0] = *(const float4*)(Bb + (wn * 32 + i * 8 + g) * 36 + t * 8 + h * 4);
#pragma unroll
        for (int k2 = 0; k2 < 2; k2++) {
            uint32_t af[2][4], bf[4][2];
#pragma unroll
            for (int mi = 0; mi < 2; mi++) {
                af[mi][0] = f2tf(a4[2 * mi][2 * k2]);
                af[mi][1] = f2tf(a4[2 * mi + 1][2 * k2]);
                af[mi][2] = f2tf(a4[2 * mi][2 * k2 + 1]);
                af[mi][3] = f2tf(a4[2 * mi + 1][2 * k2 + 1]);
            }
#pragma unroll
            for (int ni = 0; ni < 4; ni++) {
                bf[ni][0] = __float_as_uint(b4[ni][2 * k2]);
                bf[ni][1] = __float_as_uint(b4[ni][2 * k2 + 1]);
            }
#pragma unroll
            for (int mi = 0; mi < 2; mi++)
#pragma unroll
                for (int ni = 0; ni < 4; ni++)
                    mma_tf32(acc[mi][ni], af[mi], bf[ni]);
        }
    }
}

// ---------------- conversion kernel (fp16 perm + Wobs tf32) ------------------
__device__ __forceinline__ void cvt_group_h(const float* __restrict__ src, __half* __restrict__ dst)
{
    float v[32];
#pragma unroll
    for (int i = 0; i < 8; i++) *(float4*)&v[i * 4] = *(const float4*)(src + i * 4);
    uint32_t w[16];
#pragma unroll
    for (int W = 0; W < 16; W++) {
        int tt = W >> 2, gg = (W >> 1) & 1, hi = W & 1;
        int l0 = gg * 16 + hi * 8 + tt * 2;
        __half2 h = __floats2half2_rn(v[l0], v[l0 + 1]);
        w[W] = *(uint32_t*)&h;
    }
#pragma unroll
    for (int i = 0; i < 4; i++) ((uint4*)dst)[i] = *(uint4*)&w[i * 4];
}

struct HSegs { const float* src[7]; int gbase[7]; };
#define CVT_ST_BLK 1024
#define CVT_W_GROUPS 15232
#define CVT_W_BLK 60
#define CVT_OBS_BLK 16

__global__ void __launch_bounds__(256) cvt_all_kernel(
    const float* __restrict__ states, __half* __restrict__ sth,
    HSegs segs, __half* __restrict__ wh,
    const float* __restrict__ Wobs, float* __restrict__ wtf)
{
    int b = blockIdx.x, tid = threadIdx.x;
    if (b < CVT_ST_BLK) {
        int gidx = b * 256 + tid;
        cvt_group_h(states + (size_t)gidx * 32, sth + (size_t)gidx * 32);
    } else if (b < CVT_ST_BLK + CVT_W_BLK) {
        int gidx = (b - CVT_ST_BLK) * 256 + tid;
        if (gidx < CVT_W_GROUPS) {
            int k = 0;
#pragma unroll
            for (int kk = 1; kk < 7; kk++) if (gidx >= segs.gbase[kk]) k = kk;
            cvt_group_h(segs.src[k] + (size_t)(gidx - segs.gbase[k]) * 32,
                        wh + (size_t)gidx * 32);
        }
    } else {
        int i4 = ((b - CVT_ST_BLK - CVT_W_BLK) * 256 + tid) * 4;
        float4 v = *(const float4*)(Wobs + i4);
        uint4 u = { f2tf(v.x), f2tf(v.y), f2tf(v.z), f2tf(v.w) };
        *(uint4*)(wtf + i4) = u;
    }
}

// ---------------- encoder GEMM (tf32): obs -> g_xh (fp16 perm) ---------------
#define ENC_SMEM_BYTES ((2 * PL_F + 192) * 4)

__global__ void __launch_bounds__(256, 3) enc_gemm(
    const float* __restrict__ obs, const float* __restrict__ Wobs_tf,
    const float* __restrict__ b_obs, __half* __restrict__ Cx,
    const int* __restrict__ actions, const float* __restrict__ qvals,
    const float* __restrict__ W_act, const float* __restrict__ W_q,
    const float* __restrict__ b_act, const float* __restrict__ b_q)
{
    extern __shared__ float dsm[];
    float* bias_sh = dsm + 2 * PL_F;
    float* cvec_sh = bias_sh + 64;
    float* wq_sh   = cvec_sh + 64;

    const int tid = threadIdx.x;
    const int wid = tid >> 5, lane = tid & 31;
    const int wm = wid >> 1, wn = wid & 1;
    const int g = lane >> 2, t = lane & 3;
    const int row0 = blockIdx.x * 128;
    const int K = 256;

    if (tid < 64) {
        bias_sh[tid] = b_obs[tid];
        cvec_sh[tid] = b_act[tid] + b_q[tid];
        wq_sh[tid] = W_q[tid];
    }

    float acc[2][4][4];
#pragma unroll
    for (int mi = 0; mi < 2; mi++)
#pragma unroll
        for (int ni = 0; ni < 4; ni++)
#pragma unroll
            for (int jj = 0; jj < 4; jj++) acc[mi][ni][jj] = 0.f;

    {   // tf32 pipeline, BK=32, 2-stage
        const uint32_t su = smem_u32(dsm);
        const int ra = tid >> 3, q4 = (tid & 7) * 4;
        const float* Ap = obs + (size_t)(row0 + ra) * K + q4;
        const float* Bp = Wobs_tf + (size_t)ra * K + q4;
        const uint32_t sa = su + (uint32_t)(ra * 36 + q4) * 4;
        const uint32_t sb = sa + (uint32_t)AS_F * 4;
        const int nk = K >> 5;
#pragma unroll
        for (int i = 0; i < 4; i++) cp16(sa + (uint32_t)(i * ROW36) * 4, Ap + (size_t)i * 32 * K);
#pragma unroll
        for (int i = 0; i < 2; i++) cp16(sb + (uint32_t)(i * ROW36) * 4, Bp + (size_t)i * 32 * K);
        CP_COMMIT;
        for (int c = 0; c < nk; c++) {
            CP_WAIT(0);
            __syncthreads();
            if (c + 1 < nk) {
                const uint32_t so = (uint32_t)(((c + 1) & 1) * PL_F) * 4;
#pragma unroll
                for (int i = 0; i < 4; i++)
                    cp16(sa + so + (uint32_t)(i * ROW36) * 4, Ap + (c + 1) * 32 + (size_t)i * 32 * K);
#pragma unroll
                for (int i = 0; i < 2; i++)
                    cp16(sb + so + (uint32_t)(i * ROW36) * 4, Bp + (c + 1) * 32 + (size_t)i * 32 * K);
            }
            CP_COMMIT;
            const float* st = dsm + (c & 1) * PL_F;
            compute_chunk_t(st, st + AS_F, acc, wm, wn, g, t);
        }
    }

#pragma unroll
    for (int mi = 0; mi < 2; mi++)
#pragma unroll
        for (int hh = 0; hh < 2; hh++) {
            const int row = row0 + wm * 32 + mi * 16 + hh * 8 + g;
            const int act = actions[row];
            const float qv = qvals[row];
#pragma unroll
            for (int ni = 0; ni < 4; ni++) {
                const int lc = wn * 32 + ni * 8 + t * 2;
                float v0 = acc[mi][ni][hh * 2 + 0] + bias_sh[lc]
                         + cvec_sh[lc] + __ldg(&W_act[lc * 32 + act]) + qv * wq_sh[lc];
                float v1 = acc[mi][ni][hh * 2 + 1] + bias_sh[lc + 1]
                         + cvec_sh[lc + 1] + __ldg(&W_act[(lc + 1) * 32 + act]) + qv * wq_sh[lc + 1];
                *(__half2*)(Cx + (size_t)row * 64 + perm_half_base(lc)) = __floats2half2_rn(v0, v1);
            }
        }
}

// ---------------- fp16 packed GEMM ------------------------------------------
// epi: 0=id, 1=relu, 2=abs. flags bit0 = fp16-perm output (C is __half*).
struct HOp {
    const __half* A; const __half* B; const float* bias; void* C;
    int K; int Nout; int col0; int epi; int tileBase; int flags;
};
struct HOps { HOp v[10]; };
#define HP_SMEM_BYTES ((2 * PLH + 64) * 4)

__global__ void __launch_bounds__(256, 3) hp_gemm(HOps ops)
{
    extern __shared__ uint32_t hsm[];
    float* bias_sh = (float*)(hsm + 2 * PLH);

    const int bid = blockIdx.x;
    int j = 0;
#pragma unroll
    for (int k = 1; k < 10; k++) if (bid >= ops.v[k].tileBase) j = k;
    const HOp op = ops.v[j];

    const int tid = threadIdx.x;
    const int wid = tid >> 5, lane = tid & 31;
    const int wm = wid >> 1, wn = wid & 1;
    const int g = lane >> 2, t = lane & 3;
    const int row0 = (bid - op.tileBase) * 128;
    const int col0 = op.col0;
    const int K = op.K;

    if (tid < 64) bias_sh[tid] = op.bias[col0 + tid];

    float acc[2][4][4];
#pragma unroll
    for (int mi = 0; mi < 2; mi++)
#pragma unroll
        for (int ni = 0; ni < 4; ni++)
#pragma unroll
            for (int jj = 0; jj < 4; jj++) acc[mi][ni][jj] = 0.f;

    {   // fp16 pipeline: BK=32, 2-stage, 3 cp/thread/chunk
        const uint32_t su = smem_u32(hsm);
        const int arow = tid >> 2, awq = tid & 3;
        const __half* Ap  = op.A + (size_t)(row0 + arow) * K + awq * 8;
        const __half* Ap2 = Ap + (size_t)64 * K;
        const __half* Bp  = op.B + (size_t)(col0 + arow) * K + awq * 8;
        const uint32_t sa = su + (uint32_t)(arow * ROWW + awq * 4) * 4;
        const uint32_t sa2 = sa + (uint32_t)(64 * ROWW) * 4;
        const uint32_t sb = su + (uint32_t)(APLH + arow * ROWW + awq * 4) * 4;
        const int nk = K >> 5;
        cp16(sa, Ap); cp16(sa2, Ap2); cp16(sb, Bp);
        CP_COMMIT;
        for (int c = 0; c < nk; c++) {
            CP_WAIT(0);
            __syncthreads();
            if (c + 1 < nk) {
                const uint32_t so = (uint32_t)(((c + 1) & 1) * PLH) * 4;
                cp16(sa + so, Ap + (c + 1) * 32);
                cp16(sa2 + so, Ap2 + (c + 1) * 32);
                cp16(sb + so, Bp + (c + 1) * 32);
            }
            CP_COMMIT;
            const uint32_t* st = hsm + (c & 1) * PLH;
            compute_chunk_h(st, st + APLH, acc, wm, wn, g, t);
        }
    }

    const int Nout = op.Nout, epi = op.epi, hout = op.flags & 1;
#pragma unroll
    for (int mi = 0; mi < 2; mi++)
#pragma unroll
        for (int hh = 0; hh < 2; hh++) {
            const int row = row0 + wm * 32 + mi * 16 + hh * 8 + g;
#pragma unroll
            for (int ni = 0; ni < 4; ni++) {
                const int lc = wn * 32 + ni * 8 + t * 2;
                float v0 = acc[mi][ni][hh * 2 + 0] + bias_sh[lc];
                float v1 = acc[mi][ni][hh * 2 + 1] + bias_sh[lc + 1];
                if (epi == 1) { v0 = fmaxf(v0, 0.f); v1 = fmaxf(v1, 0.f); }
                else if (epi == 2) { v0 = fabsf(v0); v1 = fabsf(v1); }
                if (hout) {
                    const int cgl = col0 + lc;
                    *(__half2*)((__half*)op.C + (size_t)row * Nout + perm_half_base(cgl))
                        = __floats2half2_rn(v0, v1);
                } else {
                    float2 o = { v0, v1 };
                    *(float2*)((float*)op.C + (size_t)row * Nout + col0 + lc) = o;
                }
            }
        }
}

// ---------------- fused qkv (fp16) + attention ------------------------------
#define XPLH (128 * ROWW)
#define WPLH (192 * ROWW)
#define QA_QS_F (128 * 196)
#define QA_SMEM_BYTES ((2 * XPLH + 2 * WPLH + QA_QS_F + 192 + 65) * 4)

__global__ void __launch_bounds__(256) qkv_attn_kernel(
    const __half* __restrict__ Wqkv_h, const float* __restrict__ bqkv,
    const float* __restrict__ Wa2q, const float* __restrict__ ba2q,
    const float* __restrict__ Wo, const float* __restrict__ bo)
{
    extern __shared__ uint32_t qsm[];
    uint32_t* xs = qsm;                     // [2][128][ROWW]
    uint32_t* ws = xs + 2 * XPLH;           // [2][192][ROWW]
    float* qs = (float*)(ws + 2 * WPLH);    // [128][196]
    float* bq = qs + QA_QS_F;
    float* wc = bq + 192;

    const int tid = threadIdx.x;
    const int wid = tid >> 5, lane = tid & 31;
    const int wm = wid >> 1, wn = wid & 1;
    const int g = lane >> 2, t = lane & 3;
    const int row0 = blockIdx.x * 128;

    const uint32_t xs_u = smem_u32(xs);
    const uint32_t ws_u = smem_u32(ws);
#pragma unroll
    for (int i = 0; i < 4; i++) {           // x: 1024 16B units
        int u = tid + i * 256;
        int c = u >> 9, r = (u >> 2) & 127, wq = u & 3;
        cp16(xs_u + (uint32_t)(c * XPLH + r * ROWW + wq * 4) * 4,
             g_xh + (size_t)(row0 + r) * 64 + c * 32 + wq * 8);
    }
#pragma unroll
    for (int i = 0; i < 6; i++) {           // Wqkv: 1536 16B units
        int u = tid + i * 256;
        int c = (u >= 768) ? 1 : 0;
        int rem = u - c * 768;
        int r = rem >> 2, wq = rem & 3;
        cp16(ws_u + (uint32_t)(c * WPLH + r * ROWW + wq * 4) * 4,
             Wqkv_h + (size_t)r * 64 + c * 32 + wq * 8);
    }
    if (tid < 192) bq[tid] = bqkv[tid];
    if (tid < 64) {
        float s = 0.f;
#pragma unroll 8
        for (int c = 0; c < 64; c++) s += Wa2q[c] * Wo[c * 64 + tid];
        wc[tid] = s;
    }
    if (wid == 6) {
        float v = Wa2q[lane] * bo[lane] + Wa2q[lane + 32] * bo[lane + 32];
#pragma unroll
        for (int off = 16; off > 0; off >>= 1) v += __shfl_xor_sync(0xffffffffu, v, off);
        if (lane == 0) wc[64] = v + ba2q[0];
    }
    CP_COMMIT; CP_WAIT(0);
    __syncthreads();

    // ---- phase B: qkv = x @ Wqkv^T (fp16, 3 col blocks) ----
#pragma unroll 1
    for (int cb = 0; cb < 3; cb++) {
        float acc[2][4][4];
#pragma unroll
        for (int mi = 0; mi < 2; mi++)
#pragma unroll
            for (int ni = 0; ni < 4; ni++)
#pragma unroll
                for (int jj = 0; jj < 4; jj++) acc[mi][ni][jj] = 0.f;

#pragma unroll
        for (int c = 0; c < 2; c++)
            compute_chunk_h(xs + c * XPLH, ws + c * WPLH + (cb * 64) * ROWW,
                            acc, wm, wn, g, t);

#pragma unroll
        for (int mi = 0; mi < 2; mi++)
#pragma unroll
            for (int hh = 0; hh < 2; hh++) {
                const int row = wm * 32 + mi * 16 + hh * 8 + g;
#pragma unroll
                for (int ni = 0; ni < 4; ni++) {
                    const int lc = wn * 32 + ni * 8 + t * 2;
                    qs[row * 196 + cb * 64 + lc]     = acc[mi][ni][hh * 2 + 0] + bq[cb * 64 + lc];
                    qs[row * 196 + cb * 64 + lc + 1] = acc[mi][ni][hh * 2 + 1] + bq[cb * 64 + lc + 1];
                }
            }
    }
    __syncthreads();

    // ---- phase C: attention per sample (2 samples per warp) ----
    const int h = lane >> 3, a = lane & 7;
#pragma unroll
    for (int s2 = 0; s2 < 2; s2++) {
        const int s = wid * 2 + s2;
        const float* base = qs + s * 8 * 196;

        float q[16];
#pragma unroll
        for (int d = 0; d < 16; d++) q[d] = base[a * 196 + h * 16 + d];
        float sc[8], m = -1e30f;
#pragma unroll
        for (int b = 0; b < 8; b++) {
            float acc = 0.f;
#pragma unroll
            for (int d = 0; d < 16; d++) acc += q[d] * base[b * 196 + 64 + h * 16 + d];
            sc[b] = acc * 0.25f;
            m = fmaxf(m, sc[b]);
        }
        float sum = 0.f;
#pragma unroll
        for (int b = 0; b < 8; b++) { sc[b] = __expf(sc[b] - m); sum += sc[b]; }
        float inv = 1.f / sum;
        float o[16];
#pragma unroll
        for (int d = 0; d < 16; d++) o[d] = 0.f;
#pragma unroll
        for (int b = 0; b < 8; b++) {
            float p = sc[b] * inv;
#pragma unroll
            for (int d = 0; d < 16; d++) o[d] += p * base[b * 196 + 128 + h * 16 + d];
        }
        float part = 0.f;
#pragma unroll
        for (int d = 0; d < 16; d++) part += o[d] * wc[h * 16 + d];
        part += __shfl_xor_sync(0xffffffffu, part, 8);
        part += __shfl_xor_sync(0xffffffffu, part, 16);
        if (h == 0) {
            const int n = blockIdx.x * 16 + s;
            g_aq[n * 8 + a] = part + wc[64];
        }
    }
}

// ---------------- final mixing ----------------------------------------------
__global__ void __launch_bounds__(256) final_kernel(
    const float* __restrict__ Wv2, const float* __restrict__ bv2,
    float* __restrict__ out)
{
    const int warp = threadIdx.x >> 5, lane = threadIdx.x & 31;
    const int n = blockIdx.x * 8 + warp;
    if (n >= NTOT) return;

    float aqv[8];
#pragma unroll
    for (int a = 0; a < 8; a++) aqv[a] = g_aq[n * 8 + a];

    float tot = 0.f;
#pragma unroll
    for (int jj = 0; jj < 2; jj++) {
        int e = jj * 32 + lane;
        float hsum = g_b1[n * 64 + e];
#pragma unroll
        for (int a = 0; a < 8; a++) hsum += aqv[a] * g_w1[(size_t)n * 512 + a * 64 + e];
        float hid = hsum > 0.f ? hsum : expm1f(hsum);
        tot += hid * g_wf[n * 64 + e] + g_v1[n * 64 + e] * Wv2[e];
    }
#pragma unroll
    for (int off = 16; off > 0; off >>= 1) tot += __shfl_xor_sync(0xffffffffu, tot, off);
    if (lane == 0) out[n] = tot + bv2[0];
}

// ---------------- launch ----------------------------------------------------
extern "C" void kernel_launch(void* const* d_in, const int* in_sizes, int n_in,
                              void* d_out, int out_size)
{
    const float* agent_qs = (const float*)d_in[0];
    const float* states   = (const float*)d_in[1];
    const float* obs      = (const float*)d_in[2];
    const int*   actions  = (const int*)d_in[3];
    const float* W_obs = (const float*)d_in[4];  const float* b_obs = (const float*)d_in[5];
    const float* W_act = (const float*)d_in[6];  const float* b_act = (const float*)d_in[7];
    const float* W_q   = (const float*)d_in[8];  const float* b_q   = (const float*)d_in[9];
    const float* Wqkv  = (const float*)d_in[10]; const float* bqkv  = (const float*)d_in[11];
    const float* Wo    = (const float*)d_in[12]; const float* bo    = (const float*)d_in[13];
    const float* Wa2q  = (const float*)d_in[14]; const float* ba2q  = (const float*)d_in[15];
    const float* Wh1a  = (const float*)d_in[16]; const float* bh1a  = (const float*)d_in[17];
    const float* Wh1b  = (const float*)d_in[18]; const float* bh1b  = (const float*)d_in[19];
    const float* Whfa  = (const float*)d_in[20]; const float* bhfa  = (const float*)d_in[21];
    const float* Whfb  = (const float*)d_in[22]; const float* bhfb  = (const float*)d_in[23];
    const float* Wb1   = (const float*)d_in[24]; const float* bb1   = (const float*)d_in[25];
    const float* Wv1   = (const float*)d_in[26]; const float* bv1   = (const float*)d_in[27];
    const float* Wv2   = (const float*)d_in[28]; const float* bv2   = (const float*)d_in[29];
    float* out = (float*)d_out;

    void *p_xh, *p_sth, *p_wh, *p_wtf, *p_h1h, *p_hfh, *p_w1, *p_wf, *p_b1, *p_v1;
    cudaGetSymbolAddress(&p_xh,  g_xh);
    cudaGetSymbolAddress(&p_sth, g_sth);
    cudaGetSymbolAddress(&p_wh,  g_wh);
    cudaGetSymbolAddress(&p_wtf, g_wtf);
    cudaGetSymbolAddress(&p_h1h, g_h1h);
    cudaGetSymbolAddress(&p_hfh, g_hfh);
    cudaGetSymbolAddress(&p_w1,  g_w1);
    cudaGetSymbolAddress(&p_wf,  g_wf);
    cudaGetSymbolAddress(&p_b1,  g_b1);
    cudaGetSymbolAddress(&p_v1,  g_v1);
    __half* wh = (__half*)p_wh;

    cudaFuncSetAttribute(enc_gemm,        cudaFuncAttributeMaxDynamicSharedMemorySize, ENC_SMEM_BYTES);
    cudaFuncSetAttribute(hp_gemm,         cudaFuncAttributeMaxDynamicSharedMemorySize, HP_SMEM_BYTES);
    cudaFuncSetAttribute(qkv_attn_kernel, cudaFuncAttributeMaxDynamicSharedMemorySize, QA_SMEM_BYTES);

    // 0) conversions: states->fp16perm, weights->fp16perm pool, Wobs->tf32
    HSegs segs;
    segs.src[0] = Wqkv; segs.gbase[0] = 0;
    segs.src[1] = Wh1a; segs.gbase[1] = 384;
    segs.src[2] = Whfa; segs.gbase[2] = 4480;
    segs.src[3] = Wh1b; segs.gbase[3] = 8576;
    segs.src[4] = Whfb; segs.gbase[4] = 12672;
    segs.src[5] = Wb1;  segs.gbase[5] = 13184;
    segs.src[6] = Wv1;  segs.gbase[6] = 14208;
    cvt_all_kernel<<<CVT_ST_BLK + CVT_W_BLK + CVT_OBS_BLK, 256>>>(
        states, (__half*)p_sth, segs, wh, W_obs, (float*)p_wtf);

    // 1) encoder (tf32) -> g_xh
    enc_gemm<<<1024, 256, ENC_SMEM_BYTES>>>(
        obs, (float*)p_wtf, b_obs, (__half*)p_xh,
        actions, agent_qs, W_act, W_q, b_act, b_q);

    // 2) hp launch 1: h1a x4, hfa x4 (fp16 perm out), b1, v1 (fp32 out)
    HOps m1 = {};
    for (int i = 0; i < 4; i++)
        m1.v[i]     = { (__half*)p_sth, wh + HOFF_WH1A, bh1a, p_h1h, 512, 256, i * 64, 1, i * 128, 1 };
    for (int i = 0; i < 4; i++)
        m1.v[4 + i] = { (__half*)p_sth, wh + HOFF_WHFA, bhfa, p_hfh, 512, 256, i * 64, 1, 512 + i * 128, 1 };
    m1.v[8] = { (__half*)p_sth, wh + HOFF_WB1, bb1, p_b1, 512, 64, 0, 0, 1024, 0 };
    m1.v[9] = { (__half*)p_sth, wh + HOFF_WV1, bv1, p_v1, 512, 64, 0, 1, 1152, 0 };
    hp_gemm<<<1280, 256, HP_SMEM_BYTES>>>(m1);

    // 3) fused qkv + attention
    qkv_attn_kernel<<<1024, 256, QA_SMEM_BYTES>>>(wh + HOFF_WQKV, bqkv, Wa2q, ba2q, Wo, bo);

    // 4) hp launch 2: w1 x8, wf (fp32 out)
    HOps m2 = {};
    for (int i = 0; i < 8; i++)
        m2.v[i] = { (__half*)p_h1h, wh + HOFF_WH1B, bh1b, p_w1, 256, 512, i * 64, 2, i * 128, 0 };
    m2.v[8] = { (__half*)p_hfh, wh + HOFF_WHFB, bhfb, p_wf, 256, 64, 0, 2, 1024, 0 };
    m2.v[9] = { (__half*)p_hfh, wh + HOFF_WHFB, bhfb, p_wf, 256, 64, 0, 2, 0x7FFFFFFF, 0 };
    hp_gemm<<<1152, 256, HP_SMEM_BYTES>>>(m2);

    // 5) final mix -> y
    final_kernel<<<2048, 256>>>(Wv2, bv2, out);
}

// round 13
// speedup vs baseline: 1.4674x; 1.0623x over previous
#include <cuda_runtime.h>
#include <cuda_fp16.h>
#include <math.h>
#include <cstdint>

#define NTOT 16384

// ---- tf32 (encoder) plane geometry ----
#define AS_F 4608          // 128*36 floats
#define BS_F 2304          // 64*36 floats
#define PL_F (AS_F + BS_F)
#define ROW36 (32 * 36)

// ---- fp16 plane geometry: 16 words (64B) per 32-half row, no padding ----
#define ROWW 16
#define APLH (128 * ROWW)
#define BPLH (64 * ROWW)
#define PLH  (APLH + BPLH)

// ---------------- scratch (device globals) ----------------------------------
__device__ __align__(16) __half g_xh[131072 * 64];   // encoder out, fp16 k-perm
__device__ __align__(16) __half g_sth[NTOT * 512];   // states fp16 k-perm
__device__ __align__(16) __half g_wh[487424];        // fp16 k-perm weights pool
__device__ __align__(16) float  g_wtf[16384];        // Wobs tf32-rounded fp32
__device__ __align__(16) __half g_h1h[NTOT * 256];   // h1 fp16 k-perm
__device__ __align__(16) __half g_hfh[NTOT * 256];   // hf fp16 k-perm
__device__ __align__(16) float g_aq[NTOT * 8];
__device__ __align__(16) float g_w1[NTOT * 512];
__device__ __align__(16) float g_wf[NTOT * 64];
__device__ __align__(16) float g_b1[NTOT * 64];
__device__ __align__(16) float g_v1[NTOT * 64];

// g_wh offsets (halves)
#define HOFF_WQKV 0
#define HOFF_WH1A 12288
#define HOFF_WHFA 143360
#define HOFF_WH1B 274432
#define HOFF_WHFB 405504
#define HOFF_WB1  421888
#define HOFF_WV1  454656

// ---------------- helpers ---------------------------------------------------
__device__ __forceinline__ uint32_t f2tf(float x) {
    uint32_t r;
    asm("cvt.rna.tf32.f32 %0, %1;" : "=r"(r) : "f"(x));
    return r;
}
__device__ __forceinline__ uint32_t smem_u32(const void* p) {
    uint32_t a;
    asm("{ .reg .u64 t; cvta.to.shared.u64 t, %1; cvt.u32.u64 %0, t; }" : "=r"(a) : "l"(p));
    return a;
}
__device__ __forceinline__ void cp16(uint32_t s, const void* g) {
    asm volatile("cp.async.cg.shared.global [%0], [%1], 16;" :: "r"(s), "l"(g));
}
#define CP_COMMIT asm volatile("cp.async.commit_group;" ::: "memory")
#define CP_WAIT(N) asm volatile("cp.async.wait_group %0;" :: "n"(N) : "memory")

__device__ __forceinline__ void mma_tf32(float* c, const uint32_t* a, const uint32_t* b) {
    asm volatile(
        "mma.sync.aligned.m16n8k8.row.col.f32.tf32.tf32.f32 "
        "{%0,%1,%2,%3}, {%4,%5,%6,%7}, {%8,%9}, {%0,%1,%2,%3};\n"
        : "+f"(c[0]), "+f"(c[1]), "+f"(c[2]), "+f"(c[3])
        : "r"(a[0]), "r"(a[1]), "r"(a[2]), "r"(a[3]), "r"(b[0]), "r"(b[1]));
}
__device__ __forceinline__ void mma_f16(float* c, uint32_t a0, uint32_t a1, uint32_t a2,
                                        uint32_t a3, uint32_t b0, uint32_t b1) {
    asm volatile(
        "mma.sync.aligned.m16n8k16.row.col.f32.f16.f16.f32 "
        "{%0,%1,%2,%3}, {%4,%5,%6,%7}, {%8,%9}, {%0,%1,%2,%3};\n"
        : "+f"(c[0]), "+f"(c[1]), "+f"(c[2]), "+f"(c[3])
        : "r"(a0), "r"(a1), "r"(a2), "r"(a3), "r"(b0), "r"(b1));
}

// k-perm within each 32-half group
__device__ __forceinline__ int perm_half_base(int c) {   // c even
    int lg = c & 31;
    int gg = lg >> 4, l16 = lg & 15;
    int hi = (l16 >= 8) ? 1 : 0;
    int tt = (l16 - (hi ? 8 : 0)) >> 1;
    return (c & ~31) + (4 * tt + 2 * gg + hi) * 2;
}

// ---------------- fp16 compute: one 128x64x32 chunk -> 16 mma ---------------
__device__ __forceinline__ void compute_chunk_h(
    const uint32_t* __restrict__ Ab, const uint32_t* __restrict__ Bb,
    float acc[2][4][4], int wm, int wn, int g, int t)
{
    uint4 ar[2][2], br[4];
#pragma unroll
    for (int mi = 0; mi < 2; mi++)
#pragma unroll
        for (int rr = 0; rr < 2; rr++)
            ar[mi][rr] = *(const uint4*)(Ab + (wm * 32 + mi * 16 + rr * 8 + g) * ROWW + t * 4);
#pragma unroll
    for (int ni = 0; ni < 4; ni++)
        br[ni] = *(const uint4*)(Bb + (wn * 32 + ni * 8 + g) * ROWW + t * 4);
#pragma unroll
    for (int mi = 0; mi < 2; mi++)
#pragma unroll
        for (int ni = 0; ni < 4; ni++)
            mma_f16(acc[mi][ni], ar[mi][0].x, ar[mi][1].x, ar[mi][0].y, ar[mi][1].y,
                    br[ni].x, br[ni].y);
#pragma unroll
    for (int mi = 0; mi < 2; mi++)
#pragma unroll
        for (int ni = 0; ni < 4; ni++)
            mma_f16(acc[mi][ni], ar[mi][0].z, ar[mi][1].z, ar[mi][0].w, ar[mi][1].w,
                    br[ni].z, br[ni].w);
}

// ---------------- tf32 compute (encoder only) -------------------------------
__device__ __forceinline__ void compute_chunk_t(
    const float* __restrict__ Ab, const float* __restrict__ Bb,
    float acc[2][4][4], int wm, int wn, int g, int t)
{
#pragma unroll
    for (int h = 0; h < 2; h++) {
        float a4[4][4], b4[4][4];
#pragma unroll
        for (int i = 0; i < 4; i++)
            *(float4*)&a4[i][0] = *(const float4*)(Ab + (wm * 32 + i * 8 + g) * 36 + t * 8 + h * 4);
#pragma unroll
        for (int i = 0; i < 4; i++)
            *(float4*)&b4[i][0] = *(const float4*)(Bb + (wn * 32 + i * 8 + g) * 36 + t * 8 + h * 4);
#pragma unroll
        for (int k2 = 0; k2 < 2; k2++) {
            uint32_t af[2][4], bf[4][2];
#pragma unroll
            for (int mi = 0; mi < 2; mi++) {
                af[mi][0] = f2tf(a4[2 * mi][2 * k2]);
                af[mi][1] = f2tf(a4[2 * mi + 1][2 * k2]);
                af[mi][2] = f2tf(a4[2 * mi][2 * k2 + 1]);
                af[mi][3] = f2tf(a4[2 * mi + 1][2 * k2 + 1]);
            }
#pragma unroll
            for (int ni = 0; ni < 4; ni++) {
                bf[ni][0] = __float_as_uint(b4[ni][2 * k2]);
                bf[ni][1] = __float_as_uint(b4[ni][2 * k2 + 1]);
            }
#pragma unroll
            for (int mi = 0; mi < 2; mi++)
#pragma unroll
                for (int ni = 0; ni < 4; ni++)
                    mma_tf32(acc[mi][ni], af[mi], bf[ni]);
        }
    }
}

// ---------------- conversion kernel (fp16 perm + Wobs tf32) ------------------
__device__ __forceinline__ void cvt_group_h(const float* __restrict__ src, __half* __restrict__ dst)
{
    float v[32];
#pragma unroll
    for (int i = 0; i < 8; i++) *(float4*)&v[i * 4] = *(const float4*)(src + i * 4);
    uint32_t w[16];
#pragma unroll
    for (int W = 0; W < 16; W++) {
        int tt = W >> 2, gg = (W >> 1) & 1, hi = W & 1;
        int l0 = gg * 16 + hi * 8 + tt * 2;
        __half2 h = __floats2half2_rn(v[l0], v[l0 + 1]);
        w[W] = *(uint32_t*)&h;
    }
#pragma unroll
    for (int i = 0; i < 4; i++) ((uint4*)dst)[i] = *(uint4*)&w[i * 4];
}

struct HSegs { const float* src[7]; int gbase[7]; };
#define CVT_ST_BLK 1024
#define CVT_W_GROUPS 15232
#define CVT_W_BLK 60
#define CVT_OBS_BLK 16

__global__ void __launch_bounds__(256) cvt_all_kernel(
    const float* __restrict__ states, __half* __restrict__ sth,
    HSegs segs, __half* __restrict__ wh,
    const float* __restrict__ Wobs, float* __restrict__ wtf)
{
    int b = blockIdx.x, tid = threadIdx.x;
    if (b < CVT_ST_BLK) {
        int gidx = b * 256 + tid;
        cvt_group_h(states + (size_t)gidx * 32, sth + (size_t)gidx * 32);
    } else if (b < CVT_ST_BLK + CVT_W_BLK) {
        int gidx = (b - CVT_ST_BLK) * 256 + tid;
        if (gidx < CVT_W_GROUPS) {
            int k = 0;
#pragma unroll
            for (int kk = 1; kk < 7; kk++) if (gidx >= segs.gbase[kk]) k = kk;
            cvt_group_h(segs.src[k] + (size_t)(gidx - segs.gbase[k]) * 32,
                        wh + (size_t)gidx * 32);
        }
    } else {
        int i4 = ((b - CVT_ST_BLK - CVT_W_BLK) * 256 + tid) * 4;
        float4 v = *(const float4*)(Wobs + i4);
        uint4 u = { f2tf(v.x), f2tf(v.y), f2tf(v.z), f2tf(v.w) };
        *(uint4*)(wtf + i4) = u;
    }
}

// ---------------- encoder GEMM (tf32): obs -> g_xh (fp16 perm) ---------------
#define ENC_SMEM_BYTES ((2 * PL_F + 192) * 4)

__global__ void __launch_bounds__(256, 3) enc_gemm(
    const float* __restrict__ obs, const float* __restrict__ Wobs_tf,
    const float* __restrict__ b_obs, __half* __restrict__ Cx,
    const int* __restrict__ actions, const float* __restrict__ qvals,
    const float* __restrict__ W_act, const float* __restrict__ W_q,
    const float* __restrict__ b_act, const float* __restrict__ b_q)
{
    extern __shared__ float dsm[];
    float* bias_sh = dsm + 2 * PL_F;
    float* cvec_sh = bias_sh + 64;
    float* wq_sh   = cvec_sh + 64;

    const int tid = threadIdx.x;
    const int wid = tid >> 5, lane = tid & 31;
    const int wm = wid >> 1, wn = wid & 1;
    const int g = lane >> 2, t = lane & 3;
    const int row0 = blockIdx.x * 128;
    const int K = 256;

    if (tid < 64) {
        bias_sh[tid] = b_obs[tid];
        cvec_sh[tid] = b_act[tid] + b_q[tid];
        wq_sh[tid] = W_q[tid];
    }

    float acc[2][4][4];
#pragma unroll
    for (int mi = 0; mi < 2; mi++)
#pragma unroll
        for (int ni = 0; ni < 4; ni++)
#pragma unroll
            for (int jj = 0; jj < 4; jj++) acc[mi][ni][jj] = 0.f;

    {   // tf32 pipeline, BK=32, 2-stage
        const uint32_t su = smem_u32(dsm);
        const int ra = tid >> 3, q4 = (tid & 7) * 4;
        const float* Ap = obs + (size_t)(row0 + ra) * K + q4;
        const float* Bp = Wobs_tf + (size_t)ra * K + q4;
        const uint32_t sa = su + (uint32_t)(ra * 36 + q4) * 4;
        const uint32_t sb = sa + (uint32_t)AS_F * 4;
        const int nk = K >> 5;
#pragma unroll
        for (int i = 0; i < 4; i++) cp16(sa + (uint32_t)(i * ROW36) * 4, Ap + (size_t)i * 32 * K);
#pragma unroll
        for (int i = 0; i < 2; i++) cp16(sb + (uint32_t)(i * ROW36) * 4, Bp + (size_t)i * 32 * K);
        CP_COMMIT;
        for (int c = 0; c < nk; c++) {
            CP_WAIT(0);
            __syncthreads();
            if (c + 1 < nk) {
                const uint32_t so = (uint32_t)(((c + 1) & 1) * PL_F) * 4;
#pragma unroll
                for (int i = 0; i < 4; i++)
                    cp16(sa + so + (uint32_t)(i * ROW36) * 4, Ap + (c + 1) * 32 + (size_t)i * 32 * K);
#pragma unroll
                for (int i = 0; i < 2; i++)
                    cp16(sb + so + (uint32_t)(i * ROW36) * 4, Bp + (c + 1) * 32 + (size_t)i * 32 * K);
            }
            CP_COMMIT;
            const float* st = dsm + (c & 1) * PL_F;
            compute_chunk_t(st, st + AS_F, acc, wm, wn, g, t);
        }
    }

#pragma unroll
    for (int mi = 0; mi < 2; mi++)
#pragma unroll
        for (int hh = 0; hh < 2; hh++) {
            const int row = row0 + wm * 32 + mi * 16 + hh * 8 + g;
            const int act = actions[row];
            const float qv = qvals[row];
#pragma unroll
            for (int ni = 0; ni < 4; ni++) {
                const int lc = wn * 32 + ni * 8 + t * 2;
                float v0 = acc[mi][ni][hh * 2 + 0] + bias_sh[lc]
                         + cvec_sh[lc] + __ldg(&W_act[lc * 32 + act]) + qv * wq_sh[lc];
                float v1 = acc[mi][ni][hh * 2 + 1] + bias_sh[lc + 1]
                         + cvec_sh[lc + 1] + __ldg(&W_act[(lc + 1) * 32 + act]) + qv * wq_sh[lc + 1];
                *(__half2*)(Cx + (size_t)row * 64 + perm_half_base(lc)) = __floats2half2_rn(v0, v1);
            }
        }
}

// ---------------- fp16 packed GEMM ------------------------------------------
struct HOp {
    const __half* A; const __half* B; const float* bias; void* C;
    int K; int Nout; int col0; int epi; int tileBase; int flags;
};
struct HOps { HOp v[10]; };
#define HP_SMEM_BYTES ((2 * PLH + 64) * 4)

__global__ void __launch_bounds__(256, 3) hp_gemm(HOps ops)
{
    extern __shared__ uint32_t hsm[];
    float* bias_sh = (float*)(hsm + 2 * PLH);

    const int bid = blockIdx.x;
    int j = 0;
#pragma unroll
    for (int k = 1; k < 10; k++) if (bid >= ops.v[k].tileBase) j = k;
    const HOp op = ops.v[j];

    const int tid = threadIdx.x;
    const int wid = tid >> 5, lane = tid & 31;
    const int wm = wid >> 1, wn = wid & 1;
    const int g = lane >> 2, t = lane & 3;
    const int row0 = (bid - op.tileBase) * 128;
    const int col0 = op.col0;
    const int K = op.K;

    if (tid < 64) bias_sh[tid] = op.bias[col0 + tid];

    float acc[2][4][4];
#pragma unroll
    for (int mi = 0; mi < 2; mi++)
#pragma unroll
        for (int ni = 0; ni < 4; ni++)
#pragma unroll
            for (int jj = 0; jj < 4; jj++) acc[mi][ni][jj] = 0.f;

    {   // fp16 pipeline: BK=32, 2-stage, 3 cp/thread/chunk
        const uint32_t su = smem_u32(hsm);
        const int arow = tid >> 2, awq = tid & 3;
        const __half* Ap  = op.A + (size_t)(row0 + arow) * K + awq * 8;
        const __half* Ap2 = Ap + (size_t)64 * K;
        const __half* Bp  = op.B + (size_t)(col0 + arow) * K + awq * 8;
        const uint32_t sa = su + (uint32_t)(arow * ROWW + awq * 4) * 4;
        const uint32_t sa2 = sa + (uint32_t)(64 * ROWW) * 4;
        const uint32_t sb = su + (uint32_t)(APLH + arow * ROWW + awq * 4) * 4;
        const int nk = K >> 5;
        cp16(sa, Ap); cp16(sa2, Ap2); cp16(sb, Bp);
        CP_COMMIT;
        for (int c = 0; c < nk; c++) {
            CP_WAIT(0);
            __syncthreads();
            if (c + 1 < nk) {
                const uint32_t so = (uint32_t)(((c + 1) & 1) * PLH) * 4;
                cp16(sa + so, Ap + (c + 1) * 32);
                cp16(sa2 + so, Ap2 + (c + 1) * 32);
                cp16(sb + so, Bp + (c + 1) * 32);
            }
            CP_COMMIT;
            const uint32_t* st = hsm + (c & 1) * PLH;
            compute_chunk_h(st, st + APLH, acc, wm, wn, g, t);
        }
    }

    const int Nout = op.Nout, epi = op.epi, hout = op.flags & 1;
#pragma unroll
    for (int mi = 0; mi < 2; mi++)
#pragma unroll
        for (int hh = 0; hh < 2; hh++) {
            const int row = row0 + wm * 32 + mi * 16 + hh * 8 + g;
#pragma unroll
            for (int ni = 0; ni < 4; ni++) {
                const int lc = wn * 32 + ni * 8 + t * 2;
                float v0 = acc[mi][ni][hh * 2 + 0] + bias_sh[lc];
                float v1 = acc[mi][ni][hh * 2 + 1] + bias_sh[lc + 1];
                if (epi == 1) { v0 = fmaxf(v0, 0.f); v1 = fmaxf(v1, 0.f); }
                else if (epi == 2) { v0 = fabsf(v0); v1 = fabsf(v1); }
                if (hout) {
                    const int cgl = col0 + lc;
                    *(__half2*)((__half*)op.C + (size_t)row * Nout + perm_half_base(cgl))
                        = __floats2half2_rn(v0, v1);
                } else {
                    float2 o = { v0, v1 };
                    *(float2*)((float*)op.C + (size_t)row * Nout + col0 + lc) = o;
                }
            }
        }
}

// ---------------- fused qkv (fp16) + attention -------------------------------
// qs intermediate now fp16 ([128][200] halves) -> smem ~91 KB -> 2 CTAs/SM.
#define XPLH (128 * ROWW)
#define WPLH (192 * ROWW)
#define QSTRIDE 200                     // halves per row (196 used, pad 4)
#define QA_QS_W (128 * QSTRIDE / 2)     // uint32 words
#define QA_SMEM_BYTES ((2 * XPLH + 2 * WPLH + QA_QS_W + 192 + 65) * 4)

__global__ void __launch_bounds__(256, 2) qkv_attn_kernel(
    const __half* __restrict__ Wqkv_h, const float* __restrict__ bqkv,
    const float* __restrict__ Wa2q, const float* __restrict__ ba2q,
    const float* __restrict__ Wo, const float* __restrict__ bo)
{
    extern __shared__ uint32_t qsm[];
    uint32_t* xs = qsm;                     // [2][128][ROWW]
    uint32_t* ws = xs + 2 * XPLH;           // [2][192][ROWW]
    __half* qs = (__half*)(ws + 2 * WPLH);  // [128][QSTRIDE] fp16
    float* bq = (float*)(qs + 128 * QSTRIDE);
    float* wc = bq + 192;

    const int tid = threadIdx.x;
    const int wid = tid >> 5, lane = tid & 31;
    const int wm = wid >> 1, wn = wid & 1;
    const int g = lane >> 2, t = lane & 3;
    const int row0 = blockIdx.x * 128;

    const uint32_t xs_u = smem_u32(xs);
    const uint32_t ws_u = smem_u32(ws);
#pragma unroll
    for (int i = 0; i < 4; i++) {           // x: 1024 16B units
        int u = tid + i * 256;
        int c = u >> 9, r = (u >> 2) & 127, wq = u & 3;
        cp16(xs_u + (uint32_t)(c * XPLH + r * ROWW + wq * 4) * 4,
             g_xh + (size_t)(row0 + r) * 64 + c * 32 + wq * 8);
    }
#pragma unroll
    for (int i = 0; i < 6; i++) {           // Wqkv: 1536 16B units
        int u = tid + i * 256;
        int c = (u >= 768) ? 1 : 0;
        int rem = u - c * 768;
        int r = rem >> 2, wq = rem & 3;
        cp16(ws_u + (uint32_t)(c * WPLH + r * ROWW + wq * 4) * 4,
             Wqkv_h + (size_t)r * 64 + c * 32 + wq * 8);
    }
    if (tid < 192) bq[tid] = bqkv[tid];
    if (tid < 64) {
        float s = 0.f;
#pragma unroll 8
        for (int c = 0; c < 64; c++) s += Wa2q[c] * Wo[c * 64 + tid];
        wc[tid] = s;
    }
    if (wid == 6) {
        float v = Wa2q[lane] * bo[lane] + Wa2q[lane + 32] * bo[lane + 32];
#pragma unroll
        for (int off = 16; off > 0; off >>= 1) v += __shfl_xor_sync(0xffffffffu, v, off);
        if (lane == 0) wc[64] = v + ba2q[0];
    }
    CP_COMMIT; CP_WAIT(0);
    __syncthreads();

    // ---- phase B: qkv = x @ Wqkv^T (fp16, 3 col blocks) -> qs (fp16) ----
#pragma unroll 1
    for (int cb = 0; cb < 3; cb++) {
        float acc[2][4][4];
#pragma unroll
        for (int mi = 0; mi < 2; mi++)
#pragma unroll
            for (int ni = 0; ni < 4; ni++)
#pragma unroll
                for (int jj = 0; jj < 4; jj++) acc[mi][ni][jj] = 0.f;

#pragma unroll
        for (int c = 0; c < 2; c++)
            compute_chunk_h(xs + c * XPLH, ws + c * WPLH + (cb * 64) * ROWW,
                            acc, wm, wn, g, t);

#pragma unroll
        for (int mi = 0; mi < 2; mi++)
#pragma unroll
            for (int hh = 0; hh < 2; hh++) {
                const int row = wm * 32 + mi * 16 + hh * 8 + g;
#pragma unroll
                for (int ni = 0; ni < 4; ni++) {
                    const int lc = wn * 32 + ni * 8 + t * 2;
                    float v0 = acc[mi][ni][hh * 2 + 0] + bq[cb * 64 + lc];
                    float v1 = acc[mi][ni][hh * 2 + 1] + bq[cb * 64 + lc + 1];
                    *(__half2*)(qs + row * QSTRIDE + cb * 64 + lc) = __floats2half2_rn(v0, v1);
                }
            }
    }
    __syncthreads();

    // ---- phase C: attention per sample (2 samples per warp), fp16 qs ----
    const int h = lane >> 3, a = lane & 7;
#pragma unroll
    for (int s2 = 0; s2 < 2; s2++) {
        const int s = wid * 2 + s2;
        const __half* base = qs + s * 8 * QSTRIDE;

        float2 q2[8];
        {
            const __half2* qp = (const __half2*)(base + a * QSTRIDE + h * 16);
#pragma unroll
            for (int d2 = 0; d2 < 8; d2++) q2[d2] = __half22float2(qp[d2]);
        }
        float sc[8], m = -1e30f;
#pragma unroll
        for (int b = 0; b < 8; b++) {
            const __half2* kp = (const __half2*)(base + b * QSTRIDE + 64 + h * 16);
            float acc = 0.f;
#pragma unroll
            for (int d2 = 0; d2 < 8; d2++) {
                float2 kk = __half22float2(kp[d2]);
                acc += q2[d2].x * kk.x + q2[d2].y * kk.y;
            }
            sc[b] = acc * 0.25f;          // 1/sqrt(16)
            m = fmaxf(m, sc[b]);
        }
        float sum = 0.f;
#pragma unroll
        for (int b = 0; b < 8; b++) { sc[b] = __expf(sc[b] - m); sum += sc[b]; }
        float inv = 1.f / sum;
        float2 o2[8];
#pragma unroll
        for (int d2 = 0; d2 < 8; d2++) { o2[d2].x = 0.f; o2[d2].y = 0.f; }
#pragma unroll
        for (int b = 0; b < 8; b++) {
            float p = sc[b] * inv;
            const __half2* vp = (const __half2*)(base + b * QSTRIDE + 128 + h * 16);
#pragma unroll
            for (int d2 = 0; d2 < 8; d2++) {
                float2 vv = __half22float2(vp[d2]);
                o2[d2].x += p * vv.x;
                o2[d2].y += p * vv.y;
            }
        }
        float part = 0.f;
#pragma unroll
        for (int d2 = 0; d2 < 8; d2++)
            part += o2[d2].x * wc[h * 16 + d2 * 2] + o2[d2].y * wc[h * 16 + d2 * 2 + 1];
        part += __shfl_xor_sync(0xffffffffu, part, 8);
        part += __shfl_xor_sync(0xffffffffu, part, 16);
        if (h == 0) {
            const int n = blockIdx.x * 16 + s;
            g_aq[n * 8 + a] = part + wc[64];
        }
    }
}

// ---------------- final mixing ----------------------------------------------
__global__ void __launch_bounds__(256) final_kernel(
    const float* __restrict__ Wv2, const float* __restrict__ bv2,
    float* __restrict__ out)
{
    const int warp = threadIdx.x >> 5, lane = threadIdx.x & 31;
    const int n = blockIdx.x * 8 + warp;
    if (n >= NTOT) return;

    float aqv[8];
#pragma unroll
    for (int a = 0; a < 8; a++) aqv[a] = g_aq[n * 8 + a];

    float tot = 0.f;
#pragma unroll
    for (int jj = 0; jj < 2; jj++) {
        int e = jj * 32 + lane;
        float hsum = g_b1[n * 64 + e];
#pragma unroll
        for (int a = 0; a < 8; a++) hsum += aqv[a] * g_w1[(size_t)n * 512 + a * 64 + e];
        float hid = hsum > 0.f ? hsum : expm1f(hsum);
        tot += hid * g_wf[n * 64 + e] + g_v1[n * 64 + e] * Wv2[e];
    }
#pragma unroll
    for (int off = 16; off > 0; off >>= 1) tot += __shfl_xor_sync(0xffffffffu, tot, off);
    if (lane == 0) out[n] = tot + bv2[0];
}

// ---------------- launch ----------------------------------------------------
extern "C" void kernel_launch(void* const* d_in, const int* in_sizes, int n_in,
                              void* d_out, int out_size)
{
    const float* agent_qs = (const float*)d_in[0];
    const float* states   = (const float*)d_in[1];
    const float* obs      = (const float*)d_in[2];
    const int*   actions  = (const int*)d_in[3];
    const float* W_obs = (const float*)d_in[4];  const float* b_obs = (const float*)d_in[5];
    const float* W_act = (const float*)d_in[6];  const float* b_act = (const float*)d_in[7];
    const float* W_q   = (const float*)d_in[8];  const float* b_q   = (const float*)d_in[9];
    const float* Wqkv  = (const float*)d_in[10]; const float* bqkv  = (const float*)d_in[11];
    const float* Wo    = (const float*)d_in[12]; const float* bo    = (const float*)d_in[13];
    const float* Wa2q  = (const float*)d_in[14]; const float* ba2q  = (const float*)d_in[15];
    const float* Wh1a  = (const float*)d_in[16]; const float* bh1a  = (const float*)d_in[17];
    const float* Wh1b  = (const float*)d_in[18]; const float* bh1b  = (const float*)d_in[19];
    const float* Whfa  = (const float*)d_in[20]; const float* bhfa  = (const float*)d_in[21];
    const float* Whfb  = (const float*)d_in[22]; const float* bhfb  = (const float*)d_in[23];
    const float* Wb1   = (const float*)d_in[24]; const float* bb1   = (const float*)d_in[25];
    const float* Wv1   = (const float*)d_in[26]; const float* bv1   = (const float*)d_in[27];
    const float* Wv2   = (const float*)d_in[28]; const float* bv2   = (const float*)d_in[29];
    float* out = (float*)d_out;

    void *p_xh, *p_sth, *p_wh, *p_wtf, *p_h1h, *p_hfh, *p_w1, *p_wf, *p_b1, *p_v1;
    cudaGetSymbolAddress(&p_xh,  g_xh);
    cudaGetSymbolAddress(&p_sth, g_sth);
    cudaGetSymbolAddress(&p_wh,  g_wh);
    cudaGetSymbolAddress(&p_wtf, g_wtf);
    cudaGetSymbolAddress(&p_h1h, g_h1h);
    cudaGetSymbolAddress(&p_hfh, g_hfh);
    cudaGetSymbolAddress(&p_w1,  g_w1);
    cudaGetSymbolAddress(&p_wf,  g_wf);
    cudaGetSymbolAddress(&p_b1,  g_b1);
    cudaGetSymbolAddress(&p_v1,  g_v1);
    __half* wh = (__half*)p_wh;

    cudaFuncSetAttribute(enc_gemm,        cudaFuncAttributeMaxDynamicSharedMemorySize, ENC_SMEM_BYTES);
    cudaFuncSetAttribute(hp_gemm,         cudaFuncAttributeMaxDynamicSharedMemorySize, HP_SMEM_BYTES);
    cudaFuncSetAttribute(qkv_attn_kernel, cudaFuncAttributeMaxDynamicSharedMemorySize, QA_SMEM_BYTES);

    // 0) conversions
    HSegs segs;
    segs.src[0] = Wqkv; segs.gbase[0] = 0;
    segs.src[1] = Wh1a; segs.gbase[1] = 384;
    segs.src[2] = Whfa; segs.gbase[2] = 4480;
    segs.src[3] = Wh1b; segs.gbase[3] = 8576;
    segs.src[4] = Whfb; segs.gbase[4] = 12672;
    segs.src[5] = Wb1;  segs.gbase[5] = 13184;
    segs.src[6] = Wv1;  segs.gbase[6] = 14208;
    cvt_all_kernel<<<CVT_ST_BLK + CVT_W_BLK + CVT_OBS_BLK, 256>>>(
        states, (__half*)p_sth, segs, wh, W_obs, (float*)p_wtf);

    // 1) encoder (tf32) -> g_xh
    enc_gemm<<<1024, 256, ENC_SMEM_BYTES>>>(
        obs, (float*)p_wtf, b_obs, (__half*)p_xh,
        actions, agent_qs, W_act, W_q, b_act, b_q);

    // 2) hp launch 1: h1a x4, hfa x4 (fp16 perm out), b1, v1 (fp32 out)
    HOps m1 = {};
    for (int i = 0; i < 4; i++)
        m1.v[i]     = { (__half*)p_sth, wh + HOFF_WH1A, bh1a, p_h1h, 512, 256, i * 64, 1, i * 128, 1 };
    for (int i = 0; i < 4; i++)
        m1.v[4 + i] = { (__half*)p_sth, wh + HOFF_WHFA, bhfa, p_hfh, 512, 256, i * 64, 1, 512 + i * 128, 1 };
    m1.v[8] = { (__half*)p_sth, wh + HOFF_WB1, bb1, p_b1, 512, 64, 0, 0, 1024, 0 };
    m1.v[9] = { (__half*)p_sth, wh + HOFF_WV1, bv1, p_v1, 512, 64, 0, 1, 1152, 0 };
    hp_gemm<<<1280, 256, HP_SMEM_BYTES>>>(m1);

    // 3) fused qkv + attention (fp16 qs, 2 CTAs/SM)
    qkv_attn_kernel<<<1024, 256, QA_SMEM_BYTES>>>(wh + HOFF_WQKV, bqkv, Wa2q, ba2q, Wo, bo);

    // 4) hp launch 2: w1 x8, wf (fp32 out)
    HOps m2 = {};
    for (int i = 0; i < 8; i++)
        m2.v[i] = { (__half*)p_h1h, wh + HOFF_WH1B, bh1b, p_w1, 256, 512, i * 64, 2, i * 128, 0 };
    m2.v[8] = { (__half*)p_hfh, wh + HOFF_WHFB, bhfb, p_wf, 256, 64, 0, 2, 1024, 0 };
    m2.v[9] = { (__half*)p_hfh, wh + HOFF_WHFB, bhfb, p_wf, 256, 64, 0, 2, 0x7FFFFFFF, 0 };
    hp_gemm<<<1152, 256, HP_SMEM_BYTES>>>(m2);

    // 5) final mix -> y
    final_kernel<<<2048, 256>>>(Wv2, bv2, out);
}

// round 14
// speedup vs baseline: 1.5883x; 1.0824x over previous
#include <cuda_runtime.h>
#include <cuda_fp16.h>
#include <math.h>
#include <cstdint>

#define NTOT 16384

// ---- fp32 A-stage geometry (encoder): 36-float padded rows ----
#define AS_F 4608          // 128*36 floats per stage
#define ROW36 (32 * 36)
#define EB_W (64 * 16)     // encoder B (fp16) words per stage

// ---- fp16 plane geometry: 16 words (64B) per 32-half row ----
#define ROWW 16
#define APLH (128 * ROWW)
#define BPLH (64 * ROWW)
#define PLH  (APLH + BPLH)

// ---------------- scratch (device globals) ----------------------------------
__device__ __align__(16) __half g_xh[131072 * 64];   // encoder out, fp16 k-perm
__device__ __align__(16) __half g_sth[NTOT * 512];   // states fp16 k-perm
__device__ __align__(16) __half g_wh[503808];        // fp16 k-perm weights pool
__device__ __align__(16) __half g_h1h[NTOT * 256];
__device__ __align__(16) __half g_hfh[NTOT * 256];
__device__ __align__(16) float g_aq[NTOT * 8];
__device__ __align__(16) float g_w1[NTOT * 512];
__device__ __align__(16) float g_wf[NTOT * 64];
__device__ __align__(16) float g_b1[NTOT * 64];
__device__ __align__(16) float g_v1[NTOT * 64];

// g_wh offsets (halves)
#define HOFF_WQKV 0        // 12288
#define HOFF_WOBS 12288    // 16384
#define HOFF_WH1A 28672    // 131072
#define HOFF_WHFA 159744   // 131072
#define HOFF_WH1B 290816   // 131072
#define HOFF_WHFB 421888   // 16384
#define HOFF_WB1  438272   // 32768
#define HOFF_WV1  471040   // 32768

// ---------------- helpers ---------------------------------------------------
__device__ __forceinline__ uint32_t smem_u32(const void* p) {
    uint32_t a;
    asm("{ .reg .u64 t; cvta.to.shared.u64 t, %1; cvt.u32.u64 %0, t; }" : "=r"(a) : "l"(p));
    return a;
}
__device__ __forceinline__ void cp16(uint32_t s, const void* g) {
    asm volatile("cp.async.cg.shared.global [%0], [%1], 16;" :: "r"(s), "l"(g));
}
#define CP_COMMIT asm volatile("cp.async.commit_group;" ::: "memory")
#define CP_WAIT(N) asm volatile("cp.async.wait_group %0;" :: "n"(N) : "memory")

__device__ __forceinline__ void mma_f16(float* c, uint32_t a0, uint32_t a1, uint32_t a2,
                                        uint32_t a3, uint32_t b0, uint32_t b1) {
    asm volatile(
        "mma.sync.aligned.m16n8k16.row.col.f32.f16.f16.f32 "
        "{%0,%1,%2,%3}, {%4,%5,%6,%7}, {%8,%9}, {%0,%1,%2,%3};\n"
        : "+f"(c[0]), "+f"(c[1]), "+f"(c[2]), "+f"(c[3])
        : "r"(a0), "r"(a1), "r"(a2), "r"(a3), "r"(b0), "r"(b1));
}
__device__ __forceinline__ uint32_t packh2(float lo, float hi) {
    __half2 h = __floats2half2_rn(lo, hi);
    return *(uint32_t*)&h;
}

// k-perm within each 32-half group
__device__ __forceinline__ int perm_half_base(int c) {   // c even
    int lg = c & 31;
    int gg = lg >> 4, l16 = lg & 15;
    int hi = (l16 >= 8) ? 1 : 0;
    int tt = (l16 - (hi ? 8 : 0)) >> 1;
    return (c & ~31) + (4 * tt + 2 * gg + hi) * 2;
}

// ---------------- fp16 compute: one 128x64x32 chunk -> 16 mma ---------------
__device__ __forceinline__ void compute_chunk_h(
    const uint32_t* __restrict__ Ab, const uint32_t* __restrict__ Bb,
    float acc[2][4][4], int wm, int wn, int g, int t)
{
    uint4 ar[2][2], br[4];
#pragma unroll
    for (int mi = 0; mi < 2; mi++)
#pragma unroll
        for (int rr = 0; rr < 2; rr++)
            ar[mi][rr] = *(const uint4*)(Ab + (wm * 32 + mi * 16 + rr * 8 + g) * ROWW + t * 4);
#pragma unroll
    for (int ni = 0; ni < 4; ni++)
        br[ni] = *(const uint4*)(Bb + (wn * 32 + ni * 8 + g) * ROWW + t * 4);
#pragma unroll
    for (int mi = 0; mi < 2; mi++)
#pragma unroll
        for (int ni = 0; ni < 4; ni++)
            mma_f16(acc[mi][ni], ar[mi][0].x, ar[mi][1].x, ar[mi][0].y, ar[mi][1].y,
                    br[ni].x, br[ni].y);
#pragma unroll
    for (int mi = 0; mi < 2; mi++)
#pragma unroll
        for (int ni = 0; ni < 4; ni++)
            mma_f16(acc[mi][ni], ar[mi][0].z, ar[mi][1].z, ar[mi][0].w, ar[mi][1].w,
                    br[ni].z, br[ni].w);
}

// ---- encoder chunk: A fp32 in smem (36-stride rows), converted on the fly --
__device__ __forceinline__ void compute_chunk_enc(
    const float* __restrict__ Ab, const uint32_t* __restrict__ Bb,
    float acc[2][4][4], int wm, int wn, int g, int t)
{
    uint4 ar[2][2], br[4];
#pragma unroll
    for (int mi = 0; mi < 2; mi++)
#pragma unroll
        for (int rr = 0; rr < 2; rr++) {
            const float* pr = Ab + (wm * 32 + mi * 16 + rr * 8 + g) * 36;
            float2 f0 = *(const float2*)(pr + 2 * t);
            float2 f1 = *(const float2*)(pr + 2 * t + 8);
            float2 f2 = *(const float2*)(pr + 16 + 2 * t);
            float2 f3 = *(const float2*)(pr + 24 + 2 * t);
            ar[mi][rr].x = packh2(f0.x, f0.y);
            ar[mi][rr].y = packh2(f1.x, f1.y);
            ar[mi][rr].z = packh2(f2.x, f2.y);
            ar[mi][rr].w = packh2(f3.x, f3.y);
        }
#pragma unroll
    for (int ni = 0; ni < 4; ni++)
        br[ni] = *(const uint4*)(Bb + (wn * 32 + ni * 8 + g) * ROWW + t * 4);
#pragma unroll
    for (int mi = 0; mi < 2; mi++)
#pragma unroll
        for (int ni = 0; ni < 4; ni++)
            mma_f16(acc[mi][ni], ar[mi][0].x, ar[mi][1].x, ar[mi][0].y, ar[mi][1].y,
                    br[ni].x, br[ni].y);
#pragma unroll
    for (int mi = 0; mi < 2; mi++)
#pragma unroll
        for (int ni = 0; ni < 4; ni++)
            mma_f16(acc[mi][ni], ar[mi][0].z, ar[mi][1].z, ar[mi][0].w, ar[mi][1].w,
                    br[ni].z, br[ni].w);
}

// ---------------- conversion kernel (all weights+states -> fp16 perm) -------
__device__ __forceinline__ void cvt_group_h(const float* __restrict__ src, __half* __restrict__ dst)
{
    float v[32];
#pragma unroll
    for (int i = 0; i < 8; i++) *(float4*)&v[i * 4] = *(const float4*)(src + i * 4);
    uint32_t w[16];
#pragma unroll
    for (int W = 0; W < 16; W++) {
        int tt = W >> 2, gg = (W >> 1) & 1, hi = W & 1;
        int l0 = gg * 16 + hi * 8 + tt * 2;
        w[W] = packh2(v[l0], v[l0 + 1]);
    }
#pragma unroll
    for (int i = 0; i < 4; i++) ((uint4*)dst)[i] = *(uint4*)&w[i * 4];
}

struct HSegs { const float* src[8]; int gbase[8]; };
#define CVT_ST_BLK 1024
#define CVT_W_GROUPS 15744
#define CVT_W_BLK 62

__global__ void __launch_bounds__(256) cvt_all_kernel(
    const float* __restrict__ states, __half* __restrict__ sth,
    HSegs segs, __half* __restrict__ wh)
{
    int b = blockIdx.x, tid = threadIdx.x;
    if (b < CVT_ST_BLK) {
        int gidx = b * 256 + tid;
        cvt_group_h(states + (size_t)gidx * 32, sth + (size_t)gidx * 32);
    } else {
        int gidx = (b - CVT_ST_BLK) * 256 + tid;
        if (gidx < CVT_W_GROUPS) {
            int k = 0;
#pragma unroll
            for (int kk = 1; kk < 8; kk++) if (gidx >= segs.gbase[kk]) k = kk;
            cvt_group_h(segs.src[k] + (size_t)(gidx - segs.gbase[k]) * 32,
                        wh + (size_t)gidx * 32);
        }
    }
}

// ---------------- encoder GEMM (fp16 mma, A cvt on the fly) ------------------
#define ENC_SMEM_BYTES ((2 * AS_F + 192) * 4 + (2 * EB_W) * 4)

__global__ void __launch_bounds__(256, 3) enc_gemm(
    const float* __restrict__ obs, const __half* __restrict__ Wobs_h,
    const float* __restrict__ b_obs, __half* __restrict__ Cx,
    const int* __restrict__ actions, const float* __restrict__ qvals,
    const float* __restrict__ W_act, const float* __restrict__ W_q,
    const float* __restrict__ b_act, const float* __restrict__ b_q)
{
    extern __shared__ float dsm[];
    uint32_t* Bh = (uint32_t*)(dsm + 2 * AS_F);      // 2 stages x EB_W words
    float* bias_sh = (float*)(Bh + 2 * EB_W);
    float* cvec_sh = bias_sh + 64;
    float* wq_sh   = cvec_sh + 64;

    const int tid = threadIdx.x;
    const int wid = tid >> 5, lane = tid & 31;
    const int wm = wid >> 1, wn = wid & 1;
    const int g = lane >> 2, t = lane & 3;
    const int row0 = blockIdx.x * 128;
    const int K = 256;

    if (tid < 64) {
        bias_sh[tid] = b_obs[tid];
        cvec_sh[tid] = b_act[tid] + b_q[tid];
        wq_sh[tid] = W_q[tid];
    }

    float acc[2][4][4];
#pragma unroll
    for (int mi = 0; mi < 2; mi++)
#pragma unroll
        for (int ni = 0; ni < 4; ni++)
#pragma unroll
            for (int jj = 0; jj < 4; jj++) acc[mi][ni][jj] = 0.f;

    {
        const uint32_t sua = smem_u32(dsm);
        const uint32_t sub = smem_u32(Bh);
        const int ra = tid >> 3, q4 = (tid & 7) * 4;     // A: 4 cps/thread
        const float* Ap = obs + (size_t)(row0 + ra) * K + q4;
        const uint32_t sa = sua + (uint32_t)(ra * 36 + q4) * 4;
        const int rb = tid >> 2, wq = tid & 3;           // B: 1 cp/thread
        const __half* Bp = Wobs_h + (size_t)rb * K + wq * 8;
        const uint32_t sb = sub + (uint32_t)(rb * ROWW + wq * 4) * 4;
        const int nk = K >> 5;

        // issue chunk 0
#pragma unroll
        for (int i = 0; i < 4; i++) cp16(sa + (uint32_t)(i * ROW36) * 4, Ap + (size_t)i * 32 * K);
        cp16(sb, Bp);
        CP_COMMIT;
        for (int c = 0; c < nk; c++) {
            CP_WAIT(0);
            __syncthreads();
            if (c + 1 < nk) {
                const uint32_t soa = (uint32_t)(((c + 1) & 1) * AS_F) * 4;
                const uint32_t sob = (uint32_t)(((c + 1) & 1) * EB_W) * 4;
#pragma unroll
                for (int i = 0; i < 4; i++)
                    cp16(sa + soa + (uint32_t)(i * ROW36) * 4, Ap + (c + 1) * 32 + (size_t)i * 32 * K);
                cp16(sb + sob, Bp + (c + 1) * 32);
            }
            CP_COMMIT;
            compute_chunk_enc(dsm + (c & 1) * AS_F, Bh + (c & 1) * EB_W, acc, wm, wn, g, t);
        }
    }

#pragma unroll
    for (int mi = 0; mi < 2; mi++)
#pragma unroll
        for (int hh = 0; hh < 2; hh++) {
            const int row = row0 + wm * 32 + mi * 16 + hh * 8 + g;
            const int act = actions[row];
            const float qv = qvals[row];
#pragma unroll
            for (int ni = 0; ni < 4; ni++) {
                const int lc = wn * 32 + ni * 8 + t * 2;
                float v0 = acc[mi][ni][hh * 2 + 0] + bias_sh[lc]
                         + cvec_sh[lc] + __ldg(&W_act[lc * 32 + act]) + qv * wq_sh[lc];
                float v1 = acc[mi][ni][hh * 2 + 1] + bias_sh[lc + 1]
                         + cvec_sh[lc + 1] + __ldg(&W_act[(lc + 1) * 32 + act]) + qv * wq_sh[lc + 1];
                *(__half2*)(Cx + (size_t)row * 64 + perm_half_base(lc)) = __floats2half2_rn(v0, v1);
            }
        }
}

// ---------------- fp16 packed GEMM, BK=64 (one barrier per 64-k) -------------
struct HOp {
    const __half* A; const __half* B; const float* bias; void* C;
    int K; int Nout; int col0; int epi; int tileBase; int flags;
};
struct HOps { HOp v[10]; };
#define HP_SMEM_BYTES ((4 * PLH + 64) * 4)

__global__ void __launch_bounds__(256, 3) hp_gemm(HOps ops)
{
    extern __shared__ uint32_t hsm[];
    float* bias_sh = (float*)(hsm + 4 * PLH);

    const int bid = blockIdx.x;
    int j = 0;
#pragma unroll
    for (int k = 1; k < 10; k++) if (bid >= ops.v[k].tileBase) j = k;
    const HOp op = ops.v[j];

    const int tid = threadIdx.x;
    const int wid = tid >> 5, lane = tid & 31;
    const int wm = wid >> 1, wn = wid & 1;
    const int g = lane >> 2, t = lane & 3;
    const int row0 = (bid - op.tileBase) * 128;
    const int col0 = op.col0;
    const int K = op.K;

    if (tid < 64) bias_sh[tid] = op.bias[col0 + tid];

    float acc[2][4][4];
#pragma unroll
    for (int mi = 0; mi < 2; mi++)
#pragma unroll
        for (int ni = 0; ni < 4; ni++)
#pragma unroll
            for (int jj = 0; jj < 4; jj++) acc[mi][ni][jj] = 0.f;

    {   // 2-stage BK=64 pipeline; safety: in-loop issue targets stage (c+1)&1,
        // last read at compute(c-1), ordered by this iteration's barrier.
        const uint32_t su = smem_u32(hsm);
        const int arow = tid >> 2, awq = tid & 3;
        const __half* Ap  = op.A + (size_t)(row0 + arow) * K + awq * 8;
        const __half* Ap2 = Ap + (size_t)64 * K;
        const __half* Bp  = op.B + (size_t)(col0 + arow) * K + awq * 8;
        const uint32_t sa = su + (uint32_t)(arow * ROWW + awq * 4) * 4;
        const uint32_t sa2 = sa + (uint32_t)(64 * ROWW) * 4;
        const uint32_t sb = su + (uint32_t)(APLH + arow * ROWW + awq * 4) * 4;
        const int nk = K >> 6;

#pragma unroll
        for (int p = 0; p < 2; p++) {
            const uint32_t po = (uint32_t)(p * PLH) * 4;
            cp16(sa + po, Ap + p * 32); cp16(sa2 + po, Ap2 + p * 32); cp16(sb + po, Bp + p * 32);
        }
        CP_COMMIT;
        for (int c = 0; c < nk; c++) {
            CP_WAIT(0);
            __syncthreads();
            if (c + 1 < nk) {
                const uint32_t so = (uint32_t)(((c + 1) & 1) * 2 * PLH) * 4;
                const int off = (c + 1) * 64;
#pragma unroll
                for (int p = 0; p < 2; p++) {
                    const uint32_t po = so + (uint32_t)(p * PLH) * 4;
                    cp16(sa + po, Ap + off + p * 32);
                    cp16(sa2 + po, Ap2 + off + p * 32);
                    cp16(sb + po, Bp + off + p * 32);
                }
            }
            CP_COMMIT;
            const uint32_t* st = hsm + (c & 1) * 2 * PLH;
            compute_chunk_h(st, st + APLH, acc, wm, wn, g, t);
            compute_chunk_h(st + PLH, st + PLH + APLH, acc, wm, wn, g, t);
        }
    }

    const int Nout = op.Nout, epi = op.epi, hout = op.flags & 1;
#pragma unroll
    for (int mi = 0; mi < 2; mi++)
#pragma unroll
        for (int hh = 0; hh < 2; hh++) {
            const int row = row0 + wm * 32 + mi * 16 + hh * 8 + g;
#pragma unroll
            for (int ni = 0; ni < 4; ni++) {
                const int lc = wn * 32 + ni * 8 + t * 2;
                float v0 = acc[mi][ni][hh * 2 + 0] + bias_sh[lc];
                float v1 = acc[mi][ni][hh * 2 + 1] + bias_sh[lc + 1];
                if (epi == 1) { v0 = fmaxf(v0, 0.f); v1 = fmaxf(v1, 0.f); }
                else if (epi == 2) { v0 = fabsf(v0); v1 = fabsf(v1); }
                if (hout) {
                    const int cgl = col0 + lc;
                    *(__half2*)((__half*)op.C + (size_t)row * Nout + perm_half_base(cgl))
                        = __floats2half2_rn(v0, v1);
                } else {
                    float2 o = { v0, v1 };
                    *(float2*)((float*)op.C + (size_t)row * Nout + col0 + lc) = o;
                }
            }
        }
}

// ---------------- fused qkv (fp16) + attention (half2 phase C) ---------------
#define XPLH (128 * ROWW)
#define WPLH (192 * ROWW)
#define QSTRIDE 200
#define QA_QS_W (128 * QSTRIDE / 2)
#define QA_SMEM_BYTES ((2 * XPLH + 2 * WPLH + QA_QS_W + 192 + 65) * 4)

__global__ void __launch_bounds__(256, 2) qkv_attn_kernel(
    const __half* __restrict__ Wqkv_h, const float* __restrict__ bqkv,
    const float* __restrict__ Wa2q, const float* __restrict__ ba2q,
    const float* __restrict__ Wo, const float* __restrict__ bo)
{
    extern __shared__ uint32_t qsm[];
    uint32_t* xs = qsm;
    uint32_t* ws = xs + 2 * XPLH;
    __half* qs = (__half*)(ws + 2 * WPLH);
    float* bq = (float*)(qs + 128 * QSTRIDE);
    float* wc = bq + 192;

    const int tid = threadIdx.x;
    const int wid = tid >> 5, lane = tid & 31;
    const int wm = wid >> 1, wn = wid & 1;
    const int g = lane >> 2, t = lane & 3;
    const int row0 = blockIdx.x * 128;

    const uint32_t xs_u = smem_u32(xs);
    const uint32_t ws_u = smem_u32(ws);
#pragma unroll
    for (int i = 0; i < 4; i++) {
        int u = tid + i * 256;
        int c = u >> 9, r = (u >> 2) & 127, wq = u & 3;
        cp16(xs_u + (uint32_t)(c * XPLH + r * ROWW + wq * 4) * 4,
             g_xh + (size_t)(row0 + r) * 64 + c * 32 + wq * 8);
    }
#pragma unroll
    for (int i = 0; i < 6; i++) {
        int u = tid + i * 256;
        int c = (u >= 768) ? 1 : 0;
        int rem = u - c * 768;
        int r = rem >> 2, wq = rem & 3;
        cp16(ws_u + (uint32_t)(c * WPLH + r * ROWW + wq * 4) * 4,
             Wqkv_h + (size_t)r * 64 + c * 32 + wq * 8);
    }
    if (tid < 192) bq[tid] = bqkv[tid];
    if (tid < 64) {
        float s = 0.f;
#pragma unroll 8
        for (int c = 0; c < 64; c++) s += Wa2q[c] * Wo[c * 64 + tid];
        wc[tid] = s;
    }
    if (wid == 6) {
        float v = Wa2q[lane] * bo[lane] + Wa2q[lane + 32] * bo[lane + 32];
#pragma unroll
        for (int off = 16; off > 0; off >>= 1) v += __shfl_xor_sync(0xffffffffu, v, off);
        if (lane == 0) wc[64] = v + ba2q[0];
    }
    CP_COMMIT; CP_WAIT(0);
    __syncthreads();

    // ---- phase B: qkv = x @ Wqkv^T (fp16) -> qs (fp16) ----
#pragma unroll 1
    for (int cb = 0; cb < 3; cb++) {
        float acc[2][4][4];
#pragma unroll
        for (int mi = 0; mi < 2; mi++)
#pragma unroll
            for (int ni = 0; ni < 4; ni++)
#pragma unroll
                for (int jj = 0; jj < 4; jj++) acc[mi][ni][jj] = 0.f;

#pragma unroll
        for (int c = 0; c < 2; c++)
            compute_chunk_h(xs + c * XPLH, ws + c * WPLH + (cb * 64) * ROWW,
                            acc, wm, wn, g, t);

#pragma unroll
        for (int mi = 0; mi < 2; mi++)
#pragma unroll
            for (int hh = 0; hh < 2; hh++) {
                const int row = wm * 32 + mi * 16 + hh * 8 + g;
#pragma unroll
                for (int ni = 0; ni < 4; ni++) {
                    const int lc = wn * 32 + ni * 8 + t * 2;
                    float v0 = acc[mi][ni][hh * 2 + 0] + bq[cb * 64 + lc];
                    float v1 = acc[mi][ni][hh * 2 + 1] + bq[cb * 64 + lc + 1];
                    *(__half2*)(qs + row * QSTRIDE + cb * 64 + lc) = __floats2half2_rn(v0, v1);
                }
            }
    }
    __syncthreads();

    // ---- phase C: attention (2 samples/warp), half2 arithmetic ----
    const int h = lane >> 3, a = lane & 7;
#pragma unroll
    for (int s2 = 0; s2 < 2; s2++) {
        const int s = wid * 2 + s2;
        const __half* base = qs + s * 8 * QSTRIDE;

        __half2 hq[8];
        {
            const __half2* qp = (const __half2*)(base + a * QSTRIDE + h * 16);
#pragma unroll
            for (int d2 = 0; d2 < 8; d2++) hq[d2] = qp[d2];
        }
        float sc[8], m = -1e30f;
#pragma unroll
        for (int b = 0; b < 8; b++) {
            const __half2* kp = (const __half2*)(base + b * QSTRIDE + 64 + h * 16);
            __half2 acc2 = __hmul2(hq[0], kp[0]);
#pragma unroll
            for (int d2 = 1; d2 < 8; d2++) acc2 = __hfma2(hq[d2], kp[d2], acc2);
            float2 f = __half22float2(acc2);
            sc[b] = (f.x + f.y) * 0.25f;    // 1/sqrt(16)
            m = fmaxf(m, sc[b]);
        }
        float sum = 0.f;
#pragma unroll
        for (int b = 0; b < 8; b++) { sc[b] = __expf(sc[b] - m); sum += sc[b]; }
        float inv = 1.f / sum;
        __half2 o2[8];
#pragma unroll
        for (int d2 = 0; d2 < 8; d2++) o2[d2] = __float2half2_rn(0.f);
#pragma unroll
        for (int b = 0; b < 8; b++) {
            __half2 ph = __float2half2_rn(sc[b] * inv);
            const __half2* vp = (const __half2*)(base + b * QSTRIDE + 128 + h * 16);
#pragma unroll
            for (int d2 = 0; d2 < 8; d2++) o2[d2] = __hfma2(ph, vp[d2], o2[d2]);
        }
        float part = 0.f;
#pragma unroll
        for (int d2 = 0; d2 < 8; d2++) {
            float2 f = __half22float2(o2[d2]);
            part += f.x * wc[h * 16 + d2 * 2] + f.y * wc[h * 16 + d2 * 2 + 1];
        }
        part += __shfl_xor_sync(0xffffffffu, part, 8);
        part += __shfl_xor_sync(0xffffffffu, part, 16);
        if (h == 0) {
            const int n = blockIdx.x * 16 + s;
            g_aq[n * 8 + a] = part + wc[64];
        }
    }
}

// ---------------- final mixing ----------------------------------------------
__global__ void __launch_bounds__(256) final_kernel(
    const float* __restrict__ Wv2, const float* __restrict__ bv2,
    float* __restrict__ out)
{
    const int warp = threadIdx.x >> 5, lane = threadIdx.x & 31;
    const int n = blockIdx.x * 8 + warp;
    if (n >= NTOT) return;

    float aqv[8];
#pragma unroll
    for (int a = 0; a < 8; a++) aqv[a] = g_aq[n * 8 + a];

    float tot = 0.f;
#pragma unroll
    for (int jj = 0; jj < 2; jj++) {
        int e = jj * 32 + lane;
        float hsum = g_b1[n * 64 + e];
#pragma unroll
        for (int a = 0; a < 8; a++) hsum += aqv[a] * g_w1[(size_t)n * 512 + a * 64 + e];
        float hid = hsum > 0.f ? hsum : expm1f(hsum);
        tot += hid * g_wf[n * 64 + e] + g_v1[n * 64 + e] * Wv2[e];
    }
#pragma unroll
    for (int off = 16; off > 0; off >>= 1) tot += __shfl_xor_sync(0xffffffffu, tot, off);
    if (lane == 0) out[n] = tot + bv2[0];
}

// ---------------- launch ----------------------------------------------------
extern "C" void kernel_launch(void* const* d_in, const int* in_sizes, int n_in,
                              void* d_out, int out_size)
{
    const float* agent_qs = (const float*)d_in[0];
    const float* states   = (const float*)d_in[1];
    const float* obs      = (const float*)d_in[2];
    const int*   actions  = (const int*)d_in[3];
    const float* W_obs = (const float*)d_in[4];  const float* b_obs = (const float*)d_in[5];
    const float* W_act = (const float*)d_in[6];  const float* b_act = (const float*)d_in[7];
    const float* W_q   = (const float*)d_in[8];  const float* b_q   = (const float*)d_in[9];
    const float* Wqkv  = (const float*)d_in[10]; const float* bqkv  = (const float*)d_in[11];
    const float* Wo    = (const float*)d_in[12]; const float* bo    = (const float*)d_in[13];
    const float* Wa2q  = (const float*)d_in[14]; const float* ba2q  = (const float*)d_in[15];
    const float* Wh1a  = (const float*)d_in[16]; const float* bh1a  = (const float*)d_in[17];
    const float* Wh1b  = (const float*)d_in[18]; const float* bh1b  = (const float*)d_in[19];
    const float* Whfa  = (const float*)d_in[20]; const float* bhfa  = (const float*)d_in[21];
    const float* Whfb  = (const float*)d_in[22]; const float* bhfb  = (const float*)d_in[23];
    const float* Wb1   = (const float*)d_in[24]; const float* bb1   = (const float*)d_in[25];
    const float* Wv1   = (const float*)d_in[26]; const float* bv1   = (const float*)d_in[27];
    const float* Wv2   = (const float*)d_in[28]; const float* bv2   = (const float*)d_in[29];
    float* out = (float*)d_out;

    void *p_xh, *p_sth, *p_wh, *p_h1h, *p_hfh, *p_w1, *p_wf, *p_b1, *p_v1;
    cudaGetSymbolAddress(&p_xh,  g_xh);
    cudaGetSymbolAddress(&p_sth, g_sth);
    cudaGetSymbolAddress(&p_wh,  g_wh);
    cudaGetSymbolAddress(&p_h1h, g_h1h);
    cudaGetSymbolAddress(&p_hfh, g_hfh);
    cudaGetSymbolAddress(&p_w1,  g_w1);
    cudaGetSymbolAddress(&p_wf,  g_wf);
    cudaGetSymbolAddress(&p_b1,  g_b1);
    cudaGetSymbolAddress(&p_v1,  g_v1);
    __half* wh = (__half*)p_wh;

    cudaFuncSetAttribute(enc_gemm,        cudaFuncAttributeMaxDynamicSharedMemorySize, ENC_SMEM_BYTES);
    cudaFuncSetAttribute(hp_gemm,         cudaFuncAttributeMaxDynamicSharedMemorySize, HP_SMEM_BYTES);
    cudaFuncSetAttribute(qkv_attn_kernel, cudaFuncAttributeMaxDynamicSharedMemorySize, QA_SMEM_BYTES);

    // 0) conversions: states + ALL weights -> fp16 k-perm pool
    HSegs segs;
    segs.src[0] = Wqkv;  segs.gbase[0] = 0;       // 384 groups
    segs.src[1] = W_obs; segs.gbase[1] = 384;     // 512
    segs.src[2] = Wh1a;  segs.gbase[2] = 896;     // 4096
    segs.src[3] = Whfa;  segs.gbase[3] = 4992;    // 4096
    segs.src[4] = Wh1b;  segs.gbase[4] = 9088;    // 4096
    segs.src[5] = Whfb;  segs.gbase[5] = 13184;   // 512
    segs.src[6] = Wb1;   segs.gbase[6] = 13696;   // 1024
    segs.src[7] = Wv1;   segs.gbase[7] = 14720;   // 1024 -> 15744 total
    cvt_all_kernel<<<CVT_ST_BLK + CVT_W_BLK, 256>>>(states, (__half*)p_sth, segs, wh);

    // 1) encoder (fp16 mma, A cvt on the fly) -> g_xh
    enc_gemm<<<1024, 256, ENC_SMEM_BYTES>>>(
        obs, wh + HOFF_WOBS, b_obs, (__half*)p_xh,
        actions, agent_qs, W_act, W_q, b_act, b_q);

    // 2) hp launch 1: h1a x4, hfa x4 (fp16 perm out), b1, v1 (fp32 out)
    HOps m1 = {};
    for (int i = 0; i < 4; i++)
        m1.v[i]     = { (__half*)p_sth, wh + HOFF_WH1A, bh1a, p_h1h, 512, 256, i * 64, 1, i * 128, 1 };
    for (int i = 0; i < 4; i++)
        m1.v[4 + i] = { (__half*)p_sth, wh + HOFF_WHFA, bhfa, p_hfh, 512, 256, i * 64, 1, 512 + i * 128, 1 };
    m1.v[8] = { (__half*)p_sth, wh + HOFF_WB1, bb1, p_b1, 512, 64, 0, 0, 1024, 0 };
    m1.v[9] = { (__half*)p_sth, wh + HOFF_WV1, bv1, p_v1, 512, 64, 0, 1, 1152, 0 };
    hp_gemm<<<1280, 256, HP_SMEM_BYTES>>>(m1);

    // 3) fused qkv + attention
    qkv_attn_kernel<<<1024, 256, QA_SMEM_BYTES>>>(wh + HOFF_WQKV, bqkv, Wa2q, ba2q, Wo, bo);

    // 4) hp launch 2: w1 x8, wf
    HOps m2 = {};
    for (int i = 0; i < 8; i++)
        m2.v[i] = { (__half*)p_h1h, wh + HOFF_WH1B, bh1b, p_w1, 256, 512, i * 64, 2, i * 128, 0 };
    m2.v[8] = { (__half*)p_hfh, wh + HOFF_WHFB, bhfb, p_wf, 256, 64, 0, 2, 1024, 0 };
    m2.v[9] = { (__half*)p_hfh, wh + HOFF_WHFB, bhfb, p_wf, 256, 64, 0, 2, 0x7FFFFFFF, 0 };
    hp_gemm<<<1152, 256, HP_SMEM_BYTES>>>(m2);

    // 5) final mix -> y
    final_kernel<<<2048, 256>>>(Wv2, bv2, out);
}

// round 15
// speedup vs baseline: 1.6294x; 1.0258x over previous
#include <cuda_runtime.h>
#include <cuda_fp16.h>
#include <math.h>
#include <cstdint>

#define NTOT 16384

// ---- fp32 A-stage geometry (encoder): 36-float padded rows ----
#define AS_F 4608          // 128*36 floats per stage
#define ROW36 (32 * 36)
#define EB_W (64 * 16)     // encoder B (fp16) words per stage

// ---- fp16 plane geometry: 16 words (64B) per 32-half row ----
#define ROWW 16
#define APLH (128 * ROWW)
#define BPLH (64 * ROWW)
#define PLH  (APLH + BPLH)

// ---------------- scratch (device globals) ----------------------------------
__device__ __align__(16) __half g_xh[131072 * 64];
__device__ __align__(16) __half g_sth[NTOT * 512];
__device__ __align__(16) __half g_wh[503808];
__device__ __align__(16) __half g_h1h[NTOT * 256];
__device__ __align__(16) __half g_hfh[NTOT * 256];
__device__ __align__(16) float g_aq[NTOT * 8];
__device__ __align__(16) __half g_w1h[NTOT * 512];
__device__ __align__(16) __half g_wfh[NTOT * 64];
__device__ __align__(16) float g_b1[NTOT * 64];
__device__ __align__(16) float g_v1[NTOT * 64];

// g_wh offsets (halves)
#define HOFF_WQKV 0
#define HOFF_WOBS 12288
#define HOFF_WH1A 28672
#define HOFF_WHFA 159744
#define HOFF_WH1B 290816
#define HOFF_WHFB 421888
#define HOFF_WB1  438272
#define HOFF_WV1  471040

// ---------------- helpers ---------------------------------------------------
__device__ __forceinline__ uint32_t smem_u32(const void* p) {
    uint32_t a;
    asm("{ .reg .u64 t; cvta.to.shared.u64 t, %1; cvt.u32.u64 %0, t; }" : "=r"(a) : "l"(p));
    return a;
}
__device__ __forceinline__ void cp16(uint32_t s, const void* g) {
    asm volatile("cp.async.cg.shared.global [%0], [%1], 16;" :: "r"(s), "l"(g));
}
#define CP_COMMIT asm volatile("cp.async.commit_group;" ::: "memory")
#define CP_WAIT(N) asm volatile("cp.async.wait_group %0;" :: "n"(N) : "memory")

__device__ __forceinline__ void mma_f16(float* c, uint32_t a0, uint32_t a1, uint32_t a2,
                                        uint32_t a3, uint32_t b0, uint32_t b1) {
    asm volatile(
        "mma.sync.aligned.m16n8k16.row.col.f32.f16.f16.f32 "
        "{%0,%1,%2,%3}, {%4,%5,%6,%7}, {%8,%9}, {%0,%1,%2,%3};\n"
        : "+f"(c[0]), "+f"(c[1]), "+f"(c[2]), "+f"(c[3])
        : "r"(a0), "r"(a1), "r"(a2), "r"(a3), "r"(b0), "r"(b1));
}
__device__ __forceinline__ uint32_t packh2(float lo, float hi) {
    __half2 h = __floats2half2_rn(lo, hi);
    return *(uint32_t*)&h;
}

// k-perm within each 32-half group
__device__ __forceinline__ int perm_half_base(int c) {   // c even
    int lg = c & 31;
    int gg = lg >> 4, l16 = lg & 15;
    int hi = (l16 >= 8) ? 1 : 0;
    int tt = (l16 - (hi ? 8 : 0)) >> 1;
    return (c & ~31) + (4 * tt + 2 * gg + hi) * 2;
}

// ---------------- fp16 compute: one 128x64x32 chunk -> 16 mma ---------------
__device__ __forceinline__ void compute_chunk_h(
    const uint32_t* __restrict__ Ab, const uint32_t* __restrict__ Bb,
    float acc[2][4][4], int wm, int wn, int g, int t)
{
    uint4 ar[2][2], br[4];
#pragma unroll
    for (int mi = 0; mi < 2; mi++)
#pragma unroll
        for (int rr = 0; rr < 2; rr++)
            ar[mi][rr] = *(const uint4*)(Ab + (wm * 32 + mi * 16 + rr * 8 + g) * ROWW + t * 4);
#pragma unroll
    for (int ni = 0; ni < 4; ni++)
        br[ni] = *(const uint4*)(Bb + (wn * 32 + ni * 8 + g) * ROWW + t * 4);
#pragma unroll
    for (int mi = 0; mi < 2; mi++)
#pragma unroll
        for (int ni = 0; ni < 4; ni++)
            mma_f16(acc[mi][ni], ar[mi][0].x, ar[mi][1].x, ar[mi][0].y, ar[mi][1].y,
                    br[ni].x, br[ni].y);
#pragma unroll
    for (int mi = 0; mi < 2; mi++)
#pragma unroll
        for (int ni = 0; ni < 4; ni++)
            mma_f16(acc[mi][ni], ar[mi][0].z, ar[mi][1].z, ar[mi][0].w, ar[mi][1].w,
                    br[ni].z, br[ni].w);
}

// ---- encoder chunk: A fp32 in smem (36-stride rows), cvt on the fly --------
__device__ __forceinline__ void compute_chunk_enc(
    const float* __restrict__ Ab, const uint32_t* __restrict__ Bb,
    float acc[2][4][4], int wm, int wn, int g, int t)
{
    uint4 ar[2][2], br[4];
#pragma unroll
    for (int mi = 0; mi < 2; mi++)
#pragma unroll
        for (int rr = 0; rr < 2; rr++) {
            const float* pr = Ab + (wm * 32 + mi * 16 + rr * 8 + g) * 36;
            float2 f0 = *(const float2*)(pr + 2 * t);
            float2 f1 = *(const float2*)(pr + 2 * t + 8);
            float2 f2 = *(const float2*)(pr + 16 + 2 * t);
            float2 f3 = *(const float2*)(pr + 24 + 2 * t);
            ar[mi][rr].x = packh2(f0.x, f0.y);
            ar[mi][rr].y = packh2(f1.x, f1.y);
            ar[mi][rr].z = packh2(f2.x, f2.y);
            ar[mi][rr].w = packh2(f3.x, f3.y);
        }
#pragma unroll
    for (int ni = 0; ni < 4; ni++)
        br[ni] = *(const uint4*)(Bb + (wn * 32 + ni * 8 + g) * ROWW + t * 4);
#pragma unroll
    for (int mi = 0; mi < 2; mi++)
#pragma unroll
        for (int ni = 0; ni < 4; ni++)
            mma_f16(acc[mi][ni], ar[mi][0].x, ar[mi][1].x, ar[mi][0].y, ar[mi][1].y,
                    br[ni].x, br[ni].y);
#pragma unroll
    for (int mi = 0; mi < 2; mi++)
#pragma unroll
        for (int ni = 0; ni < 4; ni++)
            mma_f16(acc[mi][ni], ar[mi][0].z, ar[mi][1].z, ar[mi][0].w, ar[mi][1].w,
                    br[ni].z, br[ni].w);
}

// ---------------- conversion kernel ------------------------------------------
__device__ __forceinline__ void cvt_group_h(const float* __restrict__ src, __half* __restrict__ dst)
{
    float v[32];
#pragma unroll
    for (int i = 0; i < 8; i++) *(float4*)&v[i * 4] = *(const float4*)(src + i * 4);
    uint32_t w[16];
#pragma unroll
    for (int W = 0; W < 16; W++) {
        int tt = W >> 2, gg = (W >> 1) & 1, hi = W & 1;
        int l0 = gg * 16 + hi * 8 + tt * 2;
        w[W] = packh2(v[l0], v[l0 + 1]);
    }
#pragma unroll
    for (int i = 0; i < 4; i++) ((uint4*)dst)[i] = *(uint4*)&w[i * 4];
}

struct HSegs { const float* src[8]; int gbase[8]; };
#define CVT_ST_BLK 1024
#define CVT_W_GROUPS 15744
#define CVT_W_BLK 62

__global__ void __launch_bounds__(256) cvt_all_kernel(
    const float* __restrict__ states, __half* __restrict__ sth,
    HSegs segs, __half* __restrict__ wh)
{
    int b = blockIdx.x, tid = threadIdx.x;
    if (b < CVT_ST_BLK) {
        int gidx = b * 256 + tid;
        cvt_group_h(states + (size_t)gidx * 32, sth + (size_t)gidx * 32);
    } else {
        int gidx = (b - CVT_ST_BLK) * 256 + tid;
        if (gidx < CVT_W_GROUPS) {
            int k = 0;
#pragma unroll
            for (int kk = 1; kk < 8; kk++) if (gidx >= segs.gbase[kk]) k = kk;
            cvt_group_h(segs.src[k] + (size_t)(gidx - segs.gbase[k]) * 32,
                        wh + (size_t)gidx * 32);
        }
    }
}

// ---------------- mega GEMM: encoder + fp16 GEMMs in one launch --------------
// epi: 0=id, 1=relu, 2=abs, 4=encoder. flags: 1=fp16 perm out, 2=fp16 linear out.
struct MOp {
    const void* A; const __half* B; const float* bias; void* C;
    int K; int Nout; int col0; int epi; int tileBase; int flags;
};
struct MOps { MOp v[11]; };
#define MG_SMEM_BYTES (12352 * 4)   // max(enc 11456, hp 12352) words

__global__ void __launch_bounds__(256, 3) mega_gemm(
    MOps ops,
    const int* __restrict__ actions, const float* __restrict__ qvals,
    const float* __restrict__ W_act, const float* __restrict__ W_q,
    const float* __restrict__ b_act, const float* __restrict__ b_q)
{
    extern __shared__ uint32_t sh[];

    const int bid = blockIdx.x;
    int j = 0;
#pragma unroll
    for (int k = 1; k < 11; k++) if (bid >= ops.v[k].tileBase) j = k;
    const MOp op = ops.v[j];

    const int tid = threadIdx.x;
    const int wid = tid >> 5, lane = tid & 31;
    const int wm = wid >> 1, wn = wid & 1;
    const int g = lane >> 2, t = lane & 3;
    const int row0 = (bid - op.tileBase) * 128;
    const int col0 = op.col0;
    const int K = op.K;

    float acc[2][4][4];
#pragma unroll
    for (int mi = 0; mi < 2; mi++)
#pragma unroll
        for (int ni = 0; ni < 4; ni++)
#pragma unroll
            for (int jj = 0; jj < 4; jj++) acc[mi][ni][jj] = 0.f;

    if (op.epi == 4) {
        // ===== encoder path: A fp32 staged, cvt on the fly =====
        float* dsm = (float*)sh;
        uint32_t* Bh = sh + 2 * AS_F;
        float* bias_sh = (float*)(Bh + 2 * EB_W);
        float* cvec_sh = bias_sh + 64;
        float* wq_sh   = cvec_sh + 64;
        if (tid < 64) {
            bias_sh[tid] = op.bias[tid];
            cvec_sh[tid] = b_act[tid] + b_q[tid];
            wq_sh[tid] = W_q[tid];
        }
        const float* A = (const float*)op.A;
        const uint32_t sua = smem_u32(dsm);
        const uint32_t sub = smem_u32(Bh);
        const int ra = tid >> 3, q4 = (tid & 7) * 4;
        const float* Ap = A + (size_t)(row0 + ra) * K + q4;
        const uint32_t sa = sua + (uint32_t)(ra * 36 + q4) * 4;
        const int rb = tid >> 2, wq = tid & 3;
        const __half* Bp = op.B + (size_t)rb * K + wq * 8;
        const uint32_t sb = sub + (uint32_t)(rb * ROWW + wq * 4) * 4;
        const int nk = K >> 5;
#pragma unroll
        for (int i = 0; i < 4; i++) cp16(sa + (uint32_t)(i * ROW36) * 4, Ap + (size_t)i * 32 * K);
        cp16(sb, Bp);
        CP_COMMIT;
        for (int c = 0; c < nk; c++) {
            CP_WAIT(0);
            __syncthreads();
            if (c + 1 < nk) {
                const uint32_t soa = (uint32_t)(((c + 1) & 1) * AS_F) * 4;
                const uint32_t sob = (uint32_t)(((c + 1) & 1) * EB_W) * 4;
#pragma unroll
                for (int i = 0; i < 4; i++)
                    cp16(sa + soa + (uint32_t)(i * ROW36) * 4, Ap + (c + 1) * 32 + (size_t)i * 32 * K);
                cp16(sb + sob, Bp + (c + 1) * 32);
            }
            CP_COMMIT;
            compute_chunk_enc(dsm + (c & 1) * AS_F, Bh + (c & 1) * EB_W, acc, wm, wn, g, t);
        }
        __half* Cx = (__half*)op.C;
#pragma unroll
        for (int mi = 0; mi < 2; mi++)
#pragma unroll
            for (int hh = 0; hh < 2; hh++) {
                const int row = row0 + wm * 32 + mi * 16 + hh * 8 + g;
                const int act = actions[row];
                const float qv = qvals[row];
#pragma unroll
                for (int ni = 0; ni < 4; ni++) {
                    const int lc = wn * 32 + ni * 8 + t * 2;
                    float v0 = acc[mi][ni][hh * 2 + 0] + bias_sh[lc]
                             + cvec_sh[lc] + __ldg(&W_act[lc * 32 + act]) + qv * wq_sh[lc];
                    float v1 = acc[mi][ni][hh * 2 + 1] + bias_sh[lc + 1]
                             + cvec_sh[lc + 1] + __ldg(&W_act[(lc + 1) * 32 + act]) + qv * wq_sh[lc + 1];
                    *(__half2*)(Cx + (size_t)row * 64 + perm_half_base(lc)) = __floats2half2_rn(v0, v1);
                }
            }
        return;
    }

    // ===== fp16 GEMM path: BK=64, 2-stage, one barrier per 64-k =====
    uint32_t* hsm = sh;
    float* bias_sh = (float*)(hsm + 4 * PLH);
    if (tid < 64) bias_sh[tid] = op.bias[col0 + tid];
    {
        const uint32_t su = smem_u32(hsm);
        const int arow = tid >> 2, awq = tid & 3;
        const __half* Ah = (const __half*)op.A;
        const __half* Ap  = Ah + (size_t)(row0 + arow) * K + awq * 8;
        const __half* Ap2 = Ap + (size_t)64 * K;
        const __half* Bp  = op.B + (size_t)(col0 + arow) * K + awq * 8;
        const uint32_t sa = su + (uint32_t)(arow * ROWW + awq * 4) * 4;
        const uint32_t sa2 = sa + (uint32_t)(64 * ROWW) * 4;
        const uint32_t sb = su + (uint32_t)(APLH + arow * ROWW + awq * 4) * 4;
        const int nk = K >> 6;
#pragma unroll
        for (int p = 0; p < 2; p++) {
            const uint32_t po = (uint32_t)(p * PLH) * 4;
            cp16(sa + po, Ap + p * 32); cp16(sa2 + po, Ap2 + p * 32); cp16(sb + po, Bp + p * 32);
        }
        CP_COMMIT;
        for (int c = 0; c < nk; c++) {
            CP_WAIT(0);
            __syncthreads();
            if (c + 1 < nk) {
                const uint32_t so = (uint32_t)(((c + 1) & 1) * 2 * PLH) * 4;
                const int off = (c + 1) * 64;
#pragma unroll
                for (int p = 0; p < 2; p++) {
                    const uint32_t po = so + (uint32_t)(p * PLH) * 4;
                    cp16(sa + po, Ap + off + p * 32);
                    cp16(sa2 + po, Ap2 + off + p * 32);
                    cp16(sb + po, Bp + off + p * 32);
                }
            }
            CP_COMMIT;
            const uint32_t* st = hsm + (c & 1) * 2 * PLH;
            compute_chunk_h(st, st + APLH, acc, wm, wn, g, t);
            compute_chunk_h(st + PLH, st + PLH + APLH, acc, wm, wn, g, t);
        }
    }
    const int Nout = op.Nout, epi = op.epi;
    const int hperm = op.flags & 1, hlin = op.flags & 2;
#pragma unroll
    for (int mi = 0; mi < 2; mi++)
#pragma unroll
        for (int hh = 0; hh < 2; hh++) {
            const int row = row0 + wm * 32 + mi * 16 + hh * 8 + g;
#pragma unroll
            for (int ni = 0; ni < 4; ni++) {
                const int lc = wn * 32 + ni * 8 + t * 2;
                float v0 = acc[mi][ni][hh * 2 + 0] + bias_sh[lc];
                float v1 = acc[mi][ni][hh * 2 + 1] + bias_sh[lc + 1];
                if (epi == 1) { v0 = fmaxf(v0, 0.f); v1 = fmaxf(v1, 0.f); }
                else if (epi == 2) { v0 = fabsf(v0); v1 = fabsf(v1); }
                if (hperm) {
                    const int cgl = col0 + lc;
                    *(__half2*)((__half*)op.C + (size_t)row * Nout + perm_half_base(cgl))
                        = __floats2half2_rn(v0, v1);
                } else if (hlin) {
                    *(__half2*)((__half*)op.C + (size_t)row * Nout + col0 + lc)
                        = __floats2half2_rn(v0, v1);
                } else {
                    float2 o = { v0, v1 };
                    *(float2*)((float*)op.C + (size_t)row * Nout + col0 + lc) = o;
                }
            }
        }
}

// ---------------- fused qkv + attention: 2 x-tiles per CTA, prefetch ---------
#define XPLH (128 * ROWW)
#define WPLH (192 * ROWW)
#define QSTRIDE 200
#define QA_QS_W (128 * QSTRIDE / 2)
#define QA_SMEM_BYTES ((4 * XPLH + 2 * WPLH + QA_QS_W + 192 + 65) * 4)

__global__ void __launch_bounds__(256, 2) qkv_attn_kernel(
    const __half* __restrict__ Wqkv_h, const float* __restrict__ bqkv,
    const float* __restrict__ Wa2q, const float* __restrict__ ba2q,
    const float* __restrict__ Wo, const float* __restrict__ bo)
{
    extern __shared__ uint32_t qsm[];
    uint32_t* ws = qsm + 4 * XPLH;          // [2 planes][192][ROWW]
    __half* qs = (__half*)(ws + 2 * WPLH);  // [128][QSTRIDE] fp16
    float* bq = (float*)(qs + 128 * QSTRIDE);
    float* wc = bq + 192;

    const int tid = threadIdx.x;
    const int wid = tid >> 5, lane = tid & 31;
    const int wm = wid >> 1, wn = wid & 1;
    const int g = lane >> 2, t = lane & 3;

    const uint32_t xs_u = smem_u32(qsm);
    const uint32_t ws_u = smem_u32(ws);

    // stage tile 0 x (bank 0) + Wqkv + constants
    {
        const int ti0 = blockIdx.x * 2;
#pragma unroll
        for (int i = 0; i < 4; i++) {
            int u = tid + i * 256;
            int c = u >> 9, r = (u >> 2) & 127, wq = u & 3;
            cp16(xs_u + (uint32_t)(c * XPLH + r * ROWW + wq * 4) * 4,
                 g_xh + (size_t)(ti0 * 128 + r) * 64 + c * 32 + wq * 8);
        }
#pragma unroll
        for (int i = 0; i < 6; i++) {
            int u = tid + i * 256;
            int c = (u >= 768) ? 1 : 0;
            int rem = u - c * 768;
            int r = rem >> 2, wq = rem & 3;
            cp16(ws_u + (uint32_t)(c * WPLH + r * ROWW + wq * 4) * 4,
                 Wqkv_h + (size_t)r * 64 + c * 32 + wq * 8);
        }
    }
    if (tid < 192) bq[tid] = bqkv[tid];
    if (tid < 64) {
        float s = 0.f;
#pragma unroll 8
        for (int c = 0; c < 64; c++) s += Wa2q[c] * Wo[c * 64 + tid];
        wc[tid] = s;
    }
    if (wid == 6) {
        float v = Wa2q[lane] * bo[lane] + Wa2q[lane + 32] * bo[lane + 32];
#pragma unroll
        for (int off = 16; off > 0; off >>= 1) v += __shfl_xor_sync(0xffffffffu, v, off);
        if (lane == 0) wc[64] = v + ba2q[0];
    }
    CP_COMMIT;

    const int h = lane >> 3, a = lane & 7;
#pragma unroll 1
    for (int it = 0; it < 2; it++) {
        CP_WAIT(0);
        __syncthreads();
        if (it == 0) {
            // prefetch tile 1 x into bank 1 (hidden under tile 0 compute)
            const int ti1 = blockIdx.x * 2 + 1;
#pragma unroll
            for (int i = 0; i < 4; i++) {
                int u = tid + i * 256;
                int c = u >> 9, r = (u >> 2) & 127, wq = u & 3;
                cp16(xs_u + (uint32_t)(2 * XPLH + c * XPLH + r * ROWW + wq * 4) * 4,
                     g_xh + (size_t)(ti1 * 128 + r) * 64 + c * 32 + wq * 8);
            }
            CP_COMMIT;
        }
        const uint32_t* xs = qsm + it * 2 * XPLH;

        // ---- phase B: qkv = x @ Wqkv^T -> qs (fp16) ----
#pragma unroll 1
        for (int cb = 0; cb < 3; cb++) {
            float acc[2][4][4];
#pragma unroll
            for (int mi = 0; mi < 2; mi++)
#pragma unroll
                for (int ni = 0; ni < 4; ni++)
#pragma unroll
                    for (int jj = 0; jj < 4; jj++) acc[mi][ni][jj] = 0.f;
#pragma unroll
            for (int c = 0; c < 2; c++)
                compute_chunk_h(xs + c * XPLH, ws + c * WPLH + (cb * 64) * ROWW,
                                acc, wm, wn, g, t);
#pragma unroll
            for (int mi = 0; mi < 2; mi++)
#pragma unroll
                for (int hh = 0; hh < 2; hh++) {
                    const int row = wm * 32 + mi * 16 + hh * 8 + g;
#pragma unroll
                    for (int ni = 0; ni < 4; ni++) {
                        const int lc = wn * 32 + ni * 8 + t * 2;
                        float v0 = acc[mi][ni][hh * 2 + 0] + bq[cb * 64 + lc];
                        float v1 = acc[mi][ni][hh * 2 + 1] + bq[cb * 64 + lc + 1];
                        *(__half2*)(qs + row * QSTRIDE + cb * 64 + lc) = __floats2half2_rn(v0, v1);
                    }
                }
        }
        __syncthreads();

        // ---- phase C: attention (2 samples/warp), half2 arithmetic ----
#pragma unroll
        for (int s2 = 0; s2 < 2; s2++) {
            const int s = wid * 2 + s2;
            const __half* base = qs + s * 8 * QSTRIDE;

            __half2 hq[8];
            {
                const __half2* qp = (const __half2*)(base + a * QSTRIDE + h * 16);
#pragma unroll
                for (int d2 = 0; d2 < 8; d2++) hq[d2] = qp[d2];
            }
            float sc[8], m = -1e30f;
#pragma unroll
            for (int b = 0; b < 8; b++) {
                const __half2* kp = (const __half2*)(base + b * QSTRIDE + 64 + h * 16);
                __half2 acc2 = __hmul2(hq[0], kp[0]);
#pragma unroll
                for (int d2 = 1; d2 < 8; d2++) acc2 = __hfma2(hq[d2], kp[d2], acc2);
                float2 f = __half22float2(acc2);
                sc[b] = (f.x + f.y) * 0.25f;
                m = fmaxf(m, sc[b]);
            }
            float sum = 0.f;
#pragma unroll
            for (int b = 0; b < 8; b++) { sc[b] = __expf(sc[b] - m); sum += sc[b]; }
            float inv = 1.f / sum;
            __half2 o2[8];
#pragma unroll
            for (int d2 = 0; d2 < 8; d2++) o2[d2] = __float2half2_rn(0.f);
#pragma unroll
            for (int b = 0; b < 8; b++) {
                __half2 ph = __float2half2_rn(sc[b] * inv);
                const __half2* vp = (const __half2*)(base + b * QSTRIDE + 128 + h * 16);
#pragma unroll
                for (int d2 = 0; d2 < 8; d2++) o2[d2] = __hfma2(ph, vp[d2], o2[d2]);
            }
            float part = 0.f;
#pragma unroll
            for (int d2 = 0; d2 < 8; d2++) {
                float2 f = __half22float2(o2[d2]);
                part += f.x * wc[h * 16 + d2 * 2] + f.y * wc[h * 16 + d2 * 2 + 1];
            }
            part += __shfl_xor_sync(0xffffffffu, part, 8);
            part += __shfl_xor_sync(0xffffffffu, part, 16);
            if (h == 0) {
                const int n = (blockIdx.x * 2 + it) * 16 + s;
                g_aq[n * 8 + a] = part + wc[64];
            }
        }
        __syncthreads();   // qs reused by next tile's phase B
    }
}

// ---------------- final mixing (fp16 w1/wf) ----------------------------------
__global__ void __launch_bounds__(256) final_kernel(
    const float* __restrict__ Wv2, const float* __restrict__ bv2,
    float* __restrict__ out)
{
    const int warp = threadIdx.x >> 5, lane = threadIdx.x & 31;
    const int n = blockIdx.x * 8 + warp;
    if (n >= NTOT) return;

    float aqv[8];
#pragma unroll
    for (int a = 0; a < 8; a++) aqv[a] = g_aq[n * 8 + a];

    float tot = 0.f;
#pragma unroll
    for (int jj = 0; jj < 2; jj++) {
        int e = jj * 32 + lane;
        float hsum = g_b1[n * 64 + e];
#pragma unroll
        for (int a = 0; a < 8; a++)
            hsum += aqv[a] * __half2float(g_w1h[(size_t)n * 512 + a * 64 + e]);
        float hid = hsum > 0.f ? hsum : expm1f(hsum);
        tot += hid * __half2float(g_wfh[n * 64 + e]) + g_v1[n * 64 + e] * Wv2[e];
    }
#pragma unroll
    for (int off = 16; off > 0; off >>= 1) tot += __shfl_xor_sync(0xffffffffu, tot, off);
    if (lane == 0) out[n] = tot + bv2[0];
}

// ---------------- launch ----------------------------------------------------
extern "C" void kernel_launch(void* const* d_in, const int* in_sizes, int n_in,
                              void* d_out, int out_size)
{
    const float* agent_qs = (const float*)d_in[0];
    const float* states   = (const float*)d_in[1];
    const float* obs      = (const float*)d_in[2];
    const int*   actions  = (const int*)d_in[3];
    const float* W_obs = (const float*)d_in[4];  const float* b_obs = (const float*)d_in[5];
    const float* W_act = (const float*)d_in[6];  const float* b_act = (const float*)d_in[7];
    const float* W_q   = (const float*)d_in[8];  const float* b_q   = (const float*)d_in[9];
    const float* Wqkv  = (const float*)d_in[10]; const float* bqkv  = (const float*)d_in[11];
    const float* Wo    = (const float*)d_in[12]; const float* bo    = (const float*)d_in[13];
    const float* Wa2q  = (const float*)d_in[14]; const float* ba2q  = (const float*)d_in[15];
    const float* Wh1a  = (const float*)d_in[16]; const float* bh1a  = (const float*)d_in[17];
    const float* Wh1b  = (const float*)d_in[18]; const float* bh1b  = (const float*)d_in[19];
    const float* Whfa  = (const float*)d_in[20]; const float* bhfa  = (const float*)d_in[21];
    const float* Whfb  = (const float*)d_in[22]; const float* bhfb  = (const float*)d_in[23];
    const float* Wb1   = (const float*)d_in[24]; const float* bb1   = (const float*)d_in[25];
    const float* Wv1   = (const float*)d_in[26]; const float* bv1   = (const float*)d_in[27];
    const float* Wv2   = (const float*)d_in[28]; const float* bv2   = (const float*)d_in[29];
    float* out = (float*)d_out;

    void *p_xh, *p_sth, *p_wh, *p_h1h, *p_hfh, *p_w1h, *p_wfh, *p_b1, *p_v1;
    cudaGetSymbolAddress(&p_xh,  g_xh);
    cudaGetSymbolAddress(&p_sth, g_sth);
    cudaGetSymbolAddress(&p_wh,  g_wh);
    cudaGetSymbolAddress(&p_h1h, g_h1h);
    cudaGetSymbolAddress(&p_hfh, g_hfh);
    cudaGetSymbolAddress(&p_w1h, g_w1h);
    cudaGetSymbolAddress(&p_wfh, g_wfh);
    cudaGetSymbolAddress(&p_b1,  g_b1);
    cudaGetSymbolAddress(&p_v1,  g_v1);
    __half* wh = (__half*)p_wh;

    cudaFuncSetAttribute(mega_gemm,       cudaFuncAttributeMaxDynamicSharedMemorySize, MG_SMEM_BYTES);
    cudaFuncSetAttribute(qkv_attn_kernel, cudaFuncAttributeMaxDynamicSharedMemorySize, QA_SMEM_BYTES);

    // 0) conversions: states + ALL weights -> fp16 k-perm pool
    HSegs segs;
    segs.src[0] = Wqkv;  segs.gbase[0] = 0;
    segs.src[1] = W_obs; segs.gbase[1] = 384;
    segs.src[2] = Wh1a;  segs.gbase[2] = 896;
    segs.src[3] = Whfa;  segs.gbase[3] = 4992;
    segs.src[4] = Wh1b;  segs.gbase[4] = 9088;
    segs.src[5] = Whfb;  segs.gbase[5] = 13184;
    segs.src[6] = Wb1;   segs.gbase[6] = 13696;
    segs.src[7] = Wv1;   segs.gbase[7] = 14720;
    cvt_all_kernel<<<CVT_ST_BLK + CVT_W_BLK, 256>>>(states, (__half*)p_sth, segs, wh);

    // 1) mega launch 1: encoder (1024 tiles) + h1a x4 + hfa x4 + b1 + v1
    MOps m1 = {};
    m1.v[0] = { obs, wh + HOFF_WOBS, b_obs, p_xh, 256, 64, 0, 4, 0, 0 };
    for (int i = 0; i < 4; i++)
        m1.v[1 + i] = { p_sth, wh + HOFF_WH1A, bh1a, p_h1h, 512, 256, i * 64, 1, 1024 + i * 128, 1 };
    for (int i = 0; i < 4; i++)
        m1.v[5 + i] = { p_sth, wh + HOFF_WHFA, bhfa, p_hfh, 512, 256, i * 64, 1, 1536 + i * 128, 1 };
    m1.v[9]  = { p_sth, wh + HOFF_WB1, bb1, p_b1, 512, 64, 0, 0, 2048, 0 };
    m1.v[10] = { p_sth, wh + HOFF_WV1, bv1, p_v1, 512, 64, 0, 1, 2176, 0 };
    mega_gemm<<<2304, 256, MG_SMEM_BYTES>>>(m1, actions, agent_qs, W_act, W_q, b_act, b_q);

    // 2) fused qkv + attention (2 tiles/CTA)
    qkv_attn_kernel<<<512, 256, QA_SMEM_BYTES>>>(wh + HOFF_WQKV, bqkv, Wa2q, ba2q, Wo, bo);

    // 3) mega launch 2: w1 x8 (fp16 out), wf (fp16 out)
    MOps m2 = {};
    for (int i = 0; i < 8; i++)
        m2.v[i] = { p_h1h, wh + HOFF_WH1B, bh1b, p_w1h, 256, 512, i * 64, 2, i * 128, 2 };
    m2.v[8]  = { p_hfh, wh + HOFF_WHFB, bhfb, p_wfh, 256, 64, 0, 2, 1024, 2 };
    m2.v[9]  = { p_hfh, wh + HOFF_WHFB, bhfb, p_wfh, 256, 64, 0, 2, 0x7FFFFFFF, 2 };
    m2.v[10] = { p_hfh, wh + HOFF_WHFB, bhfb, p_wfh, 256, 64, 0, 2, 0x7FFFFFFF, 2 };
    mega_gemm<<<1152, 256, MG_SMEM_BYTES>>>(m2, actions, agent_qs, W_act, W_q, b_act, b_q);

    // 4) final mix -> y
    final_kernel<<<2048, 256>>>(Wv2, bv2, out);
}

// round 16
// speedup vs baseline: 1.7583x; 1.0791x over previous
#include <cuda_runtime.h>
#include <cuda_fp16.h>
#include <math.h>
#include <cstdint>

#define NTOT 16384

// ---- fp32 A-stage geometry (encoder): 36-float padded rows ----
#define AS_F 4608          // 128*36 floats per stage
#define ROW36 (32 * 36)
#define EB_W (64 * 16)     // encoder B (fp16) words per stage

// ---- fp16 plane geometry: 16 words (64B) per 32-half row ----
#define ROWW 16
#define APLH (128 * ROWW)
#define BPLH (64 * ROWW)
#define PLH  (APLH + BPLH)

// ---------------- scratch (device globals) ----------------------------------
__device__ __align__(16) __half g_xh[131072 * 64];
__device__ __align__(16) __half g_sth[NTOT * 512];
__device__ __align__(16) __half g_wh[503808];
__device__ __align__(16) __half g_h1h[NTOT * 256];
__device__ __align__(16) __half g_hfh[NTOT * 256];
__device__ __align__(16) float g_aq[NTOT * 8];
__device__ __align__(16) __half g_w1h[NTOT * 512];
__device__ __align__(16) __half g_wfh[NTOT * 64];
__device__ __align__(16) float g_b1[NTOT * 64];
__device__ __align__(16) float g_v1[NTOT * 64];

// g_wh offsets (halves)
#define HOFF_WQKV 0
#define HOFF_WOBS 12288
#define HOFF_WH1A 28672
#define HOFF_WHFA 159744
#define HOFF_WH1B 290816
#define HOFF_WHFB 421888
#define HOFF_WB1  438272
#define HOFF_WV1  471040

// ---------------- helpers ---------------------------------------------------
__device__ __forceinline__ uint32_t smem_u32(const void* p) {
    uint32_t a;
    asm("{ .reg .u64 t; cvta.to.shared.u64 t, %1; cvt.u32.u64 %0, t; }" : "=r"(a) : "l"(p));
    return a;
}
__device__ __forceinline__ void cp16(uint32_t s, const void* g) {
    asm volatile("cp.async.cg.shared.global [%0], [%1], 16;" :: "r"(s), "l"(g));
}
#define CP_COMMIT asm volatile("cp.async.commit_group;" ::: "memory")
#define CP_WAIT(N) asm volatile("cp.async.wait_group %0;" :: "n"(N) : "memory")

__device__ __forceinline__ void mma_f16(float* c, uint32_t a0, uint32_t a1, uint32_t a2,
                                        uint32_t a3, uint32_t b0, uint32_t b1) {
    asm volatile(
        "mma.sync.aligned.m16n8k16.row.col.f32.f16.f16.f32 "
        "{%0,%1,%2,%3}, {%4,%5,%6,%7}, {%8,%9}, {%0,%1,%2,%3};\n"
        : "+f"(c[0]), "+f"(c[1]), "+f"(c[2]), "+f"(c[3])
        : "r"(a0), "r"(a1), "r"(a2), "r"(a3), "r"(b0), "r"(b1));
}
__device__ __forceinline__ uint32_t packh2(float lo, float hi) {
    __half2 h = __floats2half2_rn(lo, hi);
    return *(uint32_t*)&h;
}

// k-perm within each 32-half group
__device__ __forceinline__ int perm_half_base(int c) {   // c even
    int lg = c & 31;
    int gg = lg >> 4, l16 = lg & 15;
    int hi = (l16 >= 8) ? 1 : 0;
    int tt = (l16 - (hi ? 8 : 0)) >> 1;
    return (c & ~31) + (4 * tt + 2 * gg + hi) * 2;
}

// ---------------- fp16 compute: one 128x64x32 chunk -> 16 mma ---------------
__device__ __forceinline__ void compute_chunk_h(
    const uint32_t* __restrict__ Ab, const uint32_t* __restrict__ Bb,
    float acc[2][4][4], int wm, int wn, int g, int t)
{
    uint4 ar[2][2], br[4];
#pragma unroll
    for (int mi = 0; mi < 2; mi++)
#pragma unroll
        for (int rr = 0; rr < 2; rr++)
            ar[mi][rr] = *(const uint4*)(Ab + (wm * 32 + mi * 16 + rr * 8 + g) * ROWW + t * 4);
#pragma unroll
    for (int ni = 0; ni < 4; ni++)
        br[ni] = *(const uint4*)(Bb + (wn * 32 + ni * 8 + g) * ROWW + t * 4);
#pragma unroll
    for (int mi = 0; mi < 2; mi++)
#pragma unroll
        for (int ni = 0; ni < 4; ni++)
            mma_f16(acc[mi][ni], ar[mi][0].x, ar[mi][1].x, ar[mi][0].y, ar[mi][1].y,
                    br[ni].x, br[ni].y);
#pragma unroll
    for (int mi = 0; mi < 2; mi++)
#pragma unroll
        for (int ni = 0; ni < 4; ni++)
            mma_f16(acc[mi][ni], ar[mi][0].z, ar[mi][1].z, ar[mi][0].w, ar[mi][1].w,
                    br[ni].z, br[ni].w);
}

// ---- encoder chunk: A fp32 in smem (36-stride rows), cvt on the fly --------
__device__ __forceinline__ void compute_chunk_enc(
    const float* __restrict__ Ab, const uint32_t* __restrict__ Bb,
    float acc[2][4][4], int wm, int wn, int g, int t)
{
    uint4 ar[2][2], br[4];
#pragma unroll
    for (int mi = 0; mi < 2; mi++)
#pragma unroll
        for (int rr = 0; rr < 2; rr++) {
            const float* pr = Ab + (wm * 32 + mi * 16 + rr * 8 + g) * 36;
            float2 f0 = *(const float2*)(pr + 2 * t);
            float2 f1 = *(const float2*)(pr + 2 * t + 8);
            float2 f2 = *(const float2*)(pr + 16 + 2 * t);
            float2 f3 = *(const float2*)(pr + 24 + 2 * t);
            ar[mi][rr].x = packh2(f0.x, f0.y);
            ar[mi][rr].y = packh2(f1.x, f1.y);
            ar[mi][rr].z = packh2(f2.x, f2.y);
            ar[mi][rr].w = packh2(f3.x, f3.y);
        }
#pragma unroll
    for (int ni = 0; ni < 4; ni++)
        br[ni] = *(const uint4*)(Bb + (wn * 32 + ni * 8 + g) * ROWW + t * 4);
#pragma unroll
    for (int mi = 0; mi < 2; mi++)
#pragma unroll
        for (int ni = 0; ni < 4; ni++)
            mma_f16(acc[mi][ni], ar[mi][0].x, ar[mi][1].x, ar[mi][0].y, ar[mi][1].y,
                    br[ni].x, br[ni].y);
#pragma unroll
    for (int mi = 0; mi < 2; mi++)
#pragma unroll
        for (int ni = 0; ni < 4; ni++)
            mma_f16(acc[mi][ni], ar[mi][0].z, ar[mi][1].z, ar[mi][0].w, ar[mi][1].w,
                    br[ni].z, br[ni].w);
}

// ---------------- conversion kernel ------------------------------------------
__device__ __forceinline__ void cvt_group_h(const float* __restrict__ src, __half* __restrict__ dst)
{
    float v[32];
#pragma unroll
    for (int i = 0; i < 8; i++) *(float4*)&v[i * 4] = *(const float4*)(src + i * 4);
    uint32_t w[16];
#pragma unroll
    for (int W = 0; W < 16; W++) {
        int tt = W >> 2, gg = (W >> 1) & 1, hi = W & 1;
        int l0 = gg * 16 + hi * 8 + tt * 2;
        w[W] = packh2(v[l0], v[l0 + 1]);
    }
#pragma unroll
    for (int i = 0; i < 4; i++) ((uint4*)dst)[i] = *(uint4*)&w[i * 4];
}

struct HSegs { const float* src[8]; int gbase[8]; };
#define CVT_ST_BLK 1024
#define CVT_W_GROUPS 15744
#define CVT_W_BLK 62

__global__ void __launch_bounds__(256) cvt_all_kernel(
    const float* __restrict__ states, __half* __restrict__ sth,
    HSegs segs, __half* __restrict__ wh)
{
    int b = blockIdx.x, tid = threadIdx.x;
    if (b < CVT_ST_BLK) {
        int gidx = b * 256 + tid;
        cvt_group_h(states + (size_t)gidx * 32, sth + (size_t)gidx * 32);
    } else {
        int gidx = (b - CVT_ST_BLK) * 256 + tid;
        if (gidx < CVT_W_GROUPS) {
            int k = 0;
#pragma unroll
            for (int kk = 1; kk < 8; kk++) if (gidx >= segs.gbase[kk]) k = kk;
            cvt_group_h(segs.src[k] + (size_t)(gidx - segs.gbase[k]) * 32,
                        wh + (size_t)gidx * 32);
        }
    }
}

// ---------------- mega GEMM (encoder + fp16 GEMM paths) ----------------------
struct MOp {
    const void* A; const __half* B; const float* bias; void* C;
    int K; int Nout; int col0; int epi; int tileBase; int flags;
};
struct MOps { MOp v[11]; };
#define MG_SMEM_BYTES (12352 * 4)

__global__ void __launch_bounds__(256, 3) mega_gemm(
    MOps ops,
    const int* __restrict__ actions, const float* __restrict__ qvals,
    const float* __restrict__ W_act, const float* __restrict__ W_q,
    const float* __restrict__ b_act, const float* __restrict__ b_q)
{
    extern __shared__ uint32_t sh[];

    const int bid = blockIdx.x;
    int j = 0;
#pragma unroll
    for (int k = 1; k < 11; k++) if (bid >= ops.v[k].tileBase) j = k;
    const MOp op = ops.v[j];

    const int tid = threadIdx.x;
    const int wid = tid >> 5, lane = tid & 31;
    const int wm = wid >> 1, wn = wid & 1;
    const int g = lane >> 2, t = lane & 3;
    const int row0 = (bid - op.tileBase) * 128;
    const int col0 = op.col0;
    const int K = op.K;

    float acc[2][4][4];
#pragma unroll
    for (int mi = 0; mi < 2; mi++)
#pragma unroll
        for (int ni = 0; ni < 4; ni++)
#pragma unroll
            for (int jj = 0; jj < 4; jj++) acc[mi][ni][jj] = 0.f;

    if (op.epi == 4) {
        float* dsm = (float*)sh;
        uint32_t* Bh = sh + 2 * AS_F;
        float* bias_sh = (float*)(Bh + 2 * EB_W);
        float* cvec_sh = bias_sh + 64;
        float* wq_sh   = cvec_sh + 64;
        if (tid < 64) {
            bias_sh[tid] = op.bias[tid];
            cvec_sh[tid] = b_act[tid] + b_q[tid];
            wq_sh[tid] = W_q[tid];
        }
        const float* A = (const float*)op.A;
        const uint32_t sua = smem_u32(dsm);
        const uint32_t sub = smem_u32(Bh);
        const int ra = tid >> 3, q4 = (tid & 7) * 4;
        const float* Ap = A + (size_t)(row0 + ra) * K + q4;
        const uint32_t sa = sua + (uint32_t)(ra * 36 + q4) * 4;
        const int rb = tid >> 2, wq = tid & 3;
        const __half* Bp = op.B + (size_t)rb * K + wq * 8;
        const uint32_t sb = sub + (uint32_t)(rb * ROWW + wq * 4) * 4;
        const int nk = K >> 5;
#pragma unroll
        for (int i = 0; i < 4; i++) cp16(sa + (uint32_t)(i * ROW36) * 4, Ap + (size_t)i * 32 * K);
        cp16(sb, Bp);
        CP_COMMIT;
        for (int c = 0; c < nk; c++) {
            CP_WAIT(0);
            __syncthreads();
            if (c + 1 < nk) {
                const uint32_t soa = (uint32_t)(((c + 1) & 1) * AS_F) * 4;
                const uint32_t sob = (uint32_t)(((c + 1) & 1) * EB_W) * 4;
#pragma unroll
                for (int i = 0; i < 4; i++)
                    cp16(sa + soa + (uint32_t)(i * ROW36) * 4, Ap + (c + 1) * 32 + (size_t)i * 32 * K);
                cp16(sb + sob, Bp + (c + 1) * 32);
            }
            CP_COMMIT;
            compute_chunk_enc(dsm + (c & 1) * AS_F, Bh + (c & 1) * EB_W, acc, wm, wn, g, t);
        }
        __half* Cx = (__half*)op.C;
#pragma unroll
        for (int mi = 0; mi < 2; mi++)
#pragma unroll
            for (int hh = 0; hh < 2; hh++) {
                const int row = row0 + wm * 32 + mi * 16 + hh * 8 + g;
                const int act = actions[row];
                const float qv = qvals[row];
#pragma unroll
                for (int ni = 0; ni < 4; ni++) {
                    const int lc = wn * 32 + ni * 8 + t * 2;
                    float v0 = acc[mi][ni][hh * 2 + 0] + bias_sh[lc]
                             + cvec_sh[lc] + __ldg(&W_act[lc * 32 + act]) + qv * wq_sh[lc];
                    float v1 = acc[mi][ni][hh * 2 + 1] + bias_sh[lc + 1]
                             + cvec_sh[lc + 1] + __ldg(&W_act[(lc + 1) * 32 + act]) + qv * wq_sh[lc + 1];
                    *(__half2*)(Cx + (size_t)row * 64 + perm_half_base(lc)) = __floats2half2_rn(v0, v1);
                }
            }
        return;
    }

    // ===== fp16 GEMM path: BK=64, 2-stage, one barrier per 64-k =====
    uint32_t* hsm = sh;
    float* bias_sh = (float*)(hsm + 4 * PLH);
    if (tid < 64) bias_sh[tid] = op.bias[col0 + tid];
    {
        const uint32_t su = smem_u32(hsm);
        const int arow = tid >> 2, awq = tid & 3;
        const __half* Ah = (const __half*)op.A;
        const __half* Ap  = Ah + (size_t)(row0 + arow) * K + awq * 8;
        const __half* Ap2 = Ap + (size_t)64 * K;
        const __half* Bp  = op.B + (size_t)(col0 + arow) * K + awq * 8;
        const uint32_t sa = su + (uint32_t)(arow * ROWW + awq * 4) * 4;
        const uint32_t sa2 = sa + (uint32_t)(64 * ROWW) * 4;
        const uint32_t sb = su + (uint32_t)(APLH + arow * ROWW + awq * 4) * 4;
        const int nk = K >> 6;
#pragma unroll
        for (int p = 0; p < 2; p++) {
            const uint32_t po = (uint32_t)(p * PLH) * 4;
            cp16(sa + po, Ap + p * 32); cp16(sa2 + po, Ap2 + p * 32); cp16(sb + po, Bp + p * 32);
        }
        CP_COMMIT;
        for (int c = 0; c < nk; c++) {
            CP_WAIT(0);
            __syncthreads();
            if (c + 1 < nk) {
                const uint32_t so = (uint32_t)(((c + 1) & 1) * 2 * PLH) * 4;
                const int off = (c + 1) * 64;
#pragma unroll
                for (int p = 0; p < 2; p++) {
                    const uint32_t po = so + (uint32_t)(p * PLH) * 4;
                    cp16(sa + po, Ap + off + p * 32);
                    cp16(sa2 + po, Ap2 + off + p * 32);
                    cp16(sb + po, Bp + off + p * 32);
                }
            }
            CP_COMMIT;
            const uint32_t* st = hsm + (c & 1) * 2 * PLH;
            compute_chunk_h(st, st + APLH, acc, wm, wn, g, t);
            compute_chunk_h(st + PLH, st + PLH + APLH, acc, wm, wn, g, t);
        }
    }
    const int Nout = op.Nout, epi = op.epi;
    const int hperm = op.flags & 1, hlin = op.flags & 2;
#pragma unroll
    for (int mi = 0; mi < 2; mi++)
#pragma unroll
        for (int hh = 0; hh < 2; hh++) {
            const int row = row0 + wm * 32 + mi * 16 + hh * 8 + g;
#pragma unroll
            for (int ni = 0; ni < 4; ni++) {
                const int lc = wn * 32 + ni * 8 + t * 2;
                float v0 = acc[mi][ni][hh * 2 + 0] + bias_sh[lc];
                float v1 = acc[mi][ni][hh * 2 + 1] + bias_sh[lc + 1];
                if (epi == 1) { v0 = fmaxf(v0, 0.f); v1 = fmaxf(v1, 0.f); }
                else if (epi == 2) { v0 = fabsf(v0); v1 = fabsf(v1); }
                if (hperm) {
                    const int cgl = col0 + lc;
                    *(__half2*)((__half*)op.C + (size_t)row * Nout + perm_half_base(cgl))
                        = __floats2half2_rn(v0, v1);
                } else if (hlin) {
                    *(__half2*)((__half*)op.C + (size_t)row * Nout + col0 + lc)
                        = __floats2half2_rn(v0, v1);
                } else {
                    float2 o = { v0, v1 };
                    *(float2*)((float*)op.C + (size_t)row * Nout + col0 + lc) = o;
                }
            }
        }
}

// ---------------- fused qkv + attention: 2 x-tiles per CTA, prefetch ---------
#define XPLH (128 * ROWW)
#define WPLH (192 * ROWW)
#define QSTRIDE 200
#define QA_QS_W (128 * QSTRIDE / 2)
#define QA_SMEM_BYTES ((4 * XPLH + 2 * WPLH + QA_QS_W + 192 + 65) * 4)

__global__ void __launch_bounds__(256, 2) qkv_attn_kernel(
    const __half* __restrict__ Wqkv_h, const float* __restrict__ bqkv,
    const float* __restrict__ Wa2q, const float* __restrict__ ba2q,
    const float* __restrict__ Wo, const float* __restrict__ bo)
{
    extern __shared__ uint32_t qsm[];
    uint32_t* ws = qsm + 4 * XPLH;
    __half* qs = (__half*)(ws + 2 * WPLH);
    float* bq = (float*)(qs + 128 * QSTRIDE);
    float* wc = bq + 192;

    const int tid = threadIdx.x;
    const int wid = tid >> 5, lane = tid & 31;
    const int wm = wid >> 1, wn = wid & 1;
    const int g = lane >> 2, t = lane & 3;

    const uint32_t xs_u = smem_u32(qsm);
    const uint32_t ws_u = smem_u32(ws);

    {
        const int ti0 = blockIdx.x * 2;
#pragma unroll
        for (int i = 0; i < 4; i++) {
            int u = tid + i * 256;
            int c = u >> 9, r = (u >> 2) & 127, wq = u & 3;
            cp16(xs_u + (uint32_t)(c * XPLH + r * ROWW + wq * 4) * 4,
                 g_xh + (size_t)(ti0 * 128 + r) * 64 + c * 32 + wq * 8);
        }
#pragma unroll
        for (int i = 0; i < 6; i++) {
            int u = tid + i * 256;
            int c = (u >= 768) ? 1 : 0;
            int rem = u - c * 768;
            int r = rem >> 2, wq = rem & 3;
            cp16(ws_u + (uint32_t)(c * WPLH + r * ROWW + wq * 4) * 4,
                 Wqkv_h + (size_t)r * 64 + c * 32 + wq * 8);
        }
    }
    if (tid < 192) bq[tid] = bqkv[tid];
    if (tid < 64) {
        float s = 0.f;
#pragma unroll 8
        for (int c = 0; c < 64; c++) s += Wa2q[c] * Wo[c * 64 + tid];
        wc[tid] = s;
    }
    if (wid == 6) {
        float v = Wa2q[lane] * bo[lane] + Wa2q[lane + 32] * bo[lane + 32];
#pragma unroll
        for (int off = 16; off > 0; off >>= 1) v += __shfl_xor_sync(0xffffffffu, v, off);
        if (lane == 0) wc[64] = v + ba2q[0];
    }
    CP_COMMIT;

    const int h = lane >> 3, a = lane & 7;
#pragma unroll 1
    for (int it = 0; it < 2; it++) {
        CP_WAIT(0);
        __syncthreads();
        if (it == 0) {
            const int ti1 = blockIdx.x * 2 + 1;
#pragma unroll
            for (int i = 0; i < 4; i++) {
                int u = tid + i * 256;
                int c = u >> 9, r = (u >> 2) & 127, wq = u & 3;
                cp16(xs_u + (uint32_t)(2 * XPLH + c * XPLH + r * ROWW + wq * 4) * 4,
                     g_xh + (size_t)(ti1 * 128 + r) * 64 + c * 32 + wq * 8);
            }
            CP_COMMIT;
        }
        const uint32_t* xs = qsm + it * 2 * XPLH;

#pragma unroll 1
        for (int cb = 0; cb < 3; cb++) {
            float acc[2][4][4];
#pragma unroll
            for (int mi = 0; mi < 2; mi++)
#pragma unroll
                for (int ni = 0; ni < 4; ni++)
#pragma unroll
                    for (int jj = 0; jj < 4; jj++) acc[mi][ni][jj] = 0.f;
#pragma unroll
            for (int c = 0; c < 2; c++)
                compute_chunk_h(xs + c * XPLH, ws + c * WPLH + (cb * 64) * ROWW,
                                acc, wm, wn, g, t);
#pragma unroll
            for (int mi = 0; mi < 2; mi++)
#pragma unroll
                for (int hh = 0; hh < 2; hh++) {
                    const int row = wm * 32 + mi * 16 + hh * 8 + g;
#pragma unroll
                    for (int ni = 0; ni < 4; ni++) {
                        const int lc = wn * 32 + ni * 8 + t * 2;
                        float v0 = acc[mi][ni][hh * 2 + 0] + bq[cb * 64 + lc];
                        float v1 = acc[mi][ni][hh * 2 + 1] + bq[cb * 64 + lc + 1];
                        *(__half2*)(qs + row * QSTRIDE + cb * 64 + lc) = __floats2half2_rn(v0, v1);
                    }
                }
        }
        __syncthreads();

#pragma unroll
        for (int s2 = 0; s2 < 2; s2++) {
            const int s = wid * 2 + s2;
            const __half* base = qs + s * 8 * QSTRIDE;

            __half2 hq[8];
            {
                const __half2* qp = (const __half2*)(base + a * QSTRIDE + h * 16);
#pragma unroll
                for (int d2 = 0; d2 < 8; d2++) hq[d2] = qp[d2];
            }
            float sc[8], m = -1e30f;
#pragma unroll
            for (int b = 0; b < 8; b++) {
                const __half2* kp = (const __half2*)(base + b * QSTRIDE + 64 + h * 16);
                __half2 acc2 = __hmul2(hq[0], kp[0]);
#pragma unroll
                for (int d2 = 1; d2 < 8; d2++) acc2 = __hfma2(hq[d2], kp[d2], acc2);
                float2 f = __half22float2(acc2);
                sc[b] = (f.x + f.y) * 0.25f;
                m = fmaxf(m, sc[b]);
            }
            float sum = 0.f;
#pragma unroll
            for (int b = 0; b < 8; b++) { sc[b] = __expf(sc[b] - m); sum += sc[b]; }
            float inv = 1.f / sum;
            __half2 o2[8];
#pragma unroll
            for (int d2 = 0; d2 < 8; d2++) o2[d2] = __float2half2_rn(0.f);
#pragma unroll
            for (int b = 0; b < 8; b++) {
                __half2 ph = __float2half2_rn(sc[b] * inv);
                const __half2* vp = (const __half2*)(base + b * QSTRIDE + 128 + h * 16);
#pragma unroll
                for (int d2 = 0; d2 < 8; d2++) o2[d2] = __hfma2(ph, vp[d2], o2[d2]);
            }
            float part = 0.f;
#pragma unroll
            for (int d2 = 0; d2 < 8; d2++) {
                float2 f = __half22float2(o2[d2]);
                part += f.x * wc[h * 16 + d2 * 2] + f.y * wc[h * 16 + d2 * 2 + 1];
            }
            part += __shfl_xor_sync(0xffffffffu, part, 8);
            part += __shfl_xor_sync(0xffffffffu, part, 16);
            if (h == 0) {
                const int n = (blockIdx.x * 2 + it) * 16 + s;
                g_aq[n * 8 + a] = part + wc[64];
            }
        }
        __syncthreads();
    }
}

// ---------------- final mixing (fp16 w1/wf) ----------------------------------
__global__ void __launch_bounds__(256) final_kernel(
    const float* __restrict__ Wv2, const float* __restrict__ bv2,
    float* __restrict__ out)
{
    const int warp = threadIdx.x >> 5, lane = threadIdx.x & 31;
    const int n = blockIdx.x * 8 + warp;
    if (n >= NTOT) return;

    float aqv[8];
#pragma unroll
    for (int a = 0; a < 8; a++) aqv[a] = g_aq[n * 8 + a];

    float tot = 0.f;
#pragma unroll
    for (int jj = 0; jj < 2; jj++) {
        int e = jj * 32 + lane;
        float hsum = g_b1[n * 64 + e];
#pragma unroll
        for (int a = 0; a < 8; a++)
            hsum += aqv[a] * __half2float(g_w1h[(size_t)n * 512 + a * 64 + e]);
        float hid = hsum > 0.f ? hsum : expm1f(hsum);
        tot += hid * __half2float(g_wfh[n * 64 + e]) + g_v1[n * 64 + e] * Wv2[e];
    }
#pragma unroll
    for (int off = 16; off > 0; off >>= 1) tot += __shfl_xor_sync(0xffffffffu, tot, off);
    if (lane == 0) out[n] = tot + bv2[0];
}

// ---------------- launch ----------------------------------------------------
extern "C" void kernel_launch(void* const* d_in, const int* in_sizes, int n_in,
                              void* d_out, int out_size)
{
    const float* agent_qs = (const float*)d_in[0];
    const float* states   = (const float*)d_in[1];
    const float* obs      = (const float*)d_in[2];
    const int*   actions  = (const int*)d_in[3];
    const float* W_obs = (const float*)d_in[4];  const float* b_obs = (const float*)d_in[5];
    const float* W_act = (const float*)d_in[6];  const float* b_act = (const float*)d_in[7];
    const float* W_q   = (const float*)d_in[8];  const float* b_q   = (const float*)d_in[9];
    const float* Wqkv  = (const float*)d_in[10]; const float* bqkv  = (const float*)d_in[11];
    const float* Wo    = (const float*)d_in[12]; const float* bo    = (const float*)d_in[13];
    const float* Wa2q  = (const float*)d_in[14]; const float* ba2q  = (const float*)d_in[15];
    const float* Wh1a  = (const float*)d_in[16]; const float* bh1a  = (const float*)d_in[17];
    const float* Wh1b  = (const float*)d_in[18]; const float* bh1b  = (const float*)d_in[19];
    const float* Whfa  = (const float*)d_in[20]; const float* bhfa  = (const float*)d_in[21];
    const float* Whfb  = (const float*)d_in[22]; const float* bhfb  = (const float*)d_in[23];
    const float* Wb1   = (const float*)d_in[24]; const float* bb1   = (const float*)d_in[25];
    const float* Wv1   = (const float*)d_in[26]; const float* bv1   = (const float*)d_in[27];
    const float* Wv2   = (const float*)d_in[28]; const float* bv2   = (const float*)d_in[29];
    float* out = (float*)d_out;

    void *p_xh, *p_sth, *p_wh, *p_h1h, *p_hfh, *p_w1h, *p_wfh, *p_b1, *p_v1;
    cudaGetSymbolAddress(&p_xh,  g_xh);
    cudaGetSymbolAddress(&p_sth, g_sth);
    cudaGetSymbolAddress(&p_wh,  g_wh);
    cudaGetSymbolAddress(&p_h1h, g_h1h);
    cudaGetSymbolAddress(&p_hfh, g_hfh);
    cudaGetSymbolAddress(&p_w1h, g_w1h);
    cudaGetSymbolAddress(&p_wfh, g_wfh);
    cudaGetSymbolAddress(&p_b1,  g_b1);
    cudaGetSymbolAddress(&p_v1,  g_v1);
    __half* wh = (__half*)p_wh;

    cudaFuncSetAttribute(mega_gemm,       cudaFuncAttributeMaxDynamicSharedMemorySize, MG_SMEM_BYTES);
    cudaFuncSetAttribute(qkv_attn_kernel, cudaFuncAttributeMaxDynamicSharedMemorySize, QA_SMEM_BYTES);

    // fork stream + events (no device allocations; capture-legal fork/join)
    cudaStream_t s2;
    cudaStreamCreateWithFlags(&s2, cudaStreamNonBlocking);
    cudaEvent_t evCvt, evB;
    cudaEventCreateWithFlags(&evCvt, cudaEventDisableTiming);
    cudaEventCreateWithFlags(&evB,   cudaEventDisableTiming);

    // 0) conversions (default stream)
    HSegs segs;
    segs.src[0] = Wqkv;  segs.gbase[0] = 0;
    segs.src[1] = W_obs; segs.gbase[1] = 384;
    segs.src[2] = Wh1a;  segs.gbase[2] = 896;
    segs.src[3] = Whfa;  segs.gbase[3] = 4992;
    segs.src[4] = Wh1b;  segs.gbase[4] = 9088;
    segs.src[5] = Whfb;  segs.gbase[5] = 13184;
    segs.src[6] = Wb1;   segs.gbase[6] = 13696;
    segs.src[7] = Wv1;   segs.gbase[7] = 14720;
    cvt_all_kernel<<<CVT_ST_BLK + CVT_W_BLK, 256>>>(states, (__half*)p_sth, segs, wh);
    cudaEventRecord(evCvt, 0);
    cudaStreamWaitEvent(s2, evCvt, 0);

    // chain A (default stream): encoder -> qkv_attn
    MOps mA = {};
    mA.v[0] = { obs, wh + HOFF_WOBS, b_obs, p_xh, 256, 64, 0, 4, 0, 0 };
    for (int i = 1; i < 11; i++) { mA.v[i] = mA.v[0]; mA.v[i].tileBase = 0x7FFFFFFF; }
    mega_gemm<<<1024, 256, MG_SMEM_BYTES>>>(mA, actions, agent_qs, W_act, W_q, b_act, b_q);
    qkv_attn_kernel<<<512, 256, QA_SMEM_BYTES>>>(wh + HOFF_WQKV, bqkv, Wa2q, ba2q, Wo, bo);

    // chain B (stream s2): hp1 -> mega2
    MOps mB = {};
    for (int i = 0; i < 4; i++)
        mB.v[i]     = { p_sth, wh + HOFF_WH1A, bh1a, p_h1h, 512, 256, i * 64, 1, i * 128, 1 };
    for (int i = 0; i < 4; i++)
        mB.v[4 + i] = { p_sth, wh + HOFF_WHFA, bhfa, p_hfh, 512, 256, i * 64, 1, 512 + i * 128, 1 };
    mB.v[8]  = { p_sth, wh + HOFF_WB1, bb1, p_b1, 512, 64, 0, 0, 1024, 0 };
    mB.v[9]  = { p_sth, wh + HOFF_WV1, bv1, p_v1, 512, 64, 0, 1, 1152, 0 };
    mB.v[10] = mB.v[9]; mB.v[10].tileBase = 0x7FFFFFFF;
    mega_gemm<<<1280, 256, MG_SMEM_BYTES, s2>>>(mB, actions, agent_qs, W_act, W_q, b_act, b_q);

    MOps mC = {};
    for (int i = 0; i < 8; i++)
        mC.v[i] = { p_h1h, wh + HOFF_WH1B, bh1b, p_w1h, 256, 512, i * 64, 2, i * 128, 2 };
    mC.v[8]  = { p_hfh, wh + HOFF_WHFB, bhfb, p_wfh, 256, 64, 0, 2, 1024, 2 };
    mC.v[9]  = mC.v[8]; mC.v[9].tileBase = 0x7FFFFFFF;
    mC.v[10] = mC.v[8]; mC.v[10].tileBase = 0x7FFFFFFF;
    mega_gemm<<<1152, 256, MG_SMEM_BYTES, s2>>>(mC, actions, agent_qs, W_act, W_q, b_act, b_q);
    cudaEventRecord(evB, s2);

    // join: final needs chain A (default) + chain B (evB)
    cudaStreamWaitEvent(0, evB, 0);
    final_kernel<<<2048, 256>>>(Wv2, bv2, out);
}